// round 1
// baseline (speedup 1.0000x reference)
#include <cuda_runtime.h>
#include <cuda_bf16.h>
#include <cstdint>

// Problem constants
#define NB 4          // batch
#define TT 1024       // seq len
#define DD 1024       // dim
#define LL 4          // layers
#define VV 32000      // vocab
#define MTOT (NB*TT)  // 4096 rows

// ---------------- scratch (device globals; no allocs allowed) ----------------
__device__ float g_x[MTOT * DD];
__device__ float g_h[MTOT * DD];
__device__ float g_qkv[MTOT * 3 * DD];
__device__ float g_lr[MTOT];
__device__ float g_KK[NB * TT * TT];
__device__ float g_u[MTOT * DD];
__device__ float g_score[NB * TT * TT];
__device__ float g_y[MTOT * DD];
__device__ float g_a[MTOT * DD];

// ---------------- helpers ----------------
__device__ __forceinline__ float blockReduceSum(float v, float* sdata) {
    int tid = threadIdx.x;
    sdata[tid] = v;
    __syncthreads();
    for (int s = 128; s > 0; s >>= 1) {
        if (tid < s) sdata[tid] += sdata[tid + s];
        __syncthreads();
    }
    float r = sdata[0];
    __syncthreads();
    return r;
}

// ---------------- embedding ----------------
__global__ void embed_kernel(float* __restrict__ x, const float* __restrict__ E,
                             const int* __restrict__ ids) {
    int m = blockIdx.x;
    int id = ids[m];
    const float4* src = (const float4*)(E + (size_t)id * DD);
    float4* dst = (float4*)(x + (size_t)m * DD);
    dst[threadIdx.x] = src[threadIdx.x];
}

// ---------------- layernorm (one block per row, 256 thr, 4 elems/thr) ----------------
__global__ void ln_kernel(float* __restrict__ out, const float* __restrict__ in,
                          const float* __restrict__ g, const float* __restrict__ b) {
    __shared__ float sdata[256];
    int m = blockIdx.x, tid = threadIdx.x;
    const float* row = in + (size_t)m * DD;
    float4 v = *(const float4*)(row + tid * 4);
    float s = v.x + v.y + v.z + v.w;
    float mean = blockReduceSum(s, sdata) * (1.0f / DD);
    float dx = v.x - mean, dy = v.y - mean, dz = v.z - mean, dw = v.w - mean;
    float s2 = dx * dx + dy * dy + dz * dz + dw * dw;
    float var = blockReduceSum(s2, sdata) * (1.0f / DD);
    float rstd = 1.0f / sqrtf(var + 1e-5f);
    float* orow = out + (size_t)m * DD;
    int c = tid * 4;
    orow[c + 0] = dx * rstd * g[c + 0] + b[c + 0];
    orow[c + 1] = dy * rstd * g[c + 1] + b[c + 1];
    orow[c + 2] = dz * rstd * g[c + 2] + b[c + 2];
    orow[c + 3] = dw * rstd * g[c + 3] + b[c + 3];
}

// ---------------- k-normalize (in place in qkv) + lr = h@Wlr + blr ----------------
__global__ void knorm_lr_kernel(float* __restrict__ qkv, const float* __restrict__ h,
                                const float* __restrict__ Wlr, const float* __restrict__ blr,
                                float* __restrict__ lr) {
    __shared__ float sdata[256];
    int m = blockIdx.x, tid = threadIdx.x;
    float* krow = qkv + (size_t)m * (3 * DD) + DD;
    const float* hrow = h + (size_t)m * DD;
    int c = tid * 4;
    float4 kv = *(float4*)(krow + c);
    float ss = kv.x * kv.x + kv.y * kv.y + kv.z * kv.z + kv.w * kv.w;
    float ksum = blockReduceSum(ss, sdata);
    float4 hv = *(const float4*)(hrow + c);
    float4 wv = *(const float4*)(Wlr + c);
    float d = hv.x * wv.x + hv.y * wv.y + hv.z * wv.z + hv.w * wv.w;
    float dot = blockReduceSum(d, sdata);
    float scale = 1.0f / sqrtf(ksum);
    kv.x *= scale; kv.y *= scale; kv.z *= scale; kv.w *= scale;
    *(float4*)(krow + c) = kv;
    if (tid == 0) lr[m] = dot + blr[0];
}

// ---------------- copy v slice of qkv -> u ----------------
__global__ void copyv_kernel(float* __restrict__ u, const float* __restrict__ qkv) {
    int m = blockIdx.x, c = threadIdx.x * 4;
    *(float4*)(u + (size_t)m * DD + c) = *(const float4*)(qkv + (size_t)m * (3 * DD) + 2 * DD + c);
}

// ---------------- u[m] *= lr[m] ----------------
__global__ void scaleu_kernel(float* __restrict__ u, const float* __restrict__ lr) {
    int m = blockIdx.x, c = threadIdx.x * 4;
    float s = lr[m];
    float4 v = *(float4*)(u + (size_t)m * DD + c);
    v.x *= s; v.y *= s; v.z *= s; v.w *= s;
    *(float4*)(u + (size_t)m * DD + c) = v;
}

// ---------------- in-chunk forward substitution (chunk of 64 rows) ----------------
// grid: (DD/256, NB); 256 threads; each thread owns one channel column d.
__global__ void chunksolve_kernel(float* __restrict__ u, const float* __restrict__ KK, int ci) {
    __shared__ float Ks[64][64];
    int batch = blockIdx.y;
    int d = blockIdx.x * 256 + threadIdx.x;
    const float* KKb = KK + (size_t)batch * TT * TT;
    float* ub = u + (size_t)batch * TT * DD;
    int base = ci * 64;
    for (int i = threadIdx.x; i < 64 * 64; i += 256) {
        int r = i >> 6, c = i & 63;
        Ks[r][c] = KKb[(size_t)(base + r) * TT + base + c];
    }
    __syncthreads();
    float uloc[64];
#pragma unroll
    for (int r = 0; r < 64; ++r) {
        float val = ub[(size_t)(base + r) * DD + d];
#pragma unroll
        for (int s = 0; s < r; ++s) val -= Ks[r][s] * uloc[s];
        uloc[r] = val;
        ub[(size_t)(base + r) * DD + d] = val;
    }
}

// ---------------- generic SGEMM: C = alpha*A@B(^T) [+bias] [+resid] [relu] [mask] ----------------
// flags: 1 = relu, 2 = strict-lower mask (zero where col >= row)
template <bool TB>
__global__ void sgemm_kernel(const float* __restrict__ A, const float* __restrict__ B,
                             const float* __restrict__ bias, const float* __restrict__ resid,
                             float* __restrict__ C,
                             int M, int N, int K, int lda, int ldb, int ldc,
                             long long sA, long long sB, long long sC,
                             float alpha, int flags) {
    int z = blockIdx.z;
    A += (long long)z * sA;
    B += (long long)z * sB;
    C += (long long)z * sC;
    if (resid) resid += (long long)z * sC;
    int m0 = blockIdx.y * 128, n0 = blockIdx.x * 128;
    bool mask = (flags & 2) != 0;
    if (mask && n0 >= m0 + 128) return;  // fully above-diagonal: never read downstream

    __shared__ float As[8][128];
    __shared__ float Bs[8][128];
    int tid = threadIdx.x;
    int tx = tid & 15, ty = tid >> 4;
    int ar = tid >> 1;          // 0..127
    int ac = (tid & 1) * 4;     // 0 or 4
    int br = tid >> 5;          // 0..7   (NN B rows)
    int bc = (tid & 31) * 4;    // 0..124 (NN B cols)

    float acc[8][8];
#pragma unroll
    for (int i = 0; i < 8; ++i)
#pragma unroll
        for (int j = 0; j < 8; ++j) acc[i][j] = 0.0f;

    for (int k0 = 0; k0 < K; k0 += 8) {
        float4 av = make_float4(0.f, 0.f, 0.f, 0.f);
        if (m0 + ar < M) av = *(const float4*)(A + (long long)(m0 + ar) * lda + k0 + ac);
        As[ac + 0][ar] = av.x; As[ac + 1][ar] = av.y;
        As[ac + 2][ar] = av.z; As[ac + 3][ar] = av.w;
        if (!TB) {
            float4 bv = make_float4(0.f, 0.f, 0.f, 0.f);
            if (n0 + bc < N) bv = *(const float4*)(B + (long long)(k0 + br) * ldb + n0 + bc);
            *(float4*)&Bs[br][bc] = bv;
        } else {
            float4 bv = make_float4(0.f, 0.f, 0.f, 0.f);
            if (n0 + ar < N) bv = *(const float4*)(B + (long long)(n0 + ar) * ldb + k0 + ac);
            Bs[ac + 0][ar] = bv.x; Bs[ac + 1][ar] = bv.y;
            Bs[ac + 2][ar] = bv.z; Bs[ac + 3][ar] = bv.w;
        }
        __syncthreads();
#pragma unroll
        for (int k = 0; k < 8; ++k) {
            float ra[8], rb[8];
            *(float4*)&ra[0] = *(float4*)&As[k][ty * 8];
            *(float4*)&ra[4] = *(float4*)&As[k][ty * 8 + 4];
            *(float4*)&rb[0] = *(float4*)&Bs[k][tx * 8];
            *(float4*)&rb[4] = *(float4*)&Bs[k][tx * 8 + 4];
#pragma unroll
            for (int i = 0; i < 8; ++i)
#pragma unroll
                for (int j = 0; j < 8; ++j) acc[i][j] += ra[i] * rb[j];
        }
        __syncthreads();
    }
    bool relu = (flags & 1) != 0;
#pragma unroll
    for (int i = 0; i < 8; ++i) {
        int row = m0 + ty * 8 + i;
        if (row >= M) continue;
#pragma unroll
        for (int j = 0; j < 8; ++j) {
            int col = n0 + tx * 8 + j;
            if (col >= N) continue;
            float v = alpha * acc[i][j];
            if (bias) v += bias[col];
            if (resid) v += resid[(long long)row * ldc + col];
            if (relu) v = fmaxf(v, 0.0f);
            if (mask && col >= row) v = 0.0f;
            C[(long long)row * ldc + col] = v;
        }
    }
}

// ---------------- host-side GEMM launcher ----------------
static void launch_gemm(bool tb, const float* A, const float* B, const float* bias,
                        const float* resid, float* C, int M, int N, int K,
                        int lda, int ldb, int ldc,
                        long long sA, long long sB, long long sC, int batch,
                        float alpha, int flags) {
    dim3 grid((N + 127) / 128, (M + 127) / 128, batch);
    if (tb)
        sgemm_kernel<true><<<grid, 256>>>(A, B, bias, resid, C, M, N, K, lda, ldb, ldc,
                                          sA, sB, sC, alpha, flags);
    else
        sgemm_kernel<false><<<grid, 256>>>(A, B, bias, resid, C, M, N, K, lda, ldb, ldc,
                                           sA, sB, sC, alpha, flags);
}

extern "C" void kernel_launch(void* const* d_in, const int* in_sizes, int n_in,
                              void* d_out, int out_size) {
    const int* ids = (const int*)d_in[0];
    const float* E = (const float*)d_in[1];
    const float* Wg = (const float*)d_in[2];
    const float* bg = (const float*)d_in[3];
    const float* Wlr = (const float*)d_in[4];
    const float* blr = (const float*)d_in[5];
    const float* Wo = (const float*)d_in[6];
    const float* bo = (const float*)d_in[7];
    const float* g_d = (const float*)d_in[8];
    const float* b_d = (const float*)d_in[9];
    const float* W1 = (const float*)d_in[10];
    const float* b1 = (const float*)d_in[11];
    const float* W2 = (const float*)d_in[12];
    const float* b2 = (const float*)d_in[13];
    const float* g_m = (const float*)d_in[14];
    const float* b_m = (const float*)d_in[15];
    const float* g_o = (const float*)d_in[16];
    const float* b_o = (const float*)d_in[17];
    float* out = (float*)d_out;

    float *x, *h, *qkv, *lr, *KK, *u, *score, *y, *a;
    cudaGetSymbolAddress((void**)&x, g_x);
    cudaGetSymbolAddress((void**)&h, g_h);
    cudaGetSymbolAddress((void**)&qkv, g_qkv);
    cudaGetSymbolAddress((void**)&lr, g_lr);
    cudaGetSymbolAddress((void**)&KK, g_KK);
    cudaGetSymbolAddress((void**)&u, g_u);
    cudaGetSymbolAddress((void**)&score, g_score);
    cudaGetSymbolAddress((void**)&y, g_y);
    cudaGetSymbolAddress((void**)&a, g_a);

    const long long sTT = (long long)TT * TT;       // per-batch stride for [T,T]
    const long long sTD = (long long)TT * DD;       // per-batch stride for [T,D]
    const long long sQ = (long long)TT * 3 * DD;    // per-batch stride inside qkv

    // x = E[ids]
    embed_kernel<<<MTOT, 256>>>(x, E, ids);

    for (int l = 0; l < LL; ++l) {
        const float* Wgl = Wg + (size_t)l * DD * 3 * DD;
        const float* bgl = bg + (size_t)l * 3 * DD;
        const float* Wlrl = Wlr + (size_t)l * DD;
        const float* blrl = blr + l;
        const float* Wol = Wo + (size_t)l * DD * DD;
        const float* bol = bo + (size_t)l * DD;
        const float* W1l = W1 + (size_t)l * DD * DD;
        const float* b1l = b1 + (size_t)l * DD;
        const float* W2l = W2 + (size_t)l * DD * DD;
        const float* b2l = b2 + (size_t)l * DD;

        // --- delta block ---
        ln_kernel<<<MTOT, 256>>>(h, x, g_d + (size_t)l * DD, b_d + (size_t)l * DD);
        // qkv = h @ Wg[l] + bg[l]
        launch_gemm(false, h, Wgl, bgl, nullptr, qkv, MTOT, 3 * DD, DD,
                    DD, 3 * DD, 3 * DD, 0, 0, 0, 1, 1.0f, 0);
        // normalize k, compute lr
        knorm_lr_kernel<<<MTOT, 256>>>(qkv, h, Wlrl, blrl, lr);
        // KK = stril(k k^T, -1), batched
        launch_gemm(true, qkv + DD, qkv + DD, nullptr, nullptr, KK, TT, TT, DD,
                    3 * DD, 3 * DD, TT, sQ, sQ, sTT, NB, 1.0f, 2);
        // u = v  (then solve (I + KK) u = v by chunked forward substitution)
        copyv_kernel<<<MTOT, 256>>>(u, qkv);
        for (int ci = 0; ci < 16; ++ci) {
            chunksolve_kernel<<<dim3(DD / 256, NB), 256>>>(u, KK, ci);
            if (ci < 15) {
                int r0 = 64 * (ci + 1);
                int Mu = TT - r0;
                // u[r0:,:] -= KK[r0:, ci*64:ci*64+64] @ u[ci*64:ci*64+64, :]
                launch_gemm(false, KK + (size_t)r0 * TT + ci * 64, u + (size_t)ci * 64 * DD,
                            nullptr, u + (size_t)r0 * DD, u + (size_t)r0 * DD,
                            Mu, DD, 64, TT, DD, DD, sTT, sTD, sTD, NB, -1.0f, 0);
            }
        }
        // u *= lr (rowwise)
        scaleu_kernel<<<MTOT, 256>>>(u, lr);
        // score[s,t] = q_s . k_t  (full, unmasked), batched
        launch_gemm(true, qkv, qkv + DD, nullptr, nullptr, score, TT, TT, DD,
                    3 * DD, 3 * DD, TT, sQ, sQ, sTT, NB, 1.0f, 0);
        // y = score @ (lr*u), batched
        launch_gemm(false, score, u, nullptr, nullptr, y, TT, DD, TT,
                    TT, DD, DD, sTT, sTD, sTD, NB, 1.0f, 0);
        // x = x + y @ Wo[l] + bo[l]
        launch_gemm(false, y, Wol, bol, x, x, MTOT, DD, DD,
                    DD, DD, DD, 0, 0, 0, 1, 1.0f, 0);

        // --- MLP block ---
        ln_kernel<<<MTOT, 256>>>(h, x, g_m + (size_t)l * DD, b_m + (size_t)l * DD);
        launch_gemm(false, h, W1l, b1l, nullptr, a, MTOT, DD, DD,
                    DD, DD, DD, 0, 0, 0, 1, 1.0f, 1 /*relu*/);
        launch_gemm(false, a, W2l, b2l, x, x, MTOT, DD, DD,
                    DD, DD, DD, 0, 0, 0, 1, 1.0f, 0);
    }

    // final LN + tied decoder: logits = ln(x) @ E^T
    ln_kernel<<<MTOT, 256>>>(h, x, g_o, b_o);
    launch_gemm(true, h, E, nullptr, nullptr, out, MTOT, VV, DD,
                DD, DD, VV, 0, 0, 0, 1, 1.0f, 0);
}

// round 5
// speedup vs baseline: 1.5392x; 1.5392x over previous
#include <cuda_runtime.h>
#include <cuda_bf16.h>
#include <cstdint>

// Problem constants
#define NB 4          // batch
#define TT 1024       // seq len
#define DD 1024       // dim
#define LL 4          // layers
#define VV 32000      // vocab
#define MTOT (NB*TT)  // 4096 rows

// ===================== PTX helpers (base ISA only) =====================
__device__ __forceinline__ uint32_t smem_to_u32(const void* p) {
    uint32_t a;
    asm("{ .reg .u64 t; cvta.to.shared.u64 t, %1; cvt.u32.u64 %0, t; }" : "=r"(a) : "l"(p));
    return a;
}
#define CP_ASYNC16(dst, src) \
    asm volatile("cp.async.cg.shared.global [%0], [%1], 16;" :: "r"((uint32_t)(dst)), "l"(src))
#define CP_ASYNC_COMMIT() asm volatile("cp.async.commit_group;" ::: "memory")
#define CP_ASYNC_WAIT(n) asm volatile("cp.async.wait_group %0;" :: "n"(n) : "memory")

__device__ __forceinline__ void ldmx4(uint32_t* r, uint32_t addr) {
    asm volatile("ldmatrix.sync.aligned.m8n8.x4.shared.b16 {%0,%1,%2,%3}, [%4];"
                 : "=r"(r[0]), "=r"(r[1]), "=r"(r[2]), "=r"(r[3]) : "r"(addr));
}
__device__ __forceinline__ void mma16816(float* c, const uint32_t* a, const uint32_t* b) {
    asm volatile(
        "mma.sync.aligned.m16n8k16.row.col.f32.bf16.bf16.f32 "
        "{%0,%1,%2,%3}, {%4,%5,%6,%7}, {%8,%9}, {%0,%1,%2,%3};"
        : "+f"(c[0]), "+f"(c[1]), "+f"(c[2]), "+f"(c[3])
        : "r"(a[0]), "r"(a[1]), "r"(a[2]), "r"(a[3]), "r"(b[0]), "r"(b[1]));
}

// ===================== scratch (device globals) =====================
__device__ float g_x[MTOT * DD];
__device__ float g_h[MTOT * DD];
__device__ float g_qkv[MTOT * 3 * DD];
__device__ float g_lr[MTOT];
__device__ float g_KK[NB * TT * TT];
__device__ float g_u[MTOT * DD];
__device__ float g_score[NB * TT * TT];
__device__ float g_y[MTOT * DD];
__device__ float g_a[MTOT * DD];
__device__ __nv_bfloat16 g_Eh[VV * DD], g_El[VV * DD];
__device__ __nv_bfloat16 g_WgTh[LL * 3 * DD * DD], g_WgTl[LL * 3 * DD * DD];
__device__ __nv_bfloat16 g_WoTh[LL * DD * DD], g_WoTl[LL * DD * DD];
__device__ __nv_bfloat16 g_W1Th[LL * DD * DD], g_W1Tl[LL * DD * DD];
__device__ __nv_bfloat16 g_W2Th[LL * DD * DD], g_W2Tl[LL * DD * DD];
__device__ __nv_bfloat16 g_hh[MTOT * DD], g_hl[MTOT * DD];
__device__ __nv_bfloat16 g_qh[MTOT * DD], g_ql[MTOT * DD];
__device__ __nv_bfloat16 g_kh[MTOT * DD], g_kl[MTOT * DD];
__device__ __nv_bfloat16 g_uth[MTOT * DD], g_utl[MTOT * DD];
__device__ __nv_bfloat16 g_sh[NB * TT * TT], g_sl[NB * TT * TT];
__device__ __nv_bfloat16 g_yh[MTOT * DD], g_yl[MTOT * DD];
__device__ __nv_bfloat16 g_ahh[MTOT * DD], g_ahl[MTOT * DD];

// ===================== small kernels =====================
__device__ __forceinline__ float blockReduceSum(float v, float* sdata) {
    int tid = threadIdx.x;
    sdata[tid] = v;
    __syncthreads();
    for (int s = 128; s > 0; s >>= 1) {
        if (tid < s) sdata[tid] += sdata[tid + s];
        __syncthreads();
    }
    float r = sdata[0];
    __syncthreads();
    return r;
}

__global__ void embed_kernel(float* __restrict__ x, const float* __restrict__ E,
                             const int* __restrict__ ids) {
    int m = blockIdx.x;
    int id = ids[m];
    const float4* src = (const float4*)(E + (size_t)id * DD);
    float4* dst = (float4*)(x + (size_t)m * DD);
    dst[threadIdx.x] = src[threadIdx.x];
}

__global__ void ln_kernel(float* __restrict__ out, const float* __restrict__ in,
                          const float* __restrict__ g, const float* __restrict__ b) {
    __shared__ float sdata[256];
    int m = blockIdx.x, tid = threadIdx.x;
    const float* row = in + (size_t)m * DD;
    float4 v = *(const float4*)(row + tid * 4);
    float s = v.x + v.y + v.z + v.w;
    float mean = blockReduceSum(s, sdata) * (1.0f / DD);
    float dx = v.x - mean, dy = v.y - mean, dz = v.z - mean, dw = v.w - mean;
    float s2 = dx * dx + dy * dy + dz * dz + dw * dw;
    float var = blockReduceSum(s2, sdata) * (1.0f / DD);
    float rstd = 1.0f / sqrtf(var + 1e-5f);
    float* orow = out + (size_t)m * DD;
    int c = tid * 4;
    orow[c + 0] = dx * rstd * g[c + 0] + b[c + 0];
    orow[c + 1] = dy * rstd * g[c + 1] + b[c + 1];
    orow[c + 2] = dz * rstd * g[c + 2] + b[c + 2];
    orow[c + 3] = dw * rstd * g[c + 3] + b[c + 3];
}

__global__ void knorm_lr_kernel(float* __restrict__ qkv, const float* __restrict__ h,
                                const float* __restrict__ Wlr, const float* __restrict__ blr,
                                float* __restrict__ lr) {
    __shared__ float sdata[256];
    int m = blockIdx.x, tid = threadIdx.x;
    float* krow = qkv + (size_t)m * (3 * DD) + DD;
    const float* hrow = h + (size_t)m * DD;
    int c = tid * 4;
    float4 kv = *(float4*)(krow + c);
    float ss = kv.x * kv.x + kv.y * kv.y + kv.z * kv.z + kv.w * kv.w;
    float ksum = blockReduceSum(ss, sdata);
    float4 hv = *(const float4*)(hrow + c);
    float4 wv = *(const float4*)(Wlr + c);
    float d = hv.x * wv.x + hv.y * wv.y + hv.z * wv.z + hv.w * wv.w;
    float dot = blockReduceSum(d, sdata);
    float scale = 1.0f / sqrtf(ksum);
    kv.x *= scale; kv.y *= scale; kv.z *= scale; kv.w *= scale;
    *(float4*)(krow + c) = kv;
    if (tid == 0) lr[m] = dot + blr[0];
}

__global__ void copyv_kernel(float* __restrict__ u, const float* __restrict__ qkv) {
    int m = blockIdx.x, c = threadIdx.x * 4;
    *(float4*)(u + (size_t)m * DD + c) = *(const float4*)(qkv + (size_t)m * (3 * DD) + 2 * DD + c);
}

__global__ void scaleu_kernel(float* __restrict__ u, const float* __restrict__ lr) {
    int m = blockIdx.x, c = threadIdx.x * 4;
    float s = lr[m];
    float4 v = *(float4*)(u + (size_t)m * DD + c);
    v.x *= s; v.y *= s; v.z *= s; v.w *= s;
    *(float4*)(u + (size_t)m * DD + c) = v;
}

__device__ __forceinline__ void split4_store(const float* arr, __nv_bfloat16* oh,
                                             __nv_bfloat16* ol) {
    union { __nv_bfloat16 b[4]; uint2 u; } ph, pl;
#pragma unroll
    for (int j = 0; j < 4; ++j) {
        __nv_bfloat16 hh = __float2bfloat16(arr[j]);
        ph.b[j] = hh;
        pl.b[j] = __float2bfloat16(arr[j] - __bfloat162float(hh));
    }
    *(uint2*)oh = ph.u;
    *(uint2*)ol = pl.u;
}

__global__ void split_kernel(const float* __restrict__ in, __nv_bfloat16* __restrict__ oh,
                             __nv_bfloat16* __restrict__ ol, long long n) {
    long long i = ((long long)blockIdx.x * blockDim.x + threadIdx.x) * 4;
    if (i >= n) return;
    float4 v = *(const float4*)(in + i);
    float arr[4] = {v.x, v.y, v.z, v.w};
    split4_store(arr, oh + i, ol + i);
}

__global__ void split_rows_kernel(const float* __restrict__ in, __nv_bfloat16* __restrict__ oh,
                                  __nv_bfloat16* __restrict__ ol, int instride) {
    int m = blockIdx.x, c = threadIdx.x * 4;
    float4 v = *(const float4*)(in + (size_t)m * instride + c);
    size_t o = (size_t)m * DD + c;
    float arr[4] = {v.x, v.y, v.z, v.w};
    split4_store(arr, oh + o, ol + o);
}

// transpose + split: in [R,C] fp32 -> out [C,R] bf16 hi/lo (batched via z)
__global__ void tsplit_kernel(const float* __restrict__ in, __nv_bfloat16* __restrict__ oh,
                              __nv_bfloat16* __restrict__ ol, int R, int C,
                              long long sIn, long long sOut) {
    __shared__ float tile[32][33];
    long long z = blockIdx.z;
    in += z * sIn; oh += z * sOut; ol += z * sOut;
    int r0 = blockIdx.y * 32, c0 = blockIdx.x * 32;
    int tx = threadIdx.x, ty = threadIdx.y;  // 32 x 8
#pragma unroll
    for (int i = 0; i < 32; i += 8)
        tile[ty + i][tx] = in[(size_t)(r0 + ty + i) * C + c0 + tx];
    __syncthreads();
#pragma unroll
    for (int i = 0; i < 32; i += 8) {
        int c = c0 + ty + i, r = r0 + tx;
        float v = tile[tx][ty + i];
        __nv_bfloat16 hh = __float2bfloat16(v);
        oh[(size_t)c * R + r] = hh;
        ol[(size_t)c * R + r] = __float2bfloat16(v - __bfloat162float(hh));
    }
}

// ============ mma.sync bf16x2-split NT GEMM: C = A@B^T (+bias)(+resid)(relu)(mask) ============
// A: [M,K] (Ah,Al) bf16 K-contiguous; B: [N,K] (Bh,Bl) bf16 K-contiguous.
// CTA tile 128x128, BK=16, 256 threads = 8 warps (4m x 2n), warp tile 32x64.
// smem: 4 tiles of 128 rows x 48B (16 bf16 = 32B data + 16B pad); 2 stages = 49152B (<=48KB, no opt-in).
// flags: 1=relu 2=strict-lower-mask 4=bias 8=resid
#define TILE_B 6144           // one padded tile (128 * 48)
#define STAGE_B 24576         // 4 tiles
#define TG_DYN_SMEM 49152     // 2 stages == 48KB

__global__ void __launch_bounds__(256, 1)
tgemm_kernel(const __nv_bfloat16* __restrict__ Ah, const __nv_bfloat16* __restrict__ Al,
             const __nv_bfloat16* __restrict__ Bh, const __nv_bfloat16* __restrict__ Bl,
             const float* __restrict__ bias, const float* __restrict__ resid,
             float* __restrict__ C, int K, int lda, int ldb, int ldc,
             long long sA, long long sB, long long sC, int flags) {
    long long z = blockIdx.z;
    Ah += z * sA; Al += z * sA; Bh += z * sB; Bl += z * sB;
    C += z * sC;
    if (resid) resid += z * sC;
    int m0 = blockIdx.x * 128, n0 = blockIdx.y * 128;
    if ((flags & 2) && n0 >= m0 + 128) return;  // fully above strict-lower diagonal

    extern __shared__ char dynsmem[];
    uint32_t sb = smem_to_u32(dynsmem);
    int tid = threadIdx.x, lane = tid & 31, wid = tid >> 5;
    int wm = wid >> 1, wn = wid & 1;  // warp grid 4(m) x 2(n)

    // loader mapping: 512 rows per stage (4 tiles x 128). thread t handles rows (t&127)
    // of tile pair (t>>7): 0 -> A tiles (hi+lo), 1 -> B tiles (hi+lo). 32B per row.
    int ldrow = tid & 127, ldpair = tid >> 7;
    const __nv_bfloat16* src0 = ldpair ? Bh : Ah;
    const __nv_bfloat16* src1 = ldpair ? Bl : Al;
    int ldld = ldpair ? ldb : lda;
    int ldbase = ldpair ? n0 : m0;
    uint32_t dst0 = sb + (ldpair * 2 + 0) * TILE_B + ldrow * 48;
    uint32_t dst1 = sb + (ldpair * 2 + 1) * TILE_B + ldrow * 48;
    const __nv_bfloat16* p0 = src0 + (size_t)(ldbase + ldrow) * ldld;
    const __nv_bfloat16* p1 = src1 + (size_t)(ldbase + ldrow) * ldld;

    const int nch = K >> 4;  // BK = 16

    // prefetch stage 0
    CP_ASYNC16(dst0, p0);      CP_ASYNC16(dst0 + 16, p0 + 8);
    CP_ASYNC16(dst1, p1);      CP_ASYNC16(dst1 + 16, p1 + 8);
    CP_ASYNC_COMMIT();

    float acc[2][8][4];
#pragma unroll
    for (int i = 0; i < 2; ++i)
#pragma unroll
        for (int j = 0; j < 8; ++j)
#pragma unroll
            for (int r = 0; r < 4; ++r) acc[i][j][r] = 0.0f;

    // ldmatrix per-lane offsets (row stride 48B, k-halves at +0/+16)
    uint32_t a_off = (lane & 15) * 48 + (lane >> 4) * 16;
    uint32_t b_off = ((lane & 7) + ((lane >> 4) & 1) * 8) * 48 + ((lane >> 3) & 1) * 16;

    for (int c = 0; c < nch; ++c) {
        if (c + 1 < nch) {
            uint32_t stoff = ((c + 1) & 1) * STAGE_B;
            int k0 = (c + 1) << 4;
            CP_ASYNC16(dst0 + stoff, p0 + k0);      CP_ASYNC16(dst0 + stoff + 16, p0 + k0 + 8);
            CP_ASYNC16(dst1 + stoff, p1 + k0);      CP_ASYNC16(dst1 + stoff + 16, p1 + k0 + 8);
            CP_ASYNC_COMMIT();
            CP_ASYNC_WAIT(1);
        } else {
            CP_ASYNC_WAIT(0);
        }
        __syncthreads();

        uint32_t st = sb + (c & 1) * STAGE_B;
        uint32_t aBase = st + (wm * 32) * 48 + a_off;
        uint32_t alBase = aBase + TILE_B;
        uint32_t bBase = st + 2 * TILE_B + (wn * 64) * 48 + b_off;
        uint32_t blBase = bBase + TILE_B;

        uint32_t ah[2][4], al2[2][4];
#pragma unroll
        for (int i = 0; i < 2; ++i) {
            ldmx4(ah[i], aBase + i * 768);    // 16 rows * 48B
            ldmx4(al2[i], alBase + i * 768);
        }
        uint32_t bh[8][2], bl[8][2];
#pragma unroll
        for (int jj = 0; jj < 4; ++jj) {
            uint32_t r[4];
            ldmx4(r, bBase + jj * 768);
            bh[2 * jj][0] = r[0]; bh[2 * jj][1] = r[1];
            bh[2 * jj + 1][0] = r[2]; bh[2 * jj + 1][1] = r[3];
            ldmx4(r, blBase + jj * 768);
            bl[2 * jj][0] = r[0]; bl[2 * jj][1] = r[1];
            bl[2 * jj + 1][0] = r[2]; bl[2 * jj + 1][1] = r[3];
        }
#pragma unroll
        for (int i = 0; i < 2; ++i)
#pragma unroll
            for (int j = 0; j < 8; ++j) {
                mma16816(acc[i][j], ah[i], bh[j]);
                mma16816(acc[i][j], ah[i], bl[j]);
                mma16816(acc[i][j], al2[i], bh[j]);
            }
        __syncthreads();
    }

    // epilogue
    int rbase = m0 + wm * 32 + (lane >> 2);
    int cbase = n0 + wn * 64 + (lane & 3) * 2;
#pragma unroll
    for (int i = 0; i < 2; ++i) {
        int r = rbase + i * 16;
#pragma unroll
        for (int j = 0; j < 8; ++j) {
            int cc = cbase + j * 8;
            float2 lo = make_float2(acc[i][j][0], acc[i][j][1]);
            float2 hi = make_float2(acc[i][j][2], acc[i][j][3]);
            if (flags & 4) {
                float2 bv = *(const float2*)(bias + cc);
                lo.x += bv.x; lo.y += bv.y; hi.x += bv.x; hi.y += bv.y;
            }
            if (flags & 8) {
                float2 r0 = *(const float2*)(resid + (long long)r * ldc + cc);
                float2 r1 = *(const float2*)(resid + (long long)(r + 8) * ldc + cc);
                lo.x += r0.x; lo.y += r0.y; hi.x += r1.x; hi.y += r1.y;
            }
            if (flags & 1) {
                lo.x = fmaxf(lo.x, 0.f); lo.y = fmaxf(lo.y, 0.f);
                hi.x = fmaxf(hi.x, 0.f); hi.y = fmaxf(hi.y, 0.f);
            }
            if (flags & 2) {
                if (cc + 0 >= r) lo.x = 0.f;
                if (cc + 1 >= r) lo.y = 0.f;
                if (cc + 0 >= r + 8) hi.x = 0.f;
                if (cc + 1 >= r + 8) hi.y = 0.f;
            }
            *(float2*)(C + (long long)r * ldc + cc) = lo;
            *(float2*)(C + (long long)(r + 8) * ldc + cc) = hi;
        }
    }
}

// ===================== in-chunk forward substitution =====================
__global__ void chunksolve_kernel(float* __restrict__ u, const float* __restrict__ KK, int ci) {
    __shared__ float Ks[64][64];
    int batch = blockIdx.y;
    int d = blockIdx.x * 256 + threadIdx.x;
    const float* KKb = KK + (size_t)batch * TT * TT;
    float* ub = u + (size_t)batch * TT * DD;
    int base = ci * 64;
    for (int i = threadIdx.x; i < 64 * 64; i += 256) {
        int r = i >> 6, c = i & 63;
        Ks[r][c] = KKb[(size_t)(base + r) * TT + base + c];
    }
    __syncthreads();
    float uloc[64];
#pragma unroll
    for (int r = 0; r < 64; ++r) {
        float val = ub[(size_t)(base + r) * DD + d];
#pragma unroll
        for (int s = 0; s < r; ++s) val -= Ks[r][s] * uloc[s];
        uloc[r] = val;
        ub[(size_t)(base + r) * DD + d] = val;
    }
}

// ===================== SIMT SGEMM (solve rank-64 updates): C -= A@B =====================
__global__ void sgemm_upd_kernel(const float* __restrict__ A, const float* __restrict__ B,
                                 float* __restrict__ C, int M, int N, int K,
                                 int lda, int ldb, int ldc,
                                 long long sA, long long sB, long long sC) {
    long long z = blockIdx.z;
    A += z * sA; B += z * sB; C += z * sC;
    int m0 = blockIdx.y * 128, n0 = blockIdx.x * 128;
    __shared__ float As[8][128];
    __shared__ float Bs[8][128];
    int tid = threadIdx.x;
    int tx = tid & 15, ty = tid >> 4;
    int ar = tid >> 1, ac = (tid & 1) * 4;
    int br = tid >> 5, bc = (tid & 31) * 4;
    float acc[8][8];
#pragma unroll
    for (int i = 0; i < 8; ++i)
#pragma unroll
        for (int j = 0; j < 8; ++j) acc[i][j] = 0.0f;
    for (int k0 = 0; k0 < K; k0 += 8) {
        float4 av = make_float4(0.f, 0.f, 0.f, 0.f);
        if (m0 + ar < M) av = *(const float4*)(A + (long long)(m0 + ar) * lda + k0 + ac);
        As[ac + 0][ar] = av.x; As[ac + 1][ar] = av.y;
        As[ac + 2][ar] = av.z; As[ac + 3][ar] = av.w;
        float4 bv = *(const float4*)(B + (long long)(k0 + br) * ldb + n0 + bc);
        *(float4*)&Bs[br][bc] = bv;
        __syncthreads();
#pragma unroll
        for (int k = 0; k < 8; ++k) {
            float ra[8], rb[8];
            *(float4*)&ra[0] = *(float4*)&As[k][ty * 8];
            *(float4*)&ra[4] = *(float4*)&As[k][ty * 8 + 4];
            *(float4*)&rb[0] = *(float4*)&Bs[k][tx * 8];
            *(float4*)&rb[4] = *(float4*)&Bs[k][tx * 8 + 4];
#pragma unroll
            for (int i = 0; i < 8; ++i)
#pragma unroll
                for (int j = 0; j < 8; ++j) acc[i][j] += ra[i] * rb[j];
        }
        __syncthreads();
    }
#pragma unroll
    for (int i = 0; i < 8; ++i) {
        int r = m0 + ty * 8 + i;
        if (r >= M) continue;
#pragma unroll
        for (int j = 0; j < 8; ++j) {
            int c = n0 + tx * 8 + j;
            C[(long long)r * ldc + c] -= acc[i][j];
        }
    }
}

// ===================== host launcher =====================
static void launch_tgemm(int flags, const __nv_bfloat16* Ah, const __nv_bfloat16* Al,
                         const __nv_bfloat16* Bh, const __nv_bfloat16* Bl,
                         const float* bias, const float* resid, float* C,
                         int M, int N, int K, int lda, int ldb, int ldc,
                         long long sA, long long sB, long long sC, int batch) {
    dim3 grid(M / 128, N / 128, batch);  // x = M tiles (L2 reuse of A)
    tgemm_kernel<<<grid, 256, TG_DYN_SMEM>>>(Ah, Al, Bh, Bl, bias, resid, C, K,
                                             lda, ldb, ldc, sA, sB, sC, flags);
}

extern "C" void kernel_launch(void* const* d_in, const int* in_sizes, int n_in,
                              void* d_out, int out_size) {
    const int* ids = (const int*)d_in[0];
    const float* E = (const float*)d_in[1];
    const float* Wg = (const float*)d_in[2];
    const float* bg = (const float*)d_in[3];
    const float* Wlr = (const float*)d_in[4];
    const float* blr = (const float*)d_in[5];
    const float* Wo = (const float*)d_in[6];
    const float* bo = (const float*)d_in[7];
    const float* g_d = (const float*)d_in[8];
    const float* b_d = (const float*)d_in[9];
    const float* W1 = (const float*)d_in[10];
    const float* b1 = (const float*)d_in[11];
    const float* W2 = (const float*)d_in[12];
    const float* b2 = (const float*)d_in[13];
    const float* g_m = (const float*)d_in[14];
    const float* b_m = (const float*)d_in[15];
    const float* g_o = (const float*)d_in[16];
    const float* b_o = (const float*)d_in[17];
    float* out = (float*)d_out;

    float *x, *h, *qkv, *lr, *KK, *u, *score, *y, *a;
    cudaGetSymbolAddress((void**)&x, g_x);
    cudaGetSymbolAddress((void**)&h, g_h);
    cudaGetSymbolAddress((void**)&qkv, g_qkv);
    cudaGetSymbolAddress((void**)&lr, g_lr);
    cudaGetSymbolAddress((void**)&KK, g_KK);
    cudaGetSymbolAddress((void**)&u, g_u);
    cudaGetSymbolAddress((void**)&score, g_score);
    cudaGetSymbolAddress((void**)&y, g_y);
    cudaGetSymbolAddress((void**)&a, g_a);
    __nv_bfloat16 *Eh, *El, *WgTh, *WgTl, *WoTh, *WoTl, *W1Th, *W1Tl, *W2Th, *W2Tl;
    __nv_bfloat16 *hh, *hl, *qh, *ql, *kh, *kl, *uth, *utl, *sh, *sl, *yh, *yl, *ah, *al;
    cudaGetSymbolAddress((void**)&Eh, g_Eh); cudaGetSymbolAddress((void**)&El, g_El);
    cudaGetSymbolAddress((void**)&WgTh, g_WgTh); cudaGetSymbolAddress((void**)&WgTl, g_WgTl);
    cudaGetSymbolAddress((void**)&WoTh, g_WoTh); cudaGetSymbolAddress((void**)&WoTl, g_WoTl);
    cudaGetSymbolAddress((void**)&W1Th, g_W1Th); cudaGetSymbolAddress((void**)&W1Tl, g_W1Tl);
    cudaGetSymbolAddress((void**)&W2Th, g_W2Th); cudaGetSymbolAddress((void**)&W2Tl, g_W2Tl);
    cudaGetSymbolAddress((void**)&hh, g_hh); cudaGetSymbolAddress((void**)&hl, g_hl);
    cudaGetSymbolAddress((void**)&qh, g_qh); cudaGetSymbolAddress((void**)&ql, g_ql);
    cudaGetSymbolAddress((void**)&kh, g_kh); cudaGetSymbolAddress((void**)&kl, g_kl);
    cudaGetSymbolAddress((void**)&uth, g_uth); cudaGetSymbolAddress((void**)&utl, g_utl);
    cudaGetSymbolAddress((void**)&sh, g_sh); cudaGetSymbolAddress((void**)&sl, g_sl);
    cudaGetSymbolAddress((void**)&yh, g_yh); cudaGetSymbolAddress((void**)&yl, g_yl);
    cudaGetSymbolAddress((void**)&ah, g_ahh); cudaGetSymbolAddress((void**)&al, g_ahl);

    const long long sTT = (long long)TT * TT;
    const long long sTD = (long long)TT * DD;

    // ---- prepass: split E; transpose+split weights ----
    {
        long long nE = (long long)VV * DD;
        split_kernel<<<(int)((nE / 4 + 255) / 256), 256>>>(E, Eh, El, nE);
        dim3 tb(32, 8);
        tsplit_kernel<<<dim3(3 * DD / 32, DD / 32, LL), tb>>>(Wg, WgTh, WgTl, DD, 3 * DD,
                                                              (long long)DD * 3 * DD, (long long)DD * 3 * DD);
        tsplit_kernel<<<dim3(DD / 32, DD / 32, LL), tb>>>(Wo, WoTh, WoTl, DD, DD,
                                                          (long long)DD * DD, (long long)DD * DD);
        tsplit_kernel<<<dim3(DD / 32, DD / 32, LL), tb>>>(W1, W1Th, W1Tl, DD, DD,
                                                          (long long)DD * DD, (long long)DD * DD);
        tsplit_kernel<<<dim3(DD / 32, DD / 32, LL), tb>>>(W2, W2Th, W2Tl, DD, DD,
                                                          (long long)DD * DD, (long long)DD * DD);
    }

    embed_kernel<<<MTOT, 256>>>(x, E, ids);

    const long long nTD = (long long)MTOT * DD;
    const long long nSS = (long long)NB * TT * TT;

    for (int l = 0; l < LL; ++l) {
        const __nv_bfloat16* WgTh_l = WgTh + (size_t)l * 3 * DD * DD;
        const __nv_bfloat16* WgTl_l = WgTl + (size_t)l * 3 * DD * DD;
        const __nv_bfloat16* WoTh_l = WoTh + (size_t)l * DD * DD;
        const __nv_bfloat16* WoTl_l = WoTl + (size_t)l * DD * DD;
        const __nv_bfloat16* W1Th_l = W1Th + (size_t)l * DD * DD;
        const __nv_bfloat16* W1Tl_l = W1Tl + (size_t)l * DD * DD;
        const __nv_bfloat16* W2Th_l = W2Th + (size_t)l * DD * DD;
        const __nv_bfloat16* W2Tl_l = W2Tl + (size_t)l * DD * DD;

        // --- delta block ---
        ln_kernel<<<MTOT, 256>>>(h, x, g_d + (size_t)l * DD, b_d + (size_t)l * DD);
        split_kernel<<<(int)((nTD / 4 + 255) / 256), 256>>>(h, hh, hl, nTD);
        // qkv = h @ Wg + bg   (NT with B = Wg^T [3D, D])
        launch_tgemm(4, hh, hl, WgTh_l, WgTl_l, bg + (size_t)l * 3 * DD, nullptr, qkv,
                     MTOT, 3 * DD, DD, DD, DD, 3 * DD, 0, 0, 0, 1);
        knorm_lr_kernel<<<MTOT, 256>>>(qkv, h, Wlr + (size_t)l * DD, blr + l, lr);
        split_rows_kernel<<<MTOT, 256>>>(qkv, qh, ql, 3 * DD);
        split_rows_kernel<<<MTOT, 256>>>(qkv + DD, kh, kl, 3 * DD);
        // KK = stril(k k^T, -1)
        launch_tgemm(2, kh, kl, kh, kl, nullptr, nullptr, KK,
                     TT, TT, DD, DD, DD, TT, sTD, sTD, sTT, NB);
        // solve (I + KK) u = v
        copyv_kernel<<<MTOT, 256>>>(u, qkv);
        for (int ci = 0; ci < 16; ++ci) {
            chunksolve_kernel<<<dim3(DD / 256, NB), 256>>>(u, KK, ci);
            if (ci < 15) {
                int r0 = 64 * (ci + 1);
                int Mu = TT - r0;
                sgemm_upd_kernel<<<dim3(DD / 128, (Mu + 127) / 128, NB), 256>>>(
                    KK + (size_t)r0 * TT + ci * 64, u + (size_t)ci * 64 * DD,
                    u + (size_t)r0 * DD, Mu, DD, 64, TT, DD, DD, sTT, sTD, sTD);
            }
        }
        scaleu_kernel<<<MTOT, 256>>>(u, lr);
        {
            dim3 tb(32, 8);
            tsplit_kernel<<<dim3(DD / 32, TT / 32, NB), tb>>>(u, uth, utl, TT, DD, sTD, sTD);
        }
        // score = q @ k^T (full)
        launch_tgemm(0, qh, ql, kh, kl, nullptr, nullptr, score,
                     TT, TT, DD, DD, DD, TT, sTD, sTD, sTT, NB);
        split_kernel<<<(int)((nSS / 4 + 255) / 256), 256>>>(score, sh, sl, nSS);
        // y = score @ u   (NT with B = u^T [D, T])
        launch_tgemm(0, sh, sl, uth, utl, nullptr, nullptr, y,
                     TT, DD, TT, TT, TT, DD, sTT, sTD, sTD, NB);
        split_kernel<<<(int)((nTD / 4 + 255) / 256), 256>>>(y, yh, yl, nTD);
        // x = x + y @ Wo + bo
        launch_tgemm(12, yh, yl, WoTh_l, WoTl_l, bo + (size_t)l * DD, x, x,
                     MTOT, DD, DD, DD, DD, DD, 0, 0, 0, 1);

        // --- MLP block ---
        ln_kernel<<<MTOT, 256>>>(h, x, g_m + (size_t)l * DD, b_m + (size_t)l * DD);
        split_kernel<<<(int)((nTD / 4 + 255) / 256), 256>>>(h, hh, hl, nTD);
        launch_tgemm(5, hh, hl, W1Th_l, W1Tl_l, b1 + (size_t)l * DD, nullptr, a,
                     MTOT, DD, DD, DD, DD, DD, 0, 0, 0, 1);
        split_kernel<<<(int)((nTD / 4 + 255) / 256), 256>>>(a, ah, al, nTD);
        launch_tgemm(12, ah, al, W2Th_l, W2Tl_l, b2 + (size_t)l * DD, x, x,
                     MTOT, DD, DD, DD, DD, DD, 0, 0, 0, 1);
    }

    // final LN + tied decoder
    ln_kernel<<<MTOT, 256>>>(h, x, g_o, b_o);
    split_kernel<<<(int)((nTD / 4 + 255) / 256), 256>>>(h, hh, hl, nTD);
    launch_tgemm(0, hh, hl, Eh, El, nullptr, nullptr, out,
                 MTOT, VV, DD, DD, DD, VV, 0, 0, 0, 1);
}

// round 7
// speedup vs baseline: 1.6865x; 1.0957x over previous
#include <cuda_runtime.h>
#include <cuda_fp16.h>
#include <cstdint>

// Problem constants
#define NB 4          // batch
#define TT 1024       // seq len
#define DD 1024       // dim
#define LL 4          // layers
#define VV 32000      // vocab
#define MTOT (NB*TT)  // 4096 rows

// ===================== PTX helpers (base ISA only) =====================
__device__ __forceinline__ uint32_t smem_to_u32(const void* p) {
    uint32_t a;
    asm("{ .reg .u64 t; cvta.to.shared.u64 t, %1; cvt.u32.u64 %0, t; }" : "=r"(a) : "l"(p));
    return a;
}
#define CP_ASYNC16(dst, src) \
    asm volatile("cp.async.cg.shared.global [%0], [%1], 16;" :: "r"((uint32_t)(dst)), "l"(src))
#define CP_ASYNC_COMMIT() asm volatile("cp.async.commit_group;" ::: "memory")
#define CP_ASYNC_WAIT(n) asm volatile("cp.async.wait_group %0;" :: "n"(n) : "memory")

__device__ __forceinline__ void ldmx4(uint32_t* r, uint32_t addr) {
    asm volatile("ldmatrix.sync.aligned.m8n8.x4.shared.b16 {%0,%1,%2,%3}, [%4];"
                 : "=r"(r[0]), "=r"(r[1]), "=r"(r[2]), "=r"(r[3]) : "r"(addr));
}
__device__ __forceinline__ void mma16816(float* c, const uint32_t* a, const uint32_t* b) {
    asm volatile(
        "mma.sync.aligned.m16n8k16.row.col.f32.f16.f16.f32 "
        "{%0,%1,%2,%3}, {%4,%5,%6,%7}, {%8,%9}, {%0,%1,%2,%3};"
        : "+f"(c[0]), "+f"(c[1]), "+f"(c[2]), "+f"(c[3])
        : "r"(a[0]), "r"(a[1]), "r"(a[2]), "r"(a[3]), "r"(b[0]), "r"(b[1]));
}

// ===================== scratch (device globals) =====================
__device__ float g_x[MTOT * DD];
__device__ float g_qkv[MTOT * 3 * DD];
__device__ float g_lr[MTOT];
__device__ float g_KK[NB * TT * TT];
__device__ float g_u[MTOT * DD];
// fp16 hi/lo pairs
__device__ __half g_Eh[VV * DD], g_El[VV * DD];
__device__ __half g_WgT[LL * 3 * DD * DD], g_WgTl[LL * 3 * DD * DD];
__device__ __half g_WoT[LL * DD * DD], g_WoTl[LL * DD * DD];
__device__ __half g_W1T[LL * DD * DD], g_W1Tl[LL * DD * DD];
__device__ __half g_W2T[LL * DD * DD], g_W2Tl[LL * DD * DD];
__device__ __half g_hh[MTOT * DD], g_hhl[MTOT * DD];
__device__ __half g_qh[MTOT * DD], g_qhl[MTOT * DD];
__device__ __half g_kh[MTOT * DD], g_khl[MTOT * DD];
__device__ __half g_ut[MTOT * DD], g_utl[MTOT * DD];
__device__ __half g_sh[NB * TT * TT], g_shl[NB * TT * TT];
__device__ __half g_yh[MTOT * DD], g_yhl[MTOT * DD];
__device__ __half g_ah[MTOT * DD], g_ahl[MTOT * DD];

// ===================== small kernels =====================
__device__ __forceinline__ float blockReduceSum(float v, float* sdata) {
    int tid = threadIdx.x;
    sdata[tid] = v;
    __syncthreads();
    for (int s = 128; s > 0; s >>= 1) {
        if (tid < s) sdata[tid] += sdata[tid + s];
        __syncthreads();
    }
    float r = sdata[0];
    __syncthreads();
    return r;
}

// write 4 floats as fp16 hi + fp16 lo (lo = residual)
__device__ __forceinline__ void store_h4_pair(__half* ph, __half* pl,
                                              float a, float b, float c, float d) {
    union { __half2 h2[2]; uint2 u; } hi, lo;
    hi.h2[0] = __floats2half2_rn(a, b);
    hi.h2[1] = __floats2half2_rn(c, d);
    lo.h2[0] = __floats2half2_rn(a - __half2float(hi.h2[0].x), b - __half2float(hi.h2[0].y));
    lo.h2[1] = __floats2half2_rn(c - __half2float(hi.h2[1].x), d - __half2float(hi.h2[1].y));
    *(uint2*)ph = hi.u;
    *(uint2*)pl = lo.u;
}

__global__ void embed_kernel(float* __restrict__ x, const float* __restrict__ E,
                             const int* __restrict__ ids) {
    int m = blockIdx.x;
    int id = ids[m];
    const float4* src = (const float4*)(E + (size_t)id * DD);
    float4* dst = (float4*)(x + (size_t)m * DD);
    dst[threadIdx.x] = src[threadIdx.x];
}

// LayerNorm -> fp16 hi/lo out; optionally fused lr = LN(x)@Wlr + blr
__global__ void ln_kernel(__half* __restrict__ oh, __half* __restrict__ ol,
                          const float* __restrict__ in,
                          const float* __restrict__ g, const float* __restrict__ b,
                          const float* __restrict__ Wlr, const float* __restrict__ blr,
                          float* __restrict__ lr) {
    __shared__ float sdata[256];
    int m = blockIdx.x, tid = threadIdx.x;
    const float* row = in + (size_t)m * DD;
    float4 v = *(const float4*)(row + tid * 4);
    float s = v.x + v.y + v.z + v.w;
    float mean = blockReduceSum(s, sdata) * (1.0f / DD);
    float dx = v.x - mean, dy = v.y - mean, dz = v.z - mean, dw = v.w - mean;
    float s2 = dx * dx + dy * dy + dz * dz + dw * dw;
    float var = blockReduceSum(s2, sdata) * (1.0f / DD);
    float rstd = 1.0f / sqrtf(var + 1e-5f);
    int c = tid * 4;
    float n0 = dx * rstd * g[c + 0] + b[c + 0];
    float n1 = dy * rstd * g[c + 1] + b[c + 1];
    float n2 = dz * rstd * g[c + 2] + b[c + 2];
    float n3 = dw * rstd * g[c + 3] + b[c + 3];
    store_h4_pair(oh + (size_t)m * DD + c, ol + (size_t)m * DD + c, n0, n1, n2, n3);
    if (Wlr) {
        float4 wv = *(const float4*)(Wlr + c);
        float d = n0 * wv.x + n1 * wv.y + n2 * wv.z + n3 * wv.w;
        float dot = blockReduceSum(d, sdata);
        if (tid == 0) lr[m] = dot + blr[0];
    }
}

// normalize k -> kh/kl; q -> qh/ql; copy v -> u (fp32)
__global__ void knorm_kernel(const float* __restrict__ qkv,
                             __half* __restrict__ qh, __half* __restrict__ ql,
                             __half* __restrict__ kh, __half* __restrict__ kl,
                             float* __restrict__ u) {
    __shared__ float sdata[256];
    int m = blockIdx.x, tid = threadIdx.x;
    const float* base = qkv + (size_t)m * (3 * DD);
    int c = tid * 4;
    float4 kv = *(const float4*)(base + DD + c);
    float ss = kv.x * kv.x + kv.y * kv.y + kv.z * kv.z + kv.w * kv.w;
    float ksum = blockReduceSum(ss, sdata);
    float scale = 1.0f / sqrtf(ksum);
    size_t o = (size_t)m * DD + c;
    store_h4_pair(kh + o, kl + o, kv.x * scale, kv.y * scale, kv.z * scale, kv.w * scale);
    float4 qv = *(const float4*)(base + c);
    store_h4_pair(qh + o, ql + o, qv.x, qv.y, qv.z, qv.w);
    *(float4*)(u + o) = *(const float4*)(base + 2 * DD + c);
}

// transpose + lr-scale + fp16 hi/lo: u [T,D] fp32 -> ut [D,T] (batched via z)
__global__ void tscale_kernel(const float* __restrict__ u, const float* __restrict__ lr,
                              __half* __restrict__ ut, __half* __restrict__ utl) {
    __shared__ float tile[32][33];
    long long z = blockIdx.z;
    u += z * (long long)TT * DD;
    ut += z * (long long)TT * DD;
    utl += z * (long long)TT * DD;
    lr += z * TT;
    int r0 = blockIdx.y * 32, c0 = blockIdx.x * 32;
    int tx = threadIdx.x, ty = threadIdx.y;  // 32 x 8
#pragma unroll
    for (int i = 0; i < 32; i += 8)
        tile[ty + i][tx] = u[(size_t)(r0 + ty + i) * DD + c0 + tx] * lr[r0 + ty + i];
    __syncthreads();
#pragma unroll
    for (int i = 0; i < 32; i += 8) {
        int c = c0 + ty + i, r = r0 + tx;
        float v = tile[tx][ty + i];
        __half hv = __float2half_rn(v);
        ut[(size_t)c * TT + r] = hv;
        utl[(size_t)c * TT + r] = __float2half_rn(v - __half2float(hv));
    }
}

// fp32 -> fp16 hi/lo elementwise (for E)
__global__ void csplit_kernel(const float* __restrict__ in, __half* __restrict__ oh,
                              __half* __restrict__ ol, long long n) {
    long long i = ((long long)blockIdx.x * blockDim.x + threadIdx.x) * 4;
    if (i >= n) return;
    float4 v = *(const float4*)(in + i);
    store_h4_pair(oh + i, ol + i, v.x, v.y, v.z, v.w);
}

// transpose + fp16 hi/lo: in [R,C] fp32 -> out [C,R] (batched via z)
__global__ void tsplit_kernel(const float* __restrict__ in, __half* __restrict__ oh,
                              __half* __restrict__ ol, int R, int C,
                              long long sIn, long long sOut) {
    __shared__ float tile[32][33];
    long long z = blockIdx.z;
    in += z * sIn; oh += z * sOut; ol += z * sOut;
    int r0 = blockIdx.y * 32, c0 = blockIdx.x * 32;
    int tx = threadIdx.x, ty = threadIdx.y;
#pragma unroll
    for (int i = 0; i < 32; i += 8)
        tile[ty + i][tx] = in[(size_t)(r0 + ty + i) * C + c0 + tx];
    __syncthreads();
#pragma unroll
    for (int i = 0; i < 32; i += 8) {
        int c = c0 + ty + i, r = r0 + tx;
        float v = tile[tx][ty + i];
        __half hv = __float2half_rn(v);
        oh[(size_t)c * R + r] = hv;
        ol[(size_t)c * R + r] = __float2half_rn(v - __half2float(hv));
    }
}

// ============ mma.sync fp16x2-split NT GEMM ============
// C = A@B^T with A=(Ah+Al), B=(Bh+Bl) fp16 pairs (split: 3 MMAs, drop Al*Bl).
// A: [M,K] K-contiguous; B: [N,K] K-contiguous.
// CTA 128x128, BK=32, 256 thr = 8 warps (4m x 2n), warp tile 32x64.
// smem/stage: 4 tiles x 128 rows x 80B = 40960B; 3 stages = 122880B (opt-in).
// flags: 1=relu 2=strict-lower-mask 4=bias 8=resid 16=split
#define TILE_B 10240
#define STAGE_B 40960
#define TG_DYN_SMEM 122880

__global__ void __launch_bounds__(256, 1)
hgemm_kernel(const __half* __restrict__ Ah, const __half* __restrict__ Al,
             const __half* __restrict__ Bh, const __half* __restrict__ Bl,
             const float* __restrict__ bias, const float* __restrict__ resid,
             float* __restrict__ C, __half* __restrict__ Ch, __half* __restrict__ Chl,
             int K, int lda, int ldb, int ldc,
             long long sA, long long sB, long long sC, int flags) {
    long long z = blockIdx.z;
    Ah += z * sA; Bh += z * sB;
    if (Al) Al += z * sA;
    if (Bl) Bl += z * sB;
    if (C) C += z * sC;
    if (Ch) Ch += z * sC;
    if (Chl) Chl += z * sC;
    if (resid) resid += z * sC;
    int m0 = blockIdx.x * 128, n0 = blockIdx.y * 128;
    if ((flags & 2) && n0 >= m0 + 128) return;  // fully above strict-lower diagonal
    const bool split = (flags & 16) != 0;

    extern __shared__ char dynsmem[];
    uint32_t sb = smem_to_u32(dynsmem);
    int tid = threadIdx.x, lane = tid & 31, wid = tid >> 5;
    int wm = wid >> 1, wn = wid & 1;  // warp grid 4(m) x 2(n)

    // loader: thread t: row (t&127) of pair (t>>7): 0 -> A(hi,lo), 1 -> B(hi,lo). 64B/row/tile.
    int ldrow = tid & 127, ldpair = tid >> 7;
    const __half* ph = (ldpair ? Bh : Ah) + (size_t)((ldpair ? n0 : m0) + ldrow) * (ldpair ? ldb : lda);
    const __half* pl = split ? ((ldpair ? Bl : Al) + (size_t)((ldpair ? n0 : m0) + ldrow) * (ldpair ? ldb : lda))
                             : nullptr;
    uint32_t dsth = sb + ldpair * 2 * TILE_B + ldrow * 80;
    uint32_t dstl = dsth + TILE_B;

    const int nch = K >> 5;  // BK = 32

#define ISSUE_STAGE(cc) do {                                                  \
        uint32_t _so = ((cc) % 3) * STAGE_B;                                  \
        const __half* _q = ph + ((size_t)(cc) << 5);                          \
        CP_ASYNC16(dsth + _so, _q);           CP_ASYNC16(dsth + _so + 16, _q + 8);  \
        CP_ASYNC16(dsth + _so + 32, _q + 16); CP_ASYNC16(dsth + _so + 48, _q + 24); \
        if (split) {                                                          \
            const __half* _ql = pl + ((size_t)(cc) << 5);                     \
            CP_ASYNC16(dstl + _so, _ql);           CP_ASYNC16(dstl + _so + 16, _ql + 8);  \
            CP_ASYNC16(dstl + _so + 32, _ql + 16); CP_ASYNC16(dstl + _so + 48, _ql + 24); \
        }                                                                     \
        CP_ASYNC_COMMIT();                                                    \
    } while (0)

    ISSUE_STAGE(0);
    ISSUE_STAGE(1);

    float acc[2][8][4];
#pragma unroll
    for (int i = 0; i < 2; ++i)
#pragma unroll
        for (int j = 0; j < 8; ++j)
#pragma unroll
            for (int r = 0; r < 4; ++r) acc[i][j][r] = 0.0f;

    // ldmatrix per-lane offsets (row stride 80B; k16-halves at +0/+16; 2nd k16 block at +32)
    uint32_t a_off = (lane & 15) * 80 + (lane >> 4) * 16;
    uint32_t b_off = ((lane & 7) + ((lane >> 4) & 1) * 8) * 80 + ((lane >> 3) & 1) * 16;

    for (int c = 0; c < nch; ++c) {
        if (c + 2 < nch) {
            ISSUE_STAGE(c + 2);
            CP_ASYNC_WAIT(2);
        } else if (c + 1 < nch) {
            CP_ASYNC_WAIT(1);
        } else {
            CP_ASYNC_WAIT(0);
        }
        __syncthreads();

        uint32_t st = sb + (c % 3) * STAGE_B;
        uint32_t aBase = st + (wm * 32) * 80 + a_off;
        uint32_t alBase = aBase + TILE_B;
        uint32_t bBase = st + 2 * TILE_B + (wn * 64) * 80 + b_off;
        uint32_t blBase = bBase + TILE_B;

#pragma unroll
        for (int kk = 0; kk < 2; ++kk) {  // two k16 steps in BK=32
            uint32_t kof = kk * 32;
            uint32_t af[2][4], alf[2][4];
#pragma unroll
            for (int i = 0; i < 2; ++i) {
                ldmx4(af[i], aBase + i * 1280 + kof);   // 16 rows * 80B
                if (split) ldmx4(alf[i], alBase + i * 1280 + kof);
            }
            uint32_t bf[8][2], blf[8][2];
#pragma unroll
            for (int jj = 0; jj < 4; ++jj) {
                uint32_t r[4];
                ldmx4(r, bBase + jj * 1280 + kof);
                bf[2 * jj][0] = r[0]; bf[2 * jj][1] = r[1];
                bf[2 * jj + 1][0] = r[2]; bf[2 * jj + 1][1] = r[3];
                if (split) {
                    ldmx4(r, blBase + jj * 1280 + kof);
                    blf[2 * jj][0] = r[0]; blf[2 * jj][1] = r[1];
                    blf[2 * jj + 1][0] = r[2]; blf[2 * jj + 1][1] = r[3];
                }
            }
#pragma unroll
            for (int i = 0; i < 2; ++i)
#pragma unroll
                for (int j = 0; j < 8; ++j) {
                    mma16816(acc[i][j], af[i], bf[j]);
                    if (split) {
                        mma16816(acc[i][j], af[i], blf[j]);
                        mma16816(acc[i][j], alf[i], bf[j]);
                    }
                }
        }
        __syncthreads();
    }

    // epilogue
    int rbase = m0 + wm * 32 + (lane >> 2);
    int cbase = n0 + wn * 64 + (lane & 3) * 2;
#pragma unroll
    for (int i = 0; i < 2; ++i) {
        int r = rbase + i * 16;
#pragma unroll
        for (int j = 0; j < 8; ++j) {
            int cc = cbase + j * 8;
            float2 lo = make_float2(acc[i][j][0], acc[i][j][1]);
            float2 hi = make_float2(acc[i][j][2], acc[i][j][3]);
            if (flags & 4) {
                float2 bv = *(const float2*)(bias + cc);
                lo.x += bv.x; lo.y += bv.y; hi.x += bv.x; hi.y += bv.y;
            }
            if (flags & 8) {
                float2 r0 = *(const float2*)(resid + (long long)r * ldc + cc);
                float2 r1 = *(const float2*)(resid + (long long)(r + 8) * ldc + cc);
                lo.x += r0.x; lo.y += r0.y; hi.x += r1.x; hi.y += r1.y;
            }
            if (flags & 1) {
                lo.x = fmaxf(lo.x, 0.f); lo.y = fmaxf(lo.y, 0.f);
                hi.x = fmaxf(hi.x, 0.f); hi.y = fmaxf(hi.y, 0.f);
            }
            if (flags & 2) {
                if (cc + 0 >= r) lo.x = 0.f;
                if (cc + 1 >= r) lo.y = 0.f;
                if (cc + 0 >= r + 8) hi.x = 0.f;
                if (cc + 1 >= r + 8) hi.y = 0.f;
            }
            if (Ch) {
                __half2 hlo = __floats2half2_rn(lo.x, lo.y);
                __half2 hhi = __floats2half2_rn(hi.x, hi.y);
                *(__half2*)(Ch + (long long)r * ldc + cc) = hlo;
                *(__half2*)(Ch + (long long)(r + 8) * ldc + cc) = hhi;
                if (Chl) {
                    *(__half2*)(Chl + (long long)r * ldc + cc) =
                        __floats2half2_rn(lo.x - __half2float(hlo.x), lo.y - __half2float(hlo.y));
                    *(__half2*)(Chl + (long long)(r + 8) * ldc + cc) =
                        __floats2half2_rn(hi.x - __half2float(hhi.x), hi.y - __half2float(hhi.y));
                }
            } else {
                *(float2*)(C + (long long)r * ldc + cc) = lo;
                *(float2*)(C + (long long)(r + 8) * ldc + cc) = hi;
            }
        }
    }
#undef ISSUE_STAGE
}

// ===================== in-chunk forward substitution =====================
__global__ void chunksolve_kernel(float* __restrict__ u, const float* __restrict__ KK, int ci) {
    __shared__ float Ks[64][64];
    int batch = blockIdx.y;
    int d = blockIdx.x * 256 + threadIdx.x;
    const float* KKb = KK + (size_t)batch * TT * TT;
    float* ub = u + (size_t)batch * TT * DD;
    int base = ci * 64;
    for (int i = threadIdx.x; i < 64 * 64; i += 256) {
        int r = i >> 6, c = i & 63;
        Ks[r][c] = KKb[(size_t)(base + r) * TT + base + c];
    }
    __syncthreads();
    float uloc[64];
#pragma unroll
    for (int r = 0; r < 64; ++r) {
        float val = ub[(size_t)(base + r) * DD + d];
#pragma unroll
        for (int s = 0; s < r; ++s) val -= Ks[r][s] * uloc[s];
        uloc[r] = val;
        ub[(size_t)(base + r) * DD + d] = val;
    }
}

// ===================== SIMT SGEMM (solve rank-64 updates): C -= A@B =====================
__global__ void sgemm_upd_kernel(const float* __restrict__ A, const float* __restrict__ B,
                                 float* __restrict__ C, int M, int N, int K,
                                 int lda, int ldb, int ldc,
                                 long long sA, long long sB, long long sC) {
    long long z = blockIdx.z;
    A += z * sA; B += z * sB; C += z * sC;
    int m0 = blockIdx.y * 128, n0 = blockIdx.x * 128;
    __shared__ float As[8][128];
    __shared__ float Bs[8][128];
    int tid = threadIdx.x;
    int tx = tid & 15, ty = tid >> 4;
    int ar = tid >> 1, ac = (tid & 1) * 4;
    int br = tid >> 5, bc = (tid & 31) * 4;
    float acc[8][8];
#pragma unroll
    for (int i = 0; i < 8; ++i)
#pragma unroll
        for (int j = 0; j < 8; ++j) acc[i][j] = 0.0f;
    for (int k0 = 0; k0 < K; k0 += 8) {
        float4 av = make_float4(0.f, 0.f, 0.f, 0.f);
        if (m0 + ar < M) av = *(const float4*)(A + (long long)(m0 + ar) * lda + k0 + ac);
        As[ac + 0][ar] = av.x; As[ac + 1][ar] = av.y;
        As[ac + 2][ar] = av.z; As[ac + 3][ar] = av.w;
        float4 bv = *(const float4*)(B + (long long)(k0 + br) * ldb + n0 + bc);
        *(float4*)&Bs[br][bc] = bv;
        __syncthreads();
#pragma unroll
        for (int k = 0; k < 8; ++k) {
            float ra[8], rb[8];
            *(float4*)&ra[0] = *(float4*)&As[k][ty * 8];
            *(float4*)&ra[4] = *(float4*)&As[k][ty * 8 + 4];
            *(float4*)&rb[0] = *(float4*)&Bs[k][tx * 8];
            *(float4*)&rb[4] = *(float4*)&Bs[k][tx * 8 + 4];
#pragma unroll
            for (int i = 0; i < 8; ++i)
#pragma unroll
                for (int j = 0; j < 8; ++j) acc[i][j] += ra[i] * rb[j];
        }
        __syncthreads();
    }
#pragma unroll
    for (int i = 0; i < 8; ++i) {
        int r = m0 + ty * 8 + i;
        if (r >= M) continue;
#pragma unroll
        for (int j = 0; j < 8; ++j) {
            int c = n0 + tx * 8 + j;
            C[(long long)r * ldc + c] -= acc[i][j];
        }
    }
}

// ===================== host launcher =====================
static void launch_hgemm(int flags, const __half* Ah, const __half* Al,
                         const __half* Bh, const __half* Bl,
                         const float* bias, const float* resid,
                         float* C, __half* Ch, __half* Chl,
                         int M, int N, int K, int lda, int ldb, int ldc,
                         long long sA, long long sB, long long sC, int batch) {
    dim3 grid(M / 128, N / 128, batch);  // x = M tiles (L2 reuse of A)
    hgemm_kernel<<<grid, 256, TG_DYN_SMEM>>>(Ah, Al, Bh, Bl, bias, resid, C, Ch, Chl,
                                             K, lda, ldb, ldc, sA, sB, sC, flags);
}

extern "C" void kernel_launch(void* const* d_in, const int* in_sizes, int n_in,
                              void* d_out, int out_size) {
    const int* ids = (const int*)d_in[0];
    const float* E = (const float*)d_in[1];
    const float* Wg = (const float*)d_in[2];
    const float* bg = (const float*)d_in[3];
    const float* Wlr = (const float*)d_in[4];
    const float* blr = (const float*)d_in[5];
    const float* Wo = (const float*)d_in[6];
    const float* bo = (const float*)d_in[7];
    const float* g_d = (const float*)d_in[8];
    const float* b_d = (const float*)d_in[9];
    const float* W1 = (const float*)d_in[10];
    const float* b1 = (const float*)d_in[11];
    const float* W2 = (const float*)d_in[12];
    const float* b2 = (const float*)d_in[13];
    const float* g_m = (const float*)d_in[14];
    const float* b_m = (const float*)d_in[15];
    const float* g_o = (const float*)d_in[16];
    const float* b_o = (const float*)d_in[17];
    float* out = (float*)d_out;

    // opt-in for 120KB dynamic smem (R4's failure was the ABSENCE of this call)
    cudaFuncSetAttribute(hgemm_kernel, cudaFuncAttributeMaxDynamicSharedMemorySize, TG_DYN_SMEM);

    float *x, *qkv, *lr, *KK, *u;
    cudaGetSymbolAddress((void**)&x, g_x);
    cudaGetSymbolAddress((void**)&qkv, g_qkv);
    cudaGetSymbolAddress((void**)&lr, g_lr);
    cudaGetSymbolAddress((void**)&KK, g_KK);
    cudaGetSymbolAddress((void**)&u, g_u);
    __half *Eh, *El, *WgT, *WgTl, *WoT, *WoTl, *W1T, *W1Tl, *W2T, *W2Tl;
    __half *hh, *hhl, *qh, *qhl, *kh, *khl, *ut, *utl, *sh, *shl, *yh, *yhl, *ah, *ahl;
    cudaGetSymbolAddress((void**)&Eh, g_Eh);   cudaGetSymbolAddress((void**)&El, g_El);
    cudaGetSymbolAddress((void**)&WgT, g_WgT); cudaGetSymbolAddress((void**)&WgTl, g_WgTl);
    cudaGetSymbolAddress((void**)&WoT, g_WoT); cudaGetSymbolAddress((void**)&WoTl, g_WoTl);
    cudaGetSymbolAddress((void**)&W1T, g_W1T); cudaGetSymbolAddress((void**)&W1Tl, g_W1Tl);
    cudaGetSymbolAddress((void**)&W2T, g_W2T); cudaGetSymbolAddress((void**)&W2Tl, g_W2Tl);
    cudaGetSymbolAddress((void**)&hh, g_hh);   cudaGetSymbolAddress((void**)&hhl, g_hhl);
    cudaGetSymbolAddress((void**)&qh, g_qh);   cudaGetSymbolAddress((void**)&qhl, g_qhl);
    cudaGetSymbolAddress((void**)&kh, g_kh);   cudaGetSymbolAddress((void**)&khl, g_khl);
    cudaGetSymbolAddress((void**)&ut, g_ut);   cudaGetSymbolAddress((void**)&utl, g_utl);
    cudaGetSymbolAddress((void**)&sh, g_sh);   cudaGetSymbolAddress((void**)&shl, g_shl);
    cudaGetSymbolAddress((void**)&yh, g_yh);   cudaGetSymbolAddress((void**)&yhl, g_yhl);
    cudaGetSymbolAddress((void**)&ah, g_ah);   cudaGetSymbolAddress((void**)&ahl, g_ahl);

    const long long sTT = (long long)TT * TT;
    const long long sTD = (long long)TT * DD;
    const int SPLIT = 16;

    // ---- prepass: split E; transpose+split weights ----
    {
        long long nE = (long long)VV * DD;
        csplit_kernel<<<(int)((nE / 4 + 255) / 256), 256>>>(E, Eh, El, nE);
        dim3 tb(32, 8);
        tsplit_kernel<<<dim3(3 * DD / 32, DD / 32, LL), tb>>>(Wg, WgT, WgTl, DD, 3 * DD,
                                                              (long long)DD * 3 * DD, (long long)DD * 3 * DD);
        tsplit_kernel<<<dim3(DD / 32, DD / 32, LL), tb>>>(Wo, WoT, WoTl, DD, DD,
                                                          (long long)DD * DD, (long long)DD * DD);
        tsplit_kernel<<<dim3(DD / 32, DD / 32, LL), tb>>>(W1, W1T, W1Tl, DD, DD,
                                                          (long long)DD * DD, (long long)DD * DD);
        tsplit_kernel<<<dim3(DD / 32, DD / 32, LL), tb>>>(W2, W2T, W2Tl, DD, DD,
                                                          (long long)DD * DD, (long long)DD * DD);
    }

    embed_kernel<<<MTOT, 256>>>(x, E, ids);

    for (int l = 0; l < LL; ++l) {
        const __half* WgT_l = WgT + (size_t)l * 3 * DD * DD;
        const __half* WgTl_l = WgTl + (size_t)l * 3 * DD * DD;
        const __half* WoT_l = WoT + (size_t)l * DD * DD;
        const __half* WoTl_l = WoTl + (size_t)l * DD * DD;
        const __half* W1T_l = W1T + (size_t)l * DD * DD;
        const __half* W1Tl_l = W1Tl + (size_t)l * DD * DD;
        const __half* W2T_l = W2T + (size_t)l * DD * DD;
        const __half* W2Tl_l = W2Tl + (size_t)l * DD * DD;

        // --- delta block ---
        ln_kernel<<<MTOT, 256>>>(hh, hhl, x, g_d + (size_t)l * DD, b_d + (size_t)l * DD,
                                 Wlr + (size_t)l * DD, blr + l, lr);
        // qkv = hh @ WgT^T + bg (fp32 out)
        launch_hgemm(SPLIT | 4, hh, hhl, WgT_l, WgTl_l, bg + (size_t)l * 3 * DD, nullptr,
                     qkv, nullptr, nullptr, MTOT, 3 * DD, DD, DD, DD, 3 * DD, 0, 0, 0, 1);
        knorm_kernel<<<MTOT, 256>>>(qkv, qh, qhl, kh, khl, u);
        // KK = stril(k k^T, -1), fp32
        launch_hgemm(SPLIT | 2, kh, khl, kh, khl, nullptr, nullptr,
                     KK, nullptr, nullptr, TT, TT, DD, DD, DD, TT, sTD, sTD, sTT, NB);
        // solve (I + KK) u = v  (fp32 SIMT chain)
        for (int ci = 0; ci < 16; ++ci) {
            chunksolve_kernel<<<dim3(DD / 256, NB), 256>>>(u, KK, ci);
            if (ci < 15) {
                int r0 = 64 * (ci + 1);
                int Mu = TT - r0;
                sgemm_upd_kernel<<<dim3(DD / 128, (Mu + 127) / 128, NB), 256>>>(
                    KK + (size_t)r0 * TT + ci * 64, u + (size_t)ci * 64 * DD,
                    u + (size_t)r0 * DD, Mu, DD, 64, TT, DD, DD, sTT, sTD, sTD);
            }
        }
        // ut = split fp16((lr*u)^T) [D,T]
        {
            dim3 tb(32, 8);
            tscale_kernel<<<dim3(DD / 32, TT / 32, NB), tb>>>(u, lr, ut, utl);
        }
        // sh = split fp16(q @ k^T) (full scores)
        launch_hgemm(SPLIT, qh, qhl, kh, khl, nullptr, nullptr,
                     nullptr, sh, shl, TT, TT, DD, DD, DD, TT, sTD, sTD, sTT, NB);
        // yh = split fp16(sh @ ut^T)
        launch_hgemm(SPLIT, sh, shl, ut, utl, nullptr, nullptr,
                     nullptr, yh, yhl, TT, DD, TT, TT, TT, DD, sTT, sTD, sTD, NB);
        // x = x + yh @ WoT^T + bo (fp32)
        launch_hgemm(SPLIT | 4 | 8, yh, yhl, WoT_l, WoTl_l, bo + (size_t)l * DD, x,
                     x, nullptr, nullptr, MTOT, DD, DD, DD, DD, DD, 0, 0, 0, 1);

        // --- MLP block ---
        ln_kernel<<<MTOT, 256>>>(hh, hhl, x, g_m + (size_t)l * DD, b_m + (size_t)l * DD,
                                 nullptr, nullptr, nullptr);
        launch_hgemm(SPLIT | 4 | 1, hh, hhl, W1T_l, W1Tl_l, b1 + (size_t)l * DD, nullptr,
                     nullptr, ah, ahl, MTOT, DD, DD, DD, DD, DD, 0, 0, 0, 1);
        launch_hgemm(SPLIT | 4 | 8, ah, ahl, W2T_l, W2Tl_l, b2 + (size_t)l * DD, x,
                     x, nullptr, nullptr, MTOT, DD, DD, DD, DD, DD, 0, 0, 0, 1);
    }

    // final LN + tied decoder: out = split-GEMM(LN(x), E^T) fp32
    ln_kernel<<<MTOT, 256>>>(hh, hhl, x, g_o, b_o, nullptr, nullptr, nullptr);
    launch_hgemm(SPLIT, hh, hhl, Eh, El, nullptr, nullptr,
                 out, nullptr, nullptr, MTOT, VV, DD, DD, DD, VV, 0, 0, 0, 1);
}

// round 9
// speedup vs baseline: 1.8547x; 1.0997x over previous
#include <cuda_runtime.h>
#include <cuda_fp16.h>
#include <cstdint>

// Problem constants
#define NB 4          // batch
#define TT 1024       // seq len
#define DD 1024       // dim
#define LL 4          // layers
#define VV 32000      // vocab
#define MTOT (NB*TT)  // 4096 rows

// ===================== PTX helpers (base ISA only) =====================
__device__ __forceinline__ uint32_t smem_to_u32(const void* p) {
    uint32_t a;
    asm("{ .reg .u64 t; cvta.to.shared.u64 t, %1; cvt.u32.u64 %0, t; }" : "=r"(a) : "l"(p));
    return a;
}
#define CP_ASYNC16(dst, src) \
    asm volatile("cp.async.cg.shared.global [%0], [%1], 16;" :: "r"((uint32_t)(dst)), "l"(src))
#define CP_ASYNC_COMMIT() asm volatile("cp.async.commit_group;" ::: "memory")
#define CP_ASYNC_WAIT(n) asm volatile("cp.async.wait_group %0;" :: "n"(n) : "memory")

__device__ __forceinline__ void ldmx4(uint32_t* r, uint32_t addr) {
    asm volatile("ldmatrix.sync.aligned.m8n8.x4.shared.b16 {%0,%1,%2,%3}, [%4];"
                 : "=r"(r[0]), "=r"(r[1]), "=r"(r[2]), "=r"(r[3]) : "r"(addr));
}
__device__ __forceinline__ void mma16816(float* c, const uint32_t* a, const uint32_t* b) {
    asm volatile(
        "mma.sync.aligned.m16n8k16.row.col.f32.f16.f16.f32 "
        "{%0,%1,%2,%3}, {%4,%5,%6,%7}, {%8,%9}, {%0,%1,%2,%3};"
        : "+f"(c[0]), "+f"(c[1]), "+f"(c[2]), "+f"(c[3])
        : "r"(a[0]), "r"(a[1]), "r"(a[2]), "r"(a[3]), "r"(b[0]), "r"(b[1]));
}

// ===================== scratch (device globals) =====================
__device__ float g_x[MTOT * DD];
__device__ float g_qkv[MTOT * 3 * DD];
__device__ float g_lr[MTOT];
__device__ float g_KK[NB * TT * TT];
__device__ float g_u[MTOT * DD];
// fp16 hi/lo pairs (g_El retained to keep static image identical to R7; unused)
__device__ __half g_Eh[VV * DD], g_El[VV * DD];
__device__ __half g_WgT[LL * 3 * DD * DD], g_WgTl[LL * 3 * DD * DD];
__device__ __half g_WoT[LL * DD * DD], g_WoTl[LL * DD * DD];
__device__ __half g_W1T[LL * DD * DD], g_W1Tl[LL * DD * DD];
__device__ __half g_W2T[LL * DD * DD], g_W2Tl[LL * DD * DD];
__device__ __half g_hh[MTOT * DD], g_hhl[MTOT * DD];
__device__ __half g_qh[MTOT * DD], g_qhl[MTOT * DD];
__device__ __half g_kh[MTOT * DD], g_khl[MTOT * DD];
__device__ __half g_ut[MTOT * DD], g_utl[MTOT * DD];
__device__ __half g_sh[NB * TT * TT], g_shl[NB * TT * TT];
__device__ __half g_yh[MTOT * DD], g_yhl[MTOT * DD];
__device__ __half g_ah[MTOT * DD], g_ahl[MTOT * DD];

// ===================== small kernels =====================
__device__ __forceinline__ float blockReduceSum(float v, float* sdata) {
    int tid = threadIdx.x;
    sdata[tid] = v;
    __syncthreads();
    for (int s = 128; s > 0; s >>= 1) {
        if (tid < s) sdata[tid] += sdata[tid + s];
        __syncthreads();
    }
    float r = sdata[0];
    __syncthreads();
    return r;
}

// write 4 floats as fp16 hi + fp16 lo (lo = residual)
__device__ __forceinline__ void store_h4_pair(__half* ph, __half* pl,
                                              float a, float b, float c, float d) {
    union { __half2 h2[2]; uint2 u; } hi, lo;
    hi.h2[0] = __floats2half2_rn(a, b);
    hi.h2[1] = __floats2half2_rn(c, d);
    lo.h2[0] = __floats2half2_rn(a - __half2float(hi.h2[0].x), b - __half2float(hi.h2[0].y));
    lo.h2[1] = __floats2half2_rn(c - __half2float(hi.h2[1].x), d - __half2float(hi.h2[1].y));
    *(uint2*)ph = hi.u;
    *(uint2*)pl = lo.u;
}

__global__ void embed_kernel(float* __restrict__ x, const float* __restrict__ E,
                             const int* __restrict__ ids) {
    int m = blockIdx.x;
    int id = ids[m];
    const float4* src = (const float4*)(E + (size_t)id * DD);
    float4* dst = (float4*)(x + (size_t)m * DD);
    dst[threadIdx.x] = src[threadIdx.x];
}

// LayerNorm -> fp16 hi/lo out; optionally fused lr = LN(x)@Wlr + blr
__global__ void ln_kernel(__half* __restrict__ oh, __half* __restrict__ ol,
                          const float* __restrict__ in,
                          const float* __restrict__ g, const float* __restrict__ b,
                          const float* __restrict__ Wlr, const float* __restrict__ blr,
                          float* __restrict__ lr) {
    __shared__ float sdata[256];
    int m = blockIdx.x, tid = threadIdx.x;
    const float* row = in + (size_t)m * DD;
    float4 v = *(const float4*)(row + tid * 4);
    float s = v.x + v.y + v.z + v.w;
    float mean = blockReduceSum(s, sdata) * (1.0f / DD);
    float dx = v.x - mean, dy = v.y - mean, dz = v.z - mean, dw = v.w - mean;
    float s2 = dx * dx + dy * dy + dz * dz + dw * dw;
    float var = blockReduceSum(s2, sdata) * (1.0f / DD);
    float rstd = 1.0f / sqrtf(var + 1e-5f);
    int c = tid * 4;
    float n0 = dx * rstd * g[c + 0] + b[c + 0];
    float n1 = dy * rstd * g[c + 1] + b[c + 1];
    float n2 = dz * rstd * g[c + 2] + b[c + 2];
    float n3 = dw * rstd * g[c + 3] + b[c + 3];
    store_h4_pair(oh + (size_t)m * DD + c, ol + (size_t)m * DD + c, n0, n1, n2, n3);
    if (Wlr) {
        float4 wv = *(const float4*)(Wlr + c);
        float d = n0 * wv.x + n1 * wv.y + n2 * wv.z + n3 * wv.w;
        float dot = blockReduceSum(d, sdata);
        if (tid == 0) lr[m] = dot + blr[0];
    }
}

// normalize k -> kh/kl; q -> qh/ql; copy v -> u (fp32)
__global__ void knorm_kernel(const float* __restrict__ qkv,
                             __half* __restrict__ qh, __half* __restrict__ ql,
                             __half* __restrict__ kh, __half* __restrict__ kl,
                             float* __restrict__ u) {
    __shared__ float sdata[256];
    int m = blockIdx.x, tid = threadIdx.x;
    const float* base = qkv + (size_t)m * (3 * DD);
    int c = tid * 4;
    float4 kv = *(const float4*)(base + DD + c);
    float ss = kv.x * kv.x + kv.y * kv.y + kv.z * kv.z + kv.w * kv.w;
    float ksum = blockReduceSum(ss, sdata);
    float scale = 1.0f / sqrtf(ksum);
    size_t o = (size_t)m * DD + c;
    store_h4_pair(kh + o, kl + o, kv.x * scale, kv.y * scale, kv.z * scale, kv.w * scale);
    float4 qv = *(const float4*)(base + c);
    store_h4_pair(qh + o, ql + o, qv.x, qv.y, qv.z, qv.w);
    *(float4*)(u + o) = *(const float4*)(base + 2 * DD + c);
}

// transpose + lr-scale + fp16 hi/lo: u [T,D] fp32 -> ut [D,T] (batched via z)
__global__ void tscale_kernel(const float* __restrict__ u, const float* __restrict__ lr,
                              __half* __restrict__ ut, __half* __restrict__ utl) {
    __shared__ float tile[32][33];
    long long z = blockIdx.z;
    u += z * (long long)TT * DD;
    ut += z * (long long)TT * DD;
    utl += z * (long long)TT * DD;
    lr += z * TT;
    int r0 = blockIdx.y * 32, c0 = blockIdx.x * 32;
    int tx = threadIdx.x, ty = threadIdx.y;  // 32 x 8
#pragma unroll
    for (int i = 0; i < 32; i += 8)
        tile[ty + i][tx] = u[(size_t)(r0 + ty + i) * DD + c0 + tx] * lr[r0 + ty + i];
    __syncthreads();
#pragma unroll
    for (int i = 0; i < 32; i += 8) {
        int c = c0 + ty + i, r = r0 + tx;
        float v = tile[tx][ty + i];
        __half hv = __float2half_rn(v);
        ut[(size_t)c * TT + r] = hv;
        utl[(size_t)c * TT + r] = __float2half_rn(v - __half2float(hv));
    }
}

// fp32 -> fp16 elementwise (for E, hi only — logits GEMM is single-pass)
__global__ void conv_kernel(const float* __restrict__ in, __half* __restrict__ out, long long n) {
    long long i = ((long long)blockIdx.x * blockDim.x + threadIdx.x) * 4;
    if (i >= n) return;
    float4 v = *(const float4*)(in + i);
    union { __half2 h2[2]; uint2 u; } pk;
    pk.h2[0] = __floats2half2_rn(v.x, v.y);
    pk.h2[1] = __floats2half2_rn(v.z, v.w);
    *(uint2*)(out + i) = pk.u;
}

// transpose + fp16 hi/lo: in [R,C] fp32 -> out [C,R] (batched via z)
__global__ void tsplit_kernel(const float* __restrict__ in, __half* __restrict__ oh,
                              __half* __restrict__ ol, int R, int C,
                              long long sIn, long long sOut) {
    __shared__ float tile[32][33];
    long long z = blockIdx.z;
    in += z * sIn; oh += z * sOut; ol += z * sOut;
    int r0 = blockIdx.y * 32, c0 = blockIdx.x * 32;
    int tx = threadIdx.x, ty = threadIdx.y;
#pragma unroll
    for (int i = 0; i < 32; i += 8)
        tile[ty + i][tx] = in[(size_t)(r0 + ty + i) * C + c0 + tx];
    __syncthreads();
#pragma unroll
    for (int i = 0; i < 32; i += 8) {
        int c = c0 + ty + i, r = r0 + tx;
        float v = tile[tx][ty + i];
        __half hv = __float2half_rn(v);
        oh[(size_t)c * R + r] = hv;
        ol[(size_t)c * R + r] = __float2half_rn(v - __half2float(hv));
    }
}

// ============ mma.sync fp16(x2-split) NT GEMM ============
// C = A@B^T; split mode: A=(Ah+Al), B=(Bh+Bl), 3 MMAs (drop Al*Bl); else single MMA on hi.
// A: [M,K] K-contiguous; B: [N,K] K-contiguous.
// CTA 128x128, BK=32, 256 thr = 8 warps (4m x 2n), warp tile 32x64.
// smem/stage: 4 tiles x 128 rows x 80B = 40960B; 3 stages = 122880B (opt-in).
// flags: 1=relu 2=strict-lower-mask 4=bias 8=resid 16=split
#define TILE_B 10240
#define STAGE_B 40960
#define TG_DYN_SMEM 122880

__global__ void __launch_bounds__(256, 1)
hgemm_kernel(const __half* __restrict__ Ah, const __half* __restrict__ Al,
             const __half* __restrict__ Bh, const __half* __restrict__ Bl,
             const float* __restrict__ bias, const float* __restrict__ resid,
             float* __restrict__ C, __half* __restrict__ Ch, __half* __restrict__ Chl,
             int K, int lda, int ldb, int ldc,
             long long sA, long long sB, long long sC, int flags) {
    long long z = blockIdx.z;
    Ah += z * sA; Bh += z * sB;
    Al += z * sA; Bl += z * sB;   // always valid pointers (hi aliased when !split)
    if (C) C += z * sC;
    if (Ch) Ch += z * sC;
    if (Chl) Chl += z * sC;
    if (resid) resid += z * sC;
    int m0 = blockIdx.x * 128, n0 = blockIdx.y * 128;
    if ((flags & 2) && n0 >= m0 + 128) return;  // fully above strict-lower diagonal
    const bool split = (flags & 16) != 0;

    extern __shared__ char dynsmem[];
    uint32_t sb = smem_to_u32(dynsmem);
    int tid = threadIdx.x, lane = tid & 31, wid = tid >> 5;
    int wm = wid >> 1, wn = wid & 1;  // warp grid 4(m) x 2(n)

    // loader: thread t: row (t&127) of pair (t>>7): 0 -> A(hi,lo), 1 -> B(hi,lo). 64B/row/tile.
    int ldrow = tid & 127, ldpair = tid >> 7;
    const __half* ph = (ldpair ? Bh : Ah) + (size_t)((ldpair ? n0 : m0) + ldrow) * (ldpair ? ldb : lda);
    const __half* pl = (ldpair ? Bl : Al) + (size_t)((ldpair ? n0 : m0) + ldrow) * (ldpair ? ldb : lda);
    uint32_t dsth = sb + ldpair * 2 * TILE_B + ldrow * 80;
    uint32_t dstl = dsth + TILE_B;

    const int nch = K >> 5;  // BK = 32

#define ISSUE_STAGE(cc) do {                                                  \
        uint32_t _so = ((cc) % 3) * STAGE_B;                                  \
        const __half* _q = ph + ((size_t)(cc) << 5);                          \
        CP_ASYNC16(dsth + _so, _q);           CP_ASYNC16(dsth + _so + 16, _q + 8);  \
        CP_ASYNC16(dsth + _so + 32, _q + 16); CP_ASYNC16(dsth + _so + 48, _q + 24); \
        if (split) {                                                          \
            const __half* _ql = pl + ((size_t)(cc) << 5);                     \
            CP_ASYNC16(dstl + _so, _ql);           CP_ASYNC16(dstl + _so + 16, _ql + 8);  \
            CP_ASYNC16(dstl + _so + 32, _ql + 16); CP_ASYNC16(dstl + _so + 48, _ql + 24); \
        }                                                                     \
        CP_ASYNC_COMMIT();                                                    \
    } while (0)

    ISSUE_STAGE(0);
    ISSUE_STAGE(1);

    float acc[2][8][4];
#pragma unroll
    for (int i = 0; i < 2; ++i)
#pragma unroll
        for (int j = 0; j < 8; ++j)
#pragma unroll
            for (int r = 0; r < 4; ++r) acc[i][j][r] = 0.0f;

    // ldmatrix per-lane offsets (row stride 80B; k16-halves at +0/+16; 2nd k16 block at +32)
    uint32_t a_off = (lane & 15) * 80 + (lane >> 4) * 16;
    uint32_t b_off = ((lane & 7) + ((lane >> 4) & 1) * 8) * 80 + ((lane >> 3) & 1) * 16;

    for (int c = 0; c < nch; ++c) {
        if (c + 2 < nch) {
            ISSUE_STAGE(c + 2);
            CP_ASYNC_WAIT(2);
        } else if (c + 1 < nch) {
            CP_ASYNC_WAIT(1);
        } else {
            CP_ASYNC_WAIT(0);
        }
        __syncthreads();

        uint32_t st = sb + (c % 3) * STAGE_B;
        uint32_t aBase = st + (wm * 32) * 80 + a_off;
        uint32_t alBase = aBase + TILE_B;
        uint32_t bBase = st + 2 * TILE_B + (wn * 64) * 80 + b_off;
        uint32_t blBase = bBase + TILE_B;

#pragma unroll
        for (int kk = 0; kk < 2; ++kk) {  // two k16 steps in BK=32
            uint32_t kof = kk * 32;
            uint32_t af[2][4], alf[2][4];
#pragma unroll
            for (int i = 0; i < 2; ++i) {
                ldmx4(af[i], aBase + i * 1280 + kof);   // 16 rows * 80B
                if (split) ldmx4(alf[i], alBase + i * 1280 + kof);
            }
            uint32_t bf[8][2], blf[8][2];
#pragma unroll
            for (int jj = 0; jj < 4; ++jj) {
                uint32_t r[4];
                ldmx4(r, bBase + jj * 1280 + kof);
                bf[2 * jj][0] = r[0]; bf[2 * jj][1] = r[1];
                bf[2 * jj + 1][0] = r[2]; bf[2 * jj + 1][1] = r[3];
                if (split) {
                    ldmx4(r, blBase + jj * 1280 + kof);
                    blf[2 * jj][0] = r[0]; blf[2 * jj][1] = r[1];
                    blf[2 * jj + 1][0] = r[2]; blf[2 * jj + 1][1] = r[3];
                }
            }
#pragma unroll
            for (int i = 0; i < 2; ++i)
#pragma unroll
                for (int j = 0; j < 8; ++j) {
                    mma16816(acc[i][j], af[i], bf[j]);
                    if (split) {
                        mma16816(acc[i][j], af[i], blf[j]);
                        mma16816(acc[i][j], alf[i], bf[j]);
                    }
                }
        }
        __syncthreads();
    }

    // epilogue
    int rbase = m0 + wm * 32 + (lane >> 2);
    int cbase = n0 + wn * 64 + (lane & 3) * 2;
#pragma unroll
    for (int i = 0; i < 2; ++i) {
        int r = rbase + i * 16;
#pragma unroll
        for (int j = 0; j < 8; ++j) {
            int cc = cbase + j * 8;
            float2 lo = make_float2(acc[i][j][0], acc[i][j][1]);
            float2 hi = make_float2(acc[i][j][2], acc[i][j][3]);
            if (flags & 4) {
                float2 bv = *(const float2*)(bias + cc);
                lo.x += bv.x; lo.y += bv.y; hi.x += bv.x; hi.y += bv.y;
            }
            if (flags & 8) {
                float2 r0 = *(const float2*)(resid + (long long)r * ldc + cc);
                float2 r1 = *(const float2*)(resid + (long long)(r + 8) * ldc + cc);
                lo.x += r0.x; lo.y += r0.y; hi.x += r1.x; hi.y += r1.y;
            }
            if (flags & 1) {
                lo.x = fmaxf(lo.x, 0.f); lo.y = fmaxf(lo.y, 0.f);
                hi.x = fmaxf(hi.x, 0.f); hi.y = fmaxf(hi.y, 0.f);
            }
            if (flags & 2) {
                if (cc + 0 >= r) lo.x = 0.f;
                if (cc + 1 >= r) lo.y = 0.f;
                if (cc + 0 >= r + 8) hi.x = 0.f;
                if (cc + 1 >= r + 8) hi.y = 0.f;
            }
            if (Ch) {
                __half2 hlo = __floats2half2_rn(lo.x, lo.y);
                __half2 hhi = __floats2half2_rn(hi.x, hi.y);
                *(__half2*)(Ch + (long long)r * ldc + cc) = hlo;
                *(__half2*)(Ch + (long long)(r + 8) * ldc + cc) = hhi;
                if (Chl) {
                    *(__half2*)(Chl + (long long)r * ldc + cc) =
                        __floats2half2_rn(lo.x - __half2float(hlo.x), lo.y - __half2float(hlo.y));
                    *(__half2*)(Chl + (long long)(r + 8) * ldc + cc) =
                        __floats2half2_rn(hi.x - __half2float(hhi.x), hi.y - __half2float(hhi.y));
                }
            } else {
                *(float2*)(C + (long long)r * ldc + cc) = lo;
                *(float2*)(C + (long long)(r + 8) * ldc + cc) = hi;
            }
        }
    }
#undef ISSUE_STAGE
}

// ===================== in-chunk forward substitution =====================
__global__ void chunksolve_kernel(float* __restrict__ u, const float* __restrict__ KK, int ci) {
    __shared__ float Ks[64][64];
    int batch = blockIdx.y;
    int d = blockIdx.x * 256 + threadIdx.x;
    const float* KKb = KK + (size_t)batch * TT * TT;
    float* ub = u + (size_t)batch * TT * DD;
    int base = ci * 64;
    for (int i = threadIdx.x; i < 64 * 64; i += 256) {
        int r = i >> 6, c = i & 63;
        Ks[r][c] = KKb[(size_t)(base + r) * TT + base + c];
    }
    __syncthreads();
    float uloc[64];
#pragma unroll
    for (int r = 0; r < 64; ++r) {
        float val = ub[(size_t)(base + r) * DD + d];
#pragma unroll
        for (int s = 0; s < r; ++s) val -= Ks[r][s] * uloc[s];
        uloc[r] = val;
        ub[(size_t)(base + r) * DD + d] = val;
    }
}

// ===================== SIMT SGEMM (solve rank-64 updates): C -= A@B =====================
__global__ void sgemm_upd_kernel(const float* __restrict__ A, const float* __restrict__ B,
                                 float* __restrict__ C, int M, int N, int K,
                                 int lda, int ldb, int ldc,
                                 long long sA, long long sB, long long sC) {
    long long z = blockIdx.z;
    A += z * sA; B += z * sB; C += z * sC;
    int m0 = blockIdx.y * 128, n0 = blockIdx.x * 128;
    __shared__ float As[8][128];
    __shared__ float Bs[8][128];
    int tid = threadIdx.x;
    int tx = tid & 15, ty = tid >> 4;
    int ar = tid >> 1, ac = (tid & 1) * 4;
    int br = tid >> 5, bc = (tid & 31) * 4;
    float acc[8][8];
#pragma unroll
    for (int i = 0; i < 8; ++i)
#pragma unroll
        for (int j = 0; j < 8; ++j) acc[i][j] = 0.0f;
    for (int k0 = 0; k0 < K; k0 += 8) {
        float4 av = make_float4(0.f, 0.f, 0.f, 0.f);
        if (m0 + ar < M) av = *(const float4*)(A + (long long)(m0 + ar) * lda + k0 + ac);
        As[ac + 0][ar] = av.x; As[ac + 1][ar] = av.y;
        As[ac + 2][ar] = av.z; As[ac + 3][ar] = av.w;
        float4 bv = *(const float4*)(B + (long long)(k0 + br) * ldb + n0 + bc);
        *(float4*)&Bs[br][bc] = bv;
        __syncthreads();
#pragma unroll
        for (int k = 0; k < 8; ++k) {
            float ra[8], rb[8];
            *(float4*)&ra[0] = *(float4*)&As[k][ty * 8];
            *(float4*)&ra[4] = *(float4*)&As[k][ty * 8 + 4];
            *(float4*)&rb[0] = *(float4*)&Bs[k][tx * 8];
            *(float4*)&rb[4] = *(float4*)&Bs[k][tx * 8 + 4];
#pragma unroll
            for (int i = 0; i < 8; ++i)
#pragma unroll
                for (int j = 0; j < 8; ++j) acc[i][j] += ra[i] * rb[j];
        }
        __syncthreads();
    }
#pragma unroll
    for (int i = 0; i < 8; ++i) {
        int r = m0 + ty * 8 + i;
        if (r >= M) continue;
#pragma unroll
        for (int j = 0; j < 8; ++j) {
            int c = n0 + tx * 8 + j;
            C[(long long)r * ldc + c] -= acc[i][j];
        }
    }
}

// ===================== host launcher =====================
static void launch_hgemm(int flags, const __half* Ah, const __half* Al,
                         const __half* Bh, const __half* Bl,
                         const float* bias, const float* resid,
                         float* C, __half* Ch, __half* Chl,
                         int M, int N, int K, int lda, int ldb, int ldc,
                         long long sA, long long sB, long long sC, int batch) {
    dim3 grid(M / 128, N / 128, batch);  // x = M tiles (L2 reuse of A)
    hgemm_kernel<<<grid, 256, TG_DYN_SMEM>>>(Ah, Al, Bh, Bl, bias, resid, C, Ch, Chl,
                                             K, lda, ldb, ldc, sA, sB, sC, flags);
}

extern "C" void kernel_launch(void* const* d_in, const int* in_sizes, int n_in,
                              void* d_out, int out_size) {
    const int* ids = (const int*)d_in[0];
    const float* E = (const float*)d_in[1];
    const float* Wg = (const float*)d_in[2];
    const float* bg = (const float*)d_in[3];
    const float* Wlr = (const float*)d_in[4];
    const float* blr = (const float*)d_in[5];
    const float* Wo = (const float*)d_in[6];
    const float* bo = (const float*)d_in[7];
    const float* g_d = (const float*)d_in[8];
    const float* b_d = (const float*)d_in[9];
    const float* W1 = (const float*)d_in[10];
    const float* b1 = (const float*)d_in[11];
    const float* W2 = (const float*)d_in[12];
    const float* b2 = (const float*)d_in[13];
    const float* g_m = (const float*)d_in[14];
    const float* b_m = (const float*)d_in[15];
    const float* g_o = (const float*)d_in[16];
    const float* b_o = (const float*)d_in[17];
    float* out = (float*)d_out;

    cudaFuncSetAttribute(hgemm_kernel, cudaFuncAttributeMaxDynamicSharedMemorySize, TG_DYN_SMEM);

    float *x, *qkv, *lr, *KK, *u;
    cudaGetSymbolAddress((void**)&x, g_x);
    cudaGetSymbolAddress((void**)&qkv, g_qkv);
    cudaGetSymbolAddress((void**)&lr, g_lr);
    cudaGetSymbolAddress((void**)&KK, g_KK);
    cudaGetSymbolAddress((void**)&u, g_u);
    __half *Eh, *WgT, *WgTl, *WoT, *WoTl, *W1T, *W1Tl, *W2T, *W2Tl;
    __half *hh, *hhl, *qh, *qhl, *kh, *khl, *ut, *utl, *sh, *shl, *yh, *yhl, *ah, *ahl;
    cudaGetSymbolAddress((void**)&Eh, g_Eh);
    cudaGetSymbolAddress((void**)&WgT, g_WgT); cudaGetSymbolAddress((void**)&WgTl, g_WgTl);
    cudaGetSymbolAddress((void**)&WoT, g_WoT); cudaGetSymbolAddress((void**)&WoTl, g_WoTl);
    cudaGetSymbolAddress((void**)&W1T, g_W1T); cudaGetSymbolAddress((void**)&W1Tl, g_W1Tl);
    cudaGetSymbolAddress((void**)&W2T, g_W2T); cudaGetSymbolAddress((void**)&W2Tl, g_W2Tl);
    cudaGetSymbolAddress((void**)&hh, g_hh);   cudaGetSymbolAddress((void**)&hhl, g_hhl);
    cudaGetSymbolAddress((void**)&qh, g_qh);   cudaGetSymbolAddress((void**)&qhl, g_qhl);
    cudaGetSymbolAddress((void**)&kh, g_kh);   cudaGetSymbolAddress((void**)&khl, g_khl);
    cudaGetSymbolAddress((void**)&ut, g_ut);   cudaGetSymbolAddress((void**)&utl, g_utl);
    cudaGetSymbolAddress((void**)&sh, g_sh);   cudaGetSymbolAddress((void**)&shl, g_shl);
    cudaGetSymbolAddress((void**)&yh, g_yh);   cudaGetSymbolAddress((void**)&yhl, g_yhl);
    cudaGetSymbolAddress((void**)&ah, g_ah);   cudaGetSymbolAddress((void**)&ahl, g_ahl);

    const long long sTT = (long long)TT * TT;
    const long long sTD = (long long)TT * DD;
    const int SPLIT = 16;

    // ---- prepass: convert E (hi only); transpose+split weights ----
    {
        long long nE = (long long)VV * DD;
        conv_kernel<<<(int)((nE / 4 + 255) / 256), 256>>>(E, Eh, nE);
        dim3 tb(32, 8);
        tsplit_kernel<<<dim3(3 * DD / 32, DD / 32, LL), tb>>>(Wg, WgT, WgTl, DD, 3 * DD,
                                                              (long long)DD * 3 * DD, (long long)DD * 3 * DD);
        tsplit_kernel<<<dim3(DD / 32, DD / 32, LL), tb>>>(Wo, WoT, WoTl, DD, DD,
                                                          (long long)DD * DD, (long long)DD * DD);
        tsplit_kernel<<<dim3(DD / 32, DD / 32, LL), tb>>>(W1, W1T, W1Tl, DD, DD,
                                                          (long long)DD * DD, (long long)DD * DD);
        tsplit_kernel<<<dim3(DD / 32, DD / 32, LL), tb>>>(W2, W2T, W2Tl, DD, DD,
                                                          (long long)DD * DD, (long long)DD * DD);
    }

    embed_kernel<<<MTOT, 256>>>(x, E, ids);

    for (int l = 0; l < LL; ++l) {
        const __half* WgT_l = WgT + (size_t)l * 3 * DD * DD;
        const __half* WgTl_l = WgTl + (size_t)l * 3 * DD * DD;
        const __half* WoT_l = WoT + (size_t)l * DD * DD;
        const __half* WoTl_l = WoTl + (size_t)l * DD * DD;
        const __half* W1T_l = W1T + (size_t)l * DD * DD;
        const __half* W1Tl_l = W1Tl + (size_t)l * DD * DD;
        const __half* W2T_l = W2T + (size_t)l * DD * DD;
        const __half* W2Tl_l = W2Tl + (size_t)l * DD * DD;

        // --- delta block ---
        ln_kernel<<<MTOT, 256>>>(hh, hhl, x, g_d + (size_t)l * DD, b_d + (size_t)l * DD,
                                 Wlr + (size_t)l * DD, blr + l, lr);
        // qkv = hh @ WgT^T + bg (fp32 out)
        launch_hgemm(SPLIT | 4, hh, hhl, WgT_l, WgTl_l, bg + (size_t)l * 3 * DD, nullptr,
                     qkv, nullptr, nullptr, MTOT, 3 * DD, DD, DD, DD, 3 * DD, 0, 0, 0, 1);
        knorm_kernel<<<MTOT, 256>>>(qkv, qh, qhl, kh, khl, u);
        // KK = stril(k k^T, -1), fp32
        launch_hgemm(SPLIT | 2, kh, khl, kh, khl, nullptr, nullptr,
                     KK, nullptr, nullptr, TT, TT, DD, DD, DD, TT, sTD, sTD, sTT, NB);
        // solve (I + KK) u = v  (fp32 SIMT chain)
        for (int ci = 0; ci < 16; ++ci) {
            chunksolve_kernel<<<dim3(DD / 256, NB), 256>>>(u, KK, ci);
            if (ci < 15) {
                int r0 = 64 * (ci + 1);
                int Mu = TT - r0;
                sgemm_upd_kernel<<<dim3(DD / 128, (Mu + 127) / 128, NB), 256>>>(
                    KK + (size_t)r0 * TT + ci * 64, u + (size_t)ci * 64 * DD,
                    u + (size_t)r0 * DD, Mu, DD, 64, TT, DD, DD, sTT, sTD, sTD);
            }
        }
        // ut = split fp16((lr*u)^T) [D,T]
        {
            dim3 tb(32, 8);
            tscale_kernel<<<dim3(DD / 32, TT / 32, NB), tb>>>(u, lr, ut, utl);
        }
        // sh = split fp16(q @ k^T) (full scores)
        launch_hgemm(SPLIT, qh, qhl, kh, khl, nullptr, nullptr,
                     nullptr, sh, shl, TT, TT, DD, DD, DD, TT, sTD, sTD, sTT, NB);
        // yh = split fp16(sh @ ut^T)
        launch_hgemm(SPLIT, sh, shl, ut, utl, nullptr, nullptr,
                     nullptr, yh, yhl, TT, DD, TT, TT, TT, DD, sTT, sTD, sTD, NB);
        // x = x + yh @ WoT^T + bo (fp32)
        launch_hgemm(SPLIT | 4 | 8, yh, yhl, WoT_l, WoTl_l, bo + (size_t)l * DD, x,
                     x, nullptr, nullptr, MTOT, DD, DD, DD, DD, DD, 0, 0, 0, 1);

        // --- MLP block ---
        ln_kernel<<<MTOT, 256>>>(hh, hhl, x, g_m + (size_t)l * DD, b_m + (size_t)l * DD,
                                 nullptr, nullptr, nullptr);
        launch_hgemm(SPLIT | 4 | 1, hh, hhl, W1T_l, W1Tl_l, b1 + (size_t)l * DD, nullptr,
                     nullptr, ah, ahl, MTOT, DD, DD, DD, DD, DD, 0, 0, 0, 1);
        launch_hgemm(SPLIT | 4 | 8, ah, ahl, W2T_l, W2Tl_l, b2 + (size_t)l * DD, x,
                     x, nullptr, nullptr, MTOT, DD, DD, DD, DD, DD, 0, 0, 0, 1);
    }

    // final LN + tied decoder: out = LN(x) @ E^T — SINGLE-PASS fp16 (error lands once, ~3e-4)
    // hi pointers passed for lo operands too (never read: !split); avoids null ptr arithmetic.
    ln_kernel<<<MTOT, 256>>>(hh, hhl, x, g_o, b_o, nullptr, nullptr, nullptr);
    launch_hgemm(0, hh, hh, Eh, Eh, nullptr, nullptr,
                 out, nullptr, nullptr, MTOT, VV, DD, DD, DD, VV, 0, 0, 0, 1);
}

// round 10
// speedup vs baseline: 1.9817x; 1.0685x over previous
#include <cuda_runtime.h>
#include <cuda_fp16.h>
#include <cstdint>

// Problem constants
#define NB 4          // batch
#define TT 1024       // seq len
#define DD 1024       // dim
#define LL 4          // layers
#define VV 32000      // vocab
#define MTOT (NB*TT)  // 4096 rows

// ===================== PTX helpers (base ISA only) =====================
__device__ __forceinline__ uint32_t smem_to_u32(const void* p) {
    uint32_t a;
    asm("{ .reg .u64 t; cvta.to.shared.u64 t, %1; cvt.u32.u64 %0, t; }" : "=r"(a) : "l"(p));
    return a;
}
#define CP_ASYNC16(dst, src) \
    asm volatile("cp.async.cg.shared.global [%0], [%1], 16;" :: "r"((uint32_t)(dst)), "l"(src))
#define CP_ASYNC_COMMIT() asm volatile("cp.async.commit_group;" ::: "memory")
#define CP_ASYNC_WAIT(n) asm volatile("cp.async.wait_group %0;" :: "n"(n) : "memory")

__device__ __forceinline__ void ldmx4(uint32_t* r, uint32_t addr) {
    asm volatile("ldmatrix.sync.aligned.m8n8.x4.shared.b16 {%0,%1,%2,%3}, [%4];"
                 : "=r"(r[0]), "=r"(r[1]), "=r"(r[2]), "=r"(r[3]) : "r"(addr));
}
__device__ __forceinline__ void mma16816(float* c, const uint32_t* a, const uint32_t* b) {
    asm volatile(
        "mma.sync.aligned.m16n8k16.row.col.f32.f16.f16.f32 "
        "{%0,%1,%2,%3}, {%4,%5,%6,%7}, {%8,%9}, {%0,%1,%2,%3};"
        : "+f"(c[0]), "+f"(c[1]), "+f"(c[2]), "+f"(c[3])
        : "r"(a[0]), "r"(a[1]), "r"(a[2]), "r"(a[3]), "r"(b[0]), "r"(b[1]));
}

// ===================== scratch (device globals) =====================
__device__ float g_x[MTOT * DD];
__device__ float g_qkv[MTOT * 3 * DD];
__device__ float g_lr[MTOT];
__device__ float g_KK[NB * TT * TT];
__device__ float g_u[MTOT * DD];
__device__ __half g_Eh[VV * DD], g_El[VV * DD];  // g_El unused (kept for image parity)
__device__ __half g_WgT[LL * 3 * DD * DD], g_WgTl[LL * 3 * DD * DD];
__device__ __half g_WoT[LL * DD * DD], g_WoTl[LL * DD * DD];
__device__ __half g_W1T[LL * DD * DD], g_W1Tl[LL * DD * DD];
__device__ __half g_W2T[LL * DD * DD], g_W2Tl[LL * DD * DD];
__device__ __half g_hh[MTOT * DD], g_hhl[MTOT * DD];
__device__ __half g_qh[MTOT * DD], g_qhl[MTOT * DD];
__device__ __half g_kh[MTOT * DD], g_khl[MTOT * DD];
__device__ __half g_ut[MTOT * DD], g_utl[MTOT * DD];
__device__ __half g_sh[NB * TT * TT], g_shl[NB * TT * TT];
__device__ __half g_yh[MTOT * DD], g_yhl[MTOT * DD];
__device__ __half g_ah[MTOT * DD], g_ahl[MTOT * DD];

// ===================== small kernels =====================
__device__ __forceinline__ float blockReduceSum(float v, float* sdata) {
    int tid = threadIdx.x;
    sdata[tid] = v;
    __syncthreads();
    for (int s = 128; s > 0; s >>= 1) {
        if (tid < s) sdata[tid] += sdata[tid + s];
        __syncthreads();
    }
    float r = sdata[0];
    __syncthreads();
    return r;
}

__device__ __forceinline__ void store_h4_pair(__half* ph, __half* pl,
                                              float a, float b, float c, float d) {
    union { __half2 h2[2]; uint2 u; } hi, lo;
    hi.h2[0] = __floats2half2_rn(a, b);
    hi.h2[1] = __floats2half2_rn(c, d);
    lo.h2[0] = __floats2half2_rn(a - __half2float(hi.h2[0].x), b - __half2float(hi.h2[0].y));
    lo.h2[1] = __floats2half2_rn(c - __half2float(hi.h2[1].x), d - __half2float(hi.h2[1].y));
    *(uint2*)ph = hi.u;
    *(uint2*)pl = lo.u;
}

__global__ void embed_kernel(float* __restrict__ x, const float* __restrict__ E,
                             const int* __restrict__ ids) {
    int m = blockIdx.x;
    int id = ids[m];
    const float4* src = (const float4*)(E + (size_t)id * DD);
    float4* dst = (float4*)(x + (size_t)m * DD);
    dst[threadIdx.x] = src[threadIdx.x];
}

__global__ void ln_kernel(__half* __restrict__ oh, __half* __restrict__ ol,
                          const float* __restrict__ in,
                          const float* __restrict__ g, const float* __restrict__ b,
                          const float* __restrict__ Wlr, const float* __restrict__ blr,
                          float* __restrict__ lr) {
    __shared__ float sdata[256];
    int m = blockIdx.x, tid = threadIdx.x;
    const float* row = in + (size_t)m * DD;
    float4 v = *(const float4*)(row + tid * 4);
    float s = v.x + v.y + v.z + v.w;
    float mean = blockReduceSum(s, sdata) * (1.0f / DD);
    float dx = v.x - mean, dy = v.y - mean, dz = v.z - mean, dw = v.w - mean;
    float s2 = dx * dx + dy * dy + dz * dz + dw * dw;
    float var = blockReduceSum(s2, sdata) * (1.0f / DD);
    float rstd = 1.0f / sqrtf(var + 1e-5f);
    int c = tid * 4;
    float n0 = dx * rstd * g[c + 0] + b[c + 0];
    float n1 = dy * rstd * g[c + 1] + b[c + 1];
    float n2 = dz * rstd * g[c + 2] + b[c + 2];
    float n3 = dw * rstd * g[c + 3] + b[c + 3];
    store_h4_pair(oh + (size_t)m * DD + c, ol + (size_t)m * DD + c, n0, n1, n2, n3);
    if (Wlr) {
        float4 wv = *(const float4*)(Wlr + c);
        float d = n0 * wv.x + n1 * wv.y + n2 * wv.z + n3 * wv.w;
        float dot = blockReduceSum(d, sdata);
        if (tid == 0) lr[m] = dot + blr[0];
    }
}

__global__ void knorm_kernel(const float* __restrict__ qkv,
                             __half* __restrict__ qh, __half* __restrict__ ql,
                             __half* __restrict__ kh, __half* __restrict__ kl,
                             float* __restrict__ u) {
    __shared__ float sdata[256];
    int m = blockIdx.x, tid = threadIdx.x;
    const float* base = qkv + (size_t)m * (3 * DD);
    int c = tid * 4;
    float4 kv = *(const float4*)(base + DD + c);
    float ss = kv.x * kv.x + kv.y * kv.y + kv.z * kv.z + kv.w * kv.w;
    float ksum = blockReduceSum(ss, sdata);
    float scale = 1.0f / sqrtf(ksum);
    size_t o = (size_t)m * DD + c;
    store_h4_pair(kh + o, kl + o, kv.x * scale, kv.y * scale, kv.z * scale, kv.w * scale);
    float4 qv = *(const float4*)(base + c);
    store_h4_pair(qh + o, ql + o, qv.x, qv.y, qv.z, qv.w);
    *(float4*)(u + o) = *(const float4*)(base + 2 * DD + c);
}

// transpose + lr-scale + fp16 hi/lo: u [T,D] fp32 -> ut [D,T] (batched via z)
__global__ void tscale_kernel(const float* __restrict__ u, const float* __restrict__ lr,
                              __half* __restrict__ ut, __half* __restrict__ utl) {
    __shared__ float tile[32][33];
    long long z = blockIdx.z;
    u += z * (long long)TT * DD;
    ut += z * (long long)TT * DD;
    utl += z * (long long)TT * DD;
    lr += z * TT;
    int r0 = blockIdx.y * 32, c0 = blockIdx.x * 32;
    int tx = threadIdx.x, ty = threadIdx.y;  // 32 x 8
#pragma unroll
    for (int i = 0; i < 32; i += 8)
        tile[ty + i][tx] = u[(size_t)(r0 + ty + i) * DD + c0 + tx] * lr[r0 + ty + i];
    __syncthreads();
#pragma unroll
    for (int i = 0; i < 32; i += 8) {
        int c = c0 + ty + i, r = r0 + tx;
        float v = tile[tx][ty + i];
        __half hv = __float2half_rn(v);
        ut[(size_t)c * TT + r] = hv;
        utl[(size_t)c * TT + r] = __float2half_rn(v - __half2float(hv));
    }
}

// fp32 -> fp16 elementwise (for E hi)
__global__ void conv_kernel(const float* __restrict__ in, __half* __restrict__ out, long long n) {
    long long i = ((long long)blockIdx.x * blockDim.x + threadIdx.x) * 4;
    if (i >= n) return;
    float4 v = *(const float4*)(in + i);
    union { __half2 h2[2]; uint2 u; } pk;
    pk.h2[0] = __floats2half2_rn(v.x, v.y);
    pk.h2[1] = __floats2half2_rn(v.z, v.w);
    *(uint2*)(out + i) = pk.u;
}

// transpose + fp16 hi/lo: in [R,C] fp32 -> out [C,R] (batched via z)
__global__ void tsplit_kernel(const float* __restrict__ in, __half* __restrict__ oh,
                              __half* __restrict__ ol, int R, int C,
                              long long sIn, long long sOut) {
    __shared__ float tile[32][33];
    long long z = blockIdx.z;
    in += z * sIn; oh += z * sOut; ol += z * sOut;
    int r0 = blockIdx.y * 32, c0 = blockIdx.x * 32;
    int tx = threadIdx.x, ty = threadIdx.y;
#pragma unroll
    for (int i = 0; i < 32; i += 8)
        tile[ty + i][tx] = in[(size_t)(r0 + ty + i) * C + c0 + tx];
    __syncthreads();
#pragma unroll
    for (int i = 0; i < 32; i += 8) {
        int c = c0 + ty + i, r = r0 + tx;
        float v = tile[tx][ty + i];
        __half hv = __float2half_rn(v);
        oh[(size_t)c * R + r] = hv;
        ol[(size_t)c * R + r] = __float2half_rn(v - __half2float(hv));
    }
}

// ============ mma.sync fp16(x2-split) NT GEMM, 2-stage, 2 CTAs/SM ============
// C = A@B^T; split: 3 MMAs (Ah*Bh + Ah*Bl + Al*Bh); else single MMA on hi.
// CTA 128x128, BK=32, 256 thr = 8 warps (4m x 2n), warp tile 32x64.
// smem/stage: 4 tiles x 128 rows x 80B = 40960B; 2 stages = 81920B (opt-in; 2 CTAs/SM).
// flags: 1=relu 2=strict-lower-mask 4=bias 8=resid 16=split
#define TILE_B 10240
#define STAGE_B 40960
#define TG_DYN_SMEM 81920

__global__ void __launch_bounds__(256, 2)
hgemm_kernel(const __half* __restrict__ Ah, const __half* __restrict__ Al,
             const __half* __restrict__ Bh, const __half* __restrict__ Bl,
             const float* __restrict__ bias, const float* __restrict__ resid,
             float* __restrict__ C, __half* __restrict__ Ch, __half* __restrict__ Chl,
             int K, int lda, int ldb, int ldc,
             long long sA, long long sB, long long sC, int flags) {
    long long z = blockIdx.z;
    Ah += z * sA; Bh += z * sB;
    Al += z * sA; Bl += z * sB;   // always valid (hi aliased when !split)
    if (C) C += z * sC;
    if (Ch) Ch += z * sC;
    if (Chl) Chl += z * sC;
    if (resid) resid += z * sC;
    int m0 = blockIdx.x * 128, n0 = blockIdx.y * 128;
    if ((flags & 2) && n0 >= m0 + 128) return;
    const bool split = (flags & 16) != 0;

    extern __shared__ char dynsmem[];
    uint32_t sb = smem_to_u32(dynsmem);
    int tid = threadIdx.x, lane = tid & 31, wid = tid >> 5;
    int wm = wid >> 1, wn = wid & 1;

    int ldrow = tid & 127, ldpair = tid >> 7;
    const __half* ph = (ldpair ? Bh : Ah) + (size_t)((ldpair ? n0 : m0) + ldrow) * (ldpair ? ldb : lda);
    const __half* pl = (ldpair ? Bl : Al) + (size_t)((ldpair ? n0 : m0) + ldrow) * (ldpair ? ldb : lda);
    uint32_t dsth = sb + ldpair * 2 * TILE_B + ldrow * 80;
    uint32_t dstl = dsth + TILE_B;

    const int nch = K >> 5;  // BK = 32

#define ISSUE_STAGE(cc) do {                                                  \
        uint32_t _so = ((cc) & 1) * STAGE_B;                                  \
        const __half* _q = ph + ((size_t)(cc) << 5);                          \
        CP_ASYNC16(dsth + _so, _q);           CP_ASYNC16(dsth + _so + 16, _q + 8);  \
        CP_ASYNC16(dsth + _so + 32, _q + 16); CP_ASYNC16(dsth + _so + 48, _q + 24); \
        if (split) {                                                          \
            const __half* _ql = pl + ((size_t)(cc) << 5);                     \
            CP_ASYNC16(dstl + _so, _ql);           CP_ASYNC16(dstl + _so + 16, _ql + 8);  \
            CP_ASYNC16(dstl + _so + 32, _ql + 16); CP_ASYNC16(dstl + _so + 48, _ql + 24); \
        }                                                                     \
        CP_ASYNC_COMMIT();                                                    \
    } while (0)

    ISSUE_STAGE(0);

    float acc[2][8][4];
#pragma unroll
    for (int i = 0; i < 2; ++i)
#pragma unroll
        for (int j = 0; j < 8; ++j)
#pragma unroll
            for (int r = 0; r < 4; ++r) acc[i][j][r] = 0.0f;

    uint32_t a_off = (lane & 15) * 80 + (lane >> 4) * 16;
    uint32_t b_off = ((lane & 7) + ((lane >> 4) & 1) * 8) * 80 + ((lane >> 3) & 1) * 16;

    for (int c = 0; c < nch; ++c) {
        if (c + 1 < nch) {
            ISSUE_STAGE(c + 1);
            CP_ASYNC_WAIT(1);
        } else {
            CP_ASYNC_WAIT(0);
        }
        __syncthreads();

        uint32_t st = sb + (c & 1) * STAGE_B;
        uint32_t aBase = st + (wm * 32) * 80 + a_off;
        uint32_t alBase = aBase + TILE_B;
        uint32_t bBase = st + 2 * TILE_B + (wn * 64) * 80 + b_off;
        uint32_t blBase = bBase + TILE_B;

#pragma unroll
        for (int kk = 0; kk < 2; ++kk) {
            uint32_t kof = kk * 32;
            uint32_t af[2][4], alf[2][4];
#pragma unroll
            for (int i = 0; i < 2; ++i) {
                ldmx4(af[i], aBase + i * 1280 + kof);
                if (split) ldmx4(alf[i], alBase + i * 1280 + kof);
            }
            // process B fragments pairwise to cap register residency (2 CTAs/SM => 128 regs)
#pragma unroll
            for (int jj = 0; jj < 4; ++jj) {
                uint32_t rb[4], rbl[4];
                ldmx4(rb, bBase + jj * 1280 + kof);
                if (split) ldmx4(rbl, blBase + jj * 1280 + kof);
#pragma unroll
                for (int h = 0; h < 2; ++h) {
                    int j = 2 * jj + h;
                    uint32_t bf[2] = {rb[2 * h], rb[2 * h + 1]};
#pragma unroll
                    for (int i = 0; i < 2; ++i) mma16816(acc[i][j], af[i], bf);
                    if (split) {
                        uint32_t blf[2] = {rbl[2 * h], rbl[2 * h + 1]};
#pragma unroll
                        for (int i = 0; i < 2; ++i) {
                            mma16816(acc[i][j], af[i], blf);
                            mma16816(acc[i][j], alf[i], bf);
                        }
                    }
                }
            }
        }
        __syncthreads();
    }

    // epilogue
    int rbase = m0 + wm * 32 + (lane >> 2);
    int cbase = n0 + wn * 64 + (lane & 3) * 2;
#pragma unroll
    for (int i = 0; i < 2; ++i) {
        int r = rbase + i * 16;
#pragma unroll
        for (int j = 0; j < 8; ++j) {
            int cc = cbase + j * 8;
            float2 lo = make_float2(acc[i][j][0], acc[i][j][1]);
            float2 hi = make_float2(acc[i][j][2], acc[i][j][3]);
            if (flags & 4) {
                float2 bv = *(const float2*)(bias + cc);
                lo.x += bv.x; lo.y += bv.y; hi.x += bv.x; hi.y += bv.y;
            }
            if (flags & 8) {
                float2 r0 = *(const float2*)(resid + (long long)r * ldc + cc);
                float2 r1 = *(const float2*)(resid + (long long)(r + 8) * ldc + cc);
                lo.x += r0.x; lo.y += r0.y; hi.x += r1.x; hi.y += r1.y;
            }
            if (flags & 1) {
                lo.x = fmaxf(lo.x, 0.f); lo.y = fmaxf(lo.y, 0.f);
                hi.x = fmaxf(hi.x, 0.f); hi.y = fmaxf(hi.y, 0.f);
            }
            if (flags & 2) {
                if (cc + 0 >= r) lo.x = 0.f;
                if (cc + 1 >= r) lo.y = 0.f;
                if (cc + 0 >= r + 8) hi.x = 0.f;
                if (cc + 1 >= r + 8) hi.y = 0.f;
            }
            if (Ch) {
                __half2 hlo = __floats2half2_rn(lo.x, lo.y);
                __half2 hhi = __floats2half2_rn(hi.x, hi.y);
                *(__half2*)(Ch + (long long)r * ldc + cc) = hlo;
                *(__half2*)(Ch + (long long)(r + 8) * ldc + cc) = hhi;
                if (Chl) {
                    *(__half2*)(Chl + (long long)r * ldc + cc) =
                        __floats2half2_rn(lo.x - __half2float(hlo.x), lo.y - __half2float(hlo.y));
                    *(__half2*)(Chl + (long long)(r + 8) * ldc + cc) =
                        __floats2half2_rn(hi.x - __half2float(hhi.x), hi.y - __half2float(hhi.y));
                }
            } else {
                *(float2*)(C + (long long)r * ldc + cc) = lo;
                *(float2*)(C + (long long)(r + 8) * ldc + cc) = hi;
            }
        }
    }
#undef ISSUE_STAGE
}

// ===================== fused 128-row panel forward substitution =====================
// Solves rows [128*ci, 128*ci+128) of (I + stril(KK)) u = u, assuming all prior
// chunk contributions already applied. Phased to keep only one 64-float uloc live.
__global__ void chunksolve2_kernel(float* __restrict__ u, const float* __restrict__ KK, int ci) {
    __shared__ float Ks[64][64];   // diag block, rows base..base+63
    __shared__ float Ks2[64][64];  // off-diag, rows base+64.. x cols base..
    __shared__ float Ksn[64][64];  // diag block, rows base+64..
    int batch = blockIdx.y;
    int d = blockIdx.x * 256 + threadIdx.x;
    const float* KKb = KK + (size_t)batch * TT * TT;
    float* ub = u + (size_t)batch * TT * DD;
    int base = ci * 128;
    for (int i = threadIdx.x; i < 64 * 64; i += 256) {
        int r = i >> 6, c = i & 63;
        Ks[r][c]  = KKb[(size_t)(base + r) * TT + base + c];
        Ks2[r][c] = KKb[(size_t)(base + 64 + r) * TT + base + c];
        Ksn[r][c] = KKb[(size_t)(base + 64 + r) * TT + base + 64 + c];
    }
    __syncthreads();
    float uloc[64];
    // phase 1: solve first 64 rows
#pragma unroll
    for (int r = 0; r < 64; ++r) {
        float val = ub[(size_t)(base + r) * DD + d];
#pragma unroll
        for (int s = 0; s < r; ++s) val -= Ks[r][s] * uloc[s];
        uloc[r] = val;
        ub[(size_t)(base + r) * DD + d] = val;
    }
    // phase 2: apply rank-64 off-diag update to next 64 rows (gmem round-trip keeps regs low)
#pragma unroll 4
    for (int r = 0; r < 64; ++r) {
        float val = ub[(size_t)(base + 64 + r) * DD + d];
#pragma unroll
        for (int s = 0; s < 64; ++s) val -= Ks2[r][s] * uloc[s];
        ub[(size_t)(base + 64 + r) * DD + d] = val;
    }
    // phase 3: solve second 64 rows (uloc reused; phase-1 values dead)
#pragma unroll
    for (int r = 0; r < 64; ++r) {
        float val = ub[(size_t)(base + 64 + r) * DD + d];
#pragma unroll
        for (int s = 0; s < r; ++s) val -= Ksn[r][s] * uloc[s];
        uloc[r] = val;
        ub[(size_t)(base + 64 + r) * DD + d] = val;
    }
}

// ===================== SIMT SGEMM (solve trailing updates): C -= A@B =====================
__global__ void sgemm_upd_kernel(const float* __restrict__ A, const float* __restrict__ B,
                                 float* __restrict__ C, int M, int N, int K,
                                 int lda, int ldb, int ldc,
                                 long long sA, long long sB, long long sC) {
    long long z = blockIdx.z;
    A += z * sA; B += z * sB; C += z * sC;
    int m0 = blockIdx.y * 128, n0 = blockIdx.x * 128;
    __shared__ float As[8][128];
    __shared__ float Bs[8][128];
    int tid = threadIdx.x;
    int tx = tid & 15, ty = tid >> 4;
    int ar = tid >> 1, ac = (tid & 1) * 4;
    int br = tid >> 5, bc = (tid & 31) * 4;
    float acc[8][8];
#pragma unroll
    for (int i = 0; i < 8; ++i)
#pragma unroll
        for (int j = 0; j < 8; ++j) acc[i][j] = 0.0f;
    for (int k0 = 0; k0 < K; k0 += 8) {
        float4 av = make_float4(0.f, 0.f, 0.f, 0.f);
        if (m0 + ar < M) av = *(const float4*)(A + (long long)(m0 + ar) * lda + k0 + ac);
        As[ac + 0][ar] = av.x; As[ac + 1][ar] = av.y;
        As[ac + 2][ar] = av.z; As[ac + 3][ar] = av.w;
        float4 bv = *(const float4*)(B + (long long)(k0 + br) * ldb + n0 + bc);
        *(float4*)&Bs[br][bc] = bv;
        __syncthreads();
#pragma unroll
        for (int k = 0; k < 8; ++k) {
            float ra[8], rb[8];
            *(float4*)&ra[0] = *(float4*)&As[k][ty * 8];
            *(float4*)&ra[4] = *(float4*)&As[k][ty * 8 + 4];
            *(float4*)&rb[0] = *(float4*)&Bs[k][tx * 8];
            *(float4*)&rb[4] = *(float4*)&Bs[k][tx * 8 + 4];
#pragma unroll
            for (int i = 0; i < 8; ++i)
#pragma unroll
                for (int j = 0; j < 8; ++j) acc[i][j] += ra[i] * rb[j];
        }
        __syncthreads();
    }
#pragma unroll
    for (int i = 0; i < 8; ++i) {
        int r = m0 + ty * 8 + i;
        if (r >= M) continue;
#pragma unroll
        for (int j = 0; j < 8; ++j) {
            int c = n0 + tx * 8 + j;
            C[(long long)r * ldc + c] -= acc[i][j];
        }
    }
}

// ===================== host launcher =====================
static void launch_hgemm(int flags, const __half* Ah, const __half* Al,
                         const __half* Bh, const __half* Bl,
                         const float* bias, const float* resid,
                         float* C, __half* Ch, __half* Chl,
                         int M, int N, int K, int lda, int ldb, int ldc,
                         long long sA, long long sB, long long sC, int batch) {
    dim3 grid(M / 128, N / 128, batch);  // x = M tiles (L2 reuse of A)
    hgemm_kernel<<<grid, 256, TG_DYN_SMEM>>>(Ah, Al, Bh, Bl, bias, resid, C, Ch, Chl,
                                             K, lda, ldb, ldc, sA, sB, sC, flags);
}

extern "C" void kernel_launch(void* const* d_in, const int* in_sizes, int n_in,
                              void* d_out, int out_size) {
    const int* ids = (const int*)d_in[0];
    const float* E = (const float*)d_in[1];
    const float* Wg = (const float*)d_in[2];
    const float* bg = (const float*)d_in[3];
    const float* Wlr = (const float*)d_in[4];
    const float* blr = (const float*)d_in[5];
    const float* Wo = (const float*)d_in[6];
    const float* bo = (const float*)d_in[7];
    const float* g_d = (const float*)d_in[8];
    const float* b_d = (const float*)d_in[9];
    const float* W1 = (const float*)d_in[10];
    const float* b1 = (const float*)d_in[11];
    const float* W2 = (const float*)d_in[12];
    const float* b2 = (const float*)d_in[13];
    const float* g_m = (const float*)d_in[14];
    const float* b_m = (const float*)d_in[15];
    const float* g_o = (const float*)d_in[16];
    const float* b_o = (const float*)d_in[17];
    float* out = (float*)d_out;

    cudaFuncSetAttribute(hgemm_kernel, cudaFuncAttributeMaxDynamicSharedMemorySize, TG_DYN_SMEM);

    float *x, *qkv, *lr, *KK, *u;
    cudaGetSymbolAddress((void**)&x, g_x);
    cudaGetSymbolAddress((void**)&qkv, g_qkv);
    cudaGetSymbolAddress((void**)&lr, g_lr);
    cudaGetSymbolAddress((void**)&KK, g_KK);
    cudaGetSymbolAddress((void**)&u, g_u);
    __half *Eh, *WgT, *WgTl, *WoT, *WoTl, *W1T, *W1Tl, *W2T, *W2Tl;
    __half *hh, *hhl, *qh, *qhl, *kh, *khl, *ut, *utl, *sh, *shl, *yh, *yhl, *ah, *ahl;
    cudaGetSymbolAddress((void**)&Eh, g_Eh);
    cudaGetSymbolAddress((void**)&WgT, g_WgT); cudaGetSymbolAddress((void**)&WgTl, g_WgTl);
    cudaGetSymbolAddress((void**)&WoT, g_WoT); cudaGetSymbolAddress((void**)&WoTl, g_WoTl);
    cudaGetSymbolAddress((void**)&W1T, g_W1T); cudaGetSymbolAddress((void**)&W1Tl, g_W1Tl);
    cudaGetSymbolAddress((void**)&W2T, g_W2T); cudaGetSymbolAddress((void**)&W2Tl, g_W2Tl);
    cudaGetSymbolAddress((void**)&hh, g_hh);   cudaGetSymbolAddress((void**)&hhl, g_hhl);
    cudaGetSymbolAddress((void**)&qh, g_qh);   cudaGetSymbolAddress((void**)&qhl, g_qhl);
    cudaGetSymbolAddress((void**)&kh, g_kh);   cudaGetSymbolAddress((void**)&khl, g_khl);
    cudaGetSymbolAddress((void**)&ut, g_ut);   cudaGetSymbolAddress((void**)&utl, g_utl);
    cudaGetSymbolAddress((void**)&sh, g_sh);   cudaGetSymbolAddress((void**)&shl, g_shl);
    cudaGetSymbolAddress((void**)&yh, g_yh);   cudaGetSymbolAddress((void**)&yhl, g_yhl);
    cudaGetSymbolAddress((void**)&ah, g_ah);   cudaGetSymbolAddress((void**)&ahl, g_ahl);

    const long long sTT = (long long)TT * TT;
    const long long sTD = (long long)TT * DD;
    const int SPLIT = 16;

    // ---- prepass: convert E (hi only); transpose+split weights ----
    {
        long long nE = (long long)VV * DD;
        conv_kernel<<<(int)((nE / 4 + 255) / 256), 256>>>(E, Eh, nE);
        dim3 tb(32, 8);
        tsplit_kernel<<<dim3(3 * DD / 32, DD / 32, LL), tb>>>(Wg, WgT, WgTl, DD, 3 * DD,
                                                              (long long)DD * 3 * DD, (long long)DD * 3 * DD);
        tsplit_kernel<<<dim3(DD / 32, DD / 32, LL), tb>>>(Wo, WoT, WoTl, DD, DD,
                                                          (long long)DD * DD, (long long)DD * DD);
        tsplit_kernel<<<dim3(DD / 32, DD / 32, LL), tb>>>(W1, W1T, W1Tl, DD, DD,
                                                          (long long)DD * DD, (long long)DD * DD);
        tsplit_kernel<<<dim3(DD / 32, DD / 32, LL), tb>>>(W2, W2T, W2Tl, DD, DD,
                                                          (long long)DD * DD, (long long)DD * DD);
    }

    embed_kernel<<<MTOT, 256>>>(x, E, ids);

    for (int l = 0; l < LL; ++l) {
        const __half* WgT_l = WgT + (size_t)l * 3 * DD * DD;
        const __half* WgTl_l = WgTl + (size_t)l * 3 * DD * DD;
        const __half* WoT_l = WoT + (size_t)l * DD * DD;
        const __half* WoTl_l = WoTl + (size_t)l * DD * DD;
        const __half* W1T_l = W1T + (size_t)l * DD * DD;
        const __half* W1Tl_l = W1Tl + (size_t)l * DD * DD;
        const __half* W2T_l = W2T + (size_t)l * DD * DD;
        const __half* W2Tl_l = W2Tl + (size_t)l * DD * DD;

        // --- delta block ---
        ln_kernel<<<MTOT, 256>>>(hh, hhl, x, g_d + (size_t)l * DD, b_d + (size_t)l * DD,
                                 Wlr + (size_t)l * DD, blr + l, lr);
        launch_hgemm(SPLIT | 4, hh, hhl, WgT_l, WgTl_l, bg + (size_t)l * 3 * DD, nullptr,
                     qkv, nullptr, nullptr, MTOT, 3 * DD, DD, DD, DD, 3 * DD, 0, 0, 0, 1);
        knorm_kernel<<<MTOT, 256>>>(qkv, qh, qhl, kh, khl, u);
        launch_hgemm(SPLIT | 2, kh, khl, kh, khl, nullptr, nullptr,
                     KK, nullptr, nullptr, TT, TT, DD, DD, DD, TT, sTD, sTD, sTT, NB);
        // solve (I + KK) u = v: 8 fused 128-row panels + 7 trailing rank-128 updates
        for (int ci = 0; ci < 8; ++ci) {
            chunksolve2_kernel<<<dim3(DD / 256, NB), 256>>>(u, KK, ci);
            if (ci < 7) {
                int r0 = 128 * (ci + 1);
                int Mu = TT - r0;
                sgemm_upd_kernel<<<dim3(DD / 128, (Mu + 127) / 128, NB), 256>>>(
                    KK + (size_t)r0 * TT + ci * 128, u + (size_t)ci * 128 * DD,
                    u + (size_t)r0 * DD, Mu, DD, 128, TT, DD, DD, sTT, sTD, sTD);
            }
        }
        {
            dim3 tb(32, 8);
            tscale_kernel<<<dim3(DD / 32, TT / 32, NB), tb>>>(u, lr, ut, utl);
        }
        launch_hgemm(SPLIT, qh, qhl, kh, khl, nullptr, nullptr,
                     nullptr, sh, shl, TT, TT, DD, DD, DD, TT, sTD, sTD, sTT, NB);
        launch_hgemm(SPLIT, sh, shl, ut, utl, nullptr, nullptr,
                     nullptr, yh, yhl, TT, DD, TT, TT, TT, DD, sTT, sTD, sTD, NB);
        launch_hgemm(SPLIT | 4 | 8, yh, yhl, WoT_l, WoTl_l, bo + (size_t)l * DD, x,
                     x, nullptr, nullptr, MTOT, DD, DD, DD, DD, DD, 0, 0, 0, 1);

        // --- MLP block ---
        ln_kernel<<<MTOT, 256>>>(hh, hhl, x, g_m + (size_t)l * DD, b_m + (size_t)l * DD,
                                 nullptr, nullptr, nullptr);
        launch_hgemm(SPLIT | 4 | 1, hh, hhl, W1T_l, W1Tl_l, b1 + (size_t)l * DD, nullptr,
                     nullptr, ah, ahl, MTOT, DD, DD, DD, DD, DD, 0, 0, 0, 1);
        launch_hgemm(SPLIT | 4 | 8, ah, ahl, W2T_l, W2Tl_l, b2 + (size_t)l * DD, x,
                     x, nullptr, nullptr, MTOT, DD, DD, DD, DD, DD, 0, 0, 0, 1);
    }

    // final LN + tied decoder: single-pass fp16 logits (error lands once, ~3e-4)
    ln_kernel<<<MTOT, 256>>>(hh, hhl, x, g_o, b_o, nullptr, nullptr, nullptr);
    launch_hgemm(0, hh, hh, Eh, Eh, nullptr, nullptr,
                 out, nullptr, nullptr, MTOT, VV, DD, DD, DD, VV, 0, 0, 0, 1);
}

// round 11
// speedup vs baseline: 2.0697x; 1.0444x over previous
#include <cuda_runtime.h>
#include <cuda_fp16.h>
#include <cstdint>

// Problem constants
#define NB 4          // batch
#define TT 1024       // seq len
#define DD 1024       // dim
#define LL 4          // layers
#define VV 32000      // vocab
#define MTOT (NB*TT)  // 4096 rows

// ===================== PTX helpers (base ISA only) =====================
__device__ __forceinline__ uint32_t smem_to_u32(const void* p) {
    uint32_t a;
    asm("{ .reg .u64 t; cvta.to.shared.u64 t, %1; cvt.u32.u64 %0, t; }" : "=r"(a) : "l"(p));
    return a;
}
#define CP_ASYNC16(dst, src) \
    asm volatile("cp.async.cg.shared.global [%0], [%1], 16;" :: "r"((uint32_t)(dst)), "l"(src))
#define CP_ASYNC_COMMIT() asm volatile("cp.async.commit_group;" ::: "memory")
#define CP_ASYNC_WAIT(n) asm volatile("cp.async.wait_group %0;" :: "n"(n) : "memory")

__device__ __forceinline__ void ldmx4(uint32_t* r, uint32_t addr) {
    asm volatile("ldmatrix.sync.aligned.m8n8.x4.shared.b16 {%0,%1,%2,%3}, [%4];"
                 : "=r"(r[0]), "=r"(r[1]), "=r"(r[2]), "=r"(r[3]) : "r"(addr));
}
__device__ __forceinline__ void mma16816(float* c, const uint32_t* a, const uint32_t* b) {
    asm volatile(
        "mma.sync.aligned.m16n8k16.row.col.f32.f16.f16.f32 "
        "{%0,%1,%2,%3}, {%4,%5,%6,%7}, {%8,%9}, {%0,%1,%2,%3};"
        : "+f"(c[0]), "+f"(c[1]), "+f"(c[2]), "+f"(c[3])
        : "r"(a[0]), "r"(a[1]), "r"(a[2]), "r"(a[3]), "r"(b[0]), "r"(b[1]));
}

// ===================== scratch (device globals) =====================
__device__ float g_x[MTOT * DD];
__device__ float g_qkv[MTOT * 3 * DD];
__device__ float g_lr[MTOT];
__device__ float g_KK[NB * TT * TT];
__device__ float g_u[MTOT * DD];
__device__ __half g_Eh[VV * DD], g_El[VV * DD];  // g_El unused (image parity)
__device__ __half g_WgT[LL * 3 * DD * DD], g_WgTl[LL * 3 * DD * DD];
__device__ __half g_WoT[LL * DD * DD], g_WoTl[LL * DD * DD];
__device__ __half g_W1T[LL * DD * DD], g_W1Tl[LL * DD * DD];
__device__ __half g_W2T[LL * DD * DD], g_W2Tl[LL * DD * DD];
__device__ __half g_hh[MTOT * DD], g_hhl[MTOT * DD];
__device__ __half g_qh[MTOT * DD], g_qhl[MTOT * DD];
__device__ __half g_kh[MTOT * DD], g_khl[MTOT * DD];
__device__ __half g_ut[MTOT * DD], g_utl[MTOT * DD];
__device__ __half g_sh[NB * TT * TT], g_shl[NB * TT * TT];
__device__ __half g_yh[MTOT * DD], g_yhl[MTOT * DD];
__device__ __half g_ah[MTOT * DD], g_ahl[MTOT * DD];

// ===================== small kernels =====================
__device__ __forceinline__ float blockReduceSum(float v, float* sdata) {
    int tid = threadIdx.x;
    sdata[tid] = v;
    __syncthreads();
    for (int s = 128; s > 0; s >>= 1) {
        if (tid < s) sdata[tid] += sdata[tid + s];
        __syncthreads();
    }
    float r = sdata[0];
    __syncthreads();
    return r;
}

__device__ __forceinline__ void store_h4_pair(__half* ph, __half* pl,
                                              float a, float b, float c, float d) {
    union { __half2 h2[2]; uint2 u; } hi, lo;
    hi.h2[0] = __floats2half2_rn(a, b);
    hi.h2[1] = __floats2half2_rn(c, d);
    lo.h2[0] = __floats2half2_rn(a - __half2float(hi.h2[0].x), b - __half2float(hi.h2[0].y));
    lo.h2[1] = __floats2half2_rn(c - __half2float(hi.h2[1].x), d - __half2float(hi.h2[1].y));
    *(uint2*)ph = hi.u;
    *(uint2*)pl = lo.u;
}

__global__ void embed_kernel(float* __restrict__ x, const float* __restrict__ E,
                             const int* __restrict__ ids) {
    int m = blockIdx.x;
    int id = ids[m];
    const float4* src = (const float4*)(E + (size_t)id * DD);
    float4* dst = (float4*)(x + (size_t)m * DD);
    dst[threadIdx.x] = src[threadIdx.x];
}

__global__ void ln_kernel(__half* __restrict__ oh, __half* __restrict__ ol,
                          const float* __restrict__ in,
                          const float* __restrict__ g, const float* __restrict__ b,
                          const float* __restrict__ Wlr, const float* __restrict__ blr,
                          float* __restrict__ lr) {
    __shared__ float sdata[256];
    int m = blockIdx.x, tid = threadIdx.x;
    const float* row = in + (size_t)m * DD;
    float4 v = *(const float4*)(row + tid * 4);
    float s = v.x + v.y + v.z + v.w;
    float mean = blockReduceSum(s, sdata) * (1.0f / DD);
    float dx = v.x - mean, dy = v.y - mean, dz = v.z - mean, dw = v.w - mean;
    float s2 = dx * dx + dy * dy + dz * dz + dw * dw;
    float var = blockReduceSum(s2, sdata) * (1.0f / DD);
    float rstd = 1.0f / sqrtf(var + 1e-5f);
    int c = tid * 4;
    float n0 = dx * rstd * g[c + 0] + b[c + 0];
    float n1 = dy * rstd * g[c + 1] + b[c + 1];
    float n2 = dz * rstd * g[c + 2] + b[c + 2];
    float n3 = dw * rstd * g[c + 3] + b[c + 3];
    store_h4_pair(oh + (size_t)m * DD + c, ol + (size_t)m * DD + c, n0, n1, n2, n3);
    if (Wlr) {
        float4 wv = *(const float4*)(Wlr + c);
        float d = n0 * wv.x + n1 * wv.y + n2 * wv.z + n3 * wv.w;
        float dot = blockReduceSum(d, sdata);
        if (tid == 0) lr[m] = dot + blr[0];
    }
}

__global__ void knorm_kernel(const float* __restrict__ qkv,
                             __half* __restrict__ qh, __half* __restrict__ ql,
                             __half* __restrict__ kh, __half* __restrict__ kl,
                             float* __restrict__ u) {
    __shared__ float sdata[256];
    int m = blockIdx.x, tid = threadIdx.x;
    const float* base = qkv + (size_t)m * (3 * DD);
    int c = tid * 4;
    float4 kv = *(const float4*)(base + DD + c);
    float ss = kv.x * kv.x + kv.y * kv.y + kv.z * kv.z + kv.w * kv.w;
    float ksum = blockReduceSum(ss, sdata);
    float scale = 1.0f / sqrtf(ksum);
    size_t o = (size_t)m * DD + c;
    store_h4_pair(kh + o, kl + o, kv.x * scale, kv.y * scale, kv.z * scale, kv.w * scale);
    float4 qv = *(const float4*)(base + c);
    store_h4_pair(qh + o, ql + o, qv.x, qv.y, qv.z, qv.w);
    *(float4*)(u + o) = *(const float4*)(base + 2 * DD + c);
}

// transpose + lr-scale + fp16 hi/lo: u [T,D] fp32 -> ut [D,T] (batched via z)
__global__ void tscale_kernel(const float* __restrict__ u, const float* __restrict__ lr,
                              __half* __restrict__ ut, __half* __restrict__ utl) {
    __shared__ float tile[32][33];
    long long z = blockIdx.z;
    u += z * (long long)TT * DD;
    ut += z * (long long)TT * DD;
    utl += z * (long long)TT * DD;
    lr += z * TT;
    int r0 = blockIdx.y * 32, c0 = blockIdx.x * 32;
    int tx = threadIdx.x, ty = threadIdx.y;  // 32 x 8
#pragma unroll
    for (int i = 0; i < 32; i += 8)
        tile[ty + i][tx] = u[(size_t)(r0 + ty + i) * DD + c0 + tx] * lr[r0 + ty + i];
    __syncthreads();
#pragma unroll
    for (int i = 0; i < 32; i += 8) {
        int c = c0 + ty + i, r = r0 + tx;
        float v = tile[tx][ty + i];
        __half hv = __float2half_rn(v);
        ut[(size_t)c * TT + r] = hv;
        utl[(size_t)c * TT + r] = __float2half_rn(v - __half2float(hv));
    }
}

// fp32 -> fp16 elementwise (for E hi)
__global__ void conv_kernel(const float* __restrict__ in, __half* __restrict__ out, long long n) {
    long long i = ((long long)blockIdx.x * blockDim.x + threadIdx.x) * 4;
    if (i >= n) return;
    float4 v = *(const float4*)(in + i);
    union { __half2 h2[2]; uint2 u; } pk;
    pk.h2[0] = __floats2half2_rn(v.x, v.y);
    pk.h2[1] = __floats2half2_rn(v.z, v.w);
    *(uint2*)(out + i) = pk.u;
}

// transpose + fp16 hi/lo: in [R,C] fp32 -> out [C,R] (batched via z)
__global__ void tsplit_kernel(const float* __restrict__ in, __half* __restrict__ oh,
                              __half* __restrict__ ol, int R, int C,
                              long long sIn, long long sOut) {
    __shared__ float tile[32][33];
    long long z = blockIdx.z;
    in += z * sIn; oh += z * sOut; ol += z * sOut;
    int r0 = blockIdx.y * 32, c0 = blockIdx.x * 32;
    int tx = threadIdx.x, ty = threadIdx.y;
#pragma unroll
    for (int i = 0; i < 32; i += 8)
        tile[ty + i][tx] = in[(size_t)(r0 + ty + i) * C + c0 + tx];
    __syncthreads();
#pragma unroll
    for (int i = 0; i < 32; i += 8) {
        int c = c0 + ty + i, r = r0 + tx;
        float v = tile[tx][ty + i];
        __half hv = __float2half_rn(v);
        oh[(size_t)c * R + r] = hv;
        ol[(size_t)c * R + r] = __float2half_rn(v - __half2float(hv));
    }
}

// ============ mma.sync fp16(x2-split) NT GEMM, 2-stage, 2 CTAs/SM ============
// C = A@B^T; split: 3 MMAs (Ah*Bh + Ah*Bl + Al*Bh); else single MMA on hi.
// CTA 128x128, BK=32, 256 thr = 8 warps (4m x 2n), warp tile 32x64.
// smem/stage: 4 tiles x 128 rows x 80B = 40960B; 2 stages = 81920B (opt-in; 2 CTAs/SM).
// flags: 1=relu 2=strict-lower-mask 4=bias 8=resid 16=split
#define TILE_B 10240
#define STAGE_B 40960
#define TG_DYN_SMEM 81920

__global__ void __launch_bounds__(256, 2)
hgemm_kernel(const __half* __restrict__ Ah, const __half* __restrict__ Al,
             const __half* __restrict__ Bh, const __half* __restrict__ Bl,
             const float* __restrict__ bias, const float* __restrict__ resid,
             float* __restrict__ C, __half* __restrict__ Ch, __half* __restrict__ Chl,
             int K, int lda, int ldb, int ldc,
             long long sA, long long sB, long long sC, int flags) {
    long long z = blockIdx.z;
    Ah += z * sA; Bh += z * sB;
    Al += z * sA; Bl += z * sB;   // always valid (hi aliased when !split)
    if (C) C += z * sC;
    if (Ch) Ch += z * sC;
    if (Chl) Chl += z * sC;
    if (resid) resid += z * sC;
    int m0 = blockIdx.x * 128, n0 = blockIdx.y * 128;
    if ((flags & 2) && n0 >= m0 + 128) return;
    const bool split = (flags & 16) != 0;

    extern __shared__ char dynsmem[];
    uint32_t sb = smem_to_u32(dynsmem);
    int tid = threadIdx.x, lane = tid & 31, wid = tid >> 5;
    int wm = wid >> 1, wn = wid & 1;

    int ldrow = tid & 127, ldpair = tid >> 7;
    const __half* ph = (ldpair ? Bh : Ah) + (size_t)((ldpair ? n0 : m0) + ldrow) * (ldpair ? ldb : lda);
    const __half* pl = (ldpair ? Bl : Al) + (size_t)((ldpair ? n0 : m0) + ldrow) * (ldpair ? ldb : lda);
    uint32_t dsth = sb + ldpair * 2 * TILE_B + ldrow * 80;
    uint32_t dstl = dsth + TILE_B;

    const int nch = K >> 5;  // BK = 32

#define ISSUE_STAGE(cc) do {                                                  \
        uint32_t _so = ((cc) & 1) * STAGE_B;                                  \
        const __half* _q = ph + ((size_t)(cc) << 5);                          \
        CP_ASYNC16(dsth + _so, _q);           CP_ASYNC16(dsth + _so + 16, _q + 8);  \
        CP_ASYNC16(dsth + _so + 32, _q + 16); CP_ASYNC16(dsth + _so + 48, _q + 24); \
        if (split) {                                                          \
            const __half* _ql = pl + ((size_t)(cc) << 5);                     \
            CP_ASYNC16(dstl + _so, _ql);           CP_ASYNC16(dstl + _so + 16, _ql + 8);  \
            CP_ASYNC16(dstl + _so + 32, _ql + 16); CP_ASYNC16(dstl + _so + 48, _ql + 24); \
        }                                                                     \
        CP_ASYNC_COMMIT();                                                    \
    } while (0)

    ISSUE_STAGE(0);

    float acc[2][8][4];
#pragma unroll
    for (int i = 0; i < 2; ++i)
#pragma unroll
        for (int j = 0; j < 8; ++j)
#pragma unroll
            for (int r = 0; r < 4; ++r) acc[i][j][r] = 0.0f;

    uint32_t a_off = (lane & 15) * 80 + (lane >> 4) * 16;
    uint32_t b_off = ((lane & 7) + ((lane >> 4) & 1) * 8) * 80 + ((lane >> 3) & 1) * 16;

    for (int c = 0; c < nch; ++c) {
        if (c + 1 < nch) {
            ISSUE_STAGE(c + 1);
            CP_ASYNC_WAIT(1);
        } else {
            CP_ASYNC_WAIT(0);
        }
        __syncthreads();

        uint32_t st = sb + (c & 1) * STAGE_B;
        uint32_t aBase = st + (wm * 32) * 80 + a_off;
        uint32_t alBase = aBase + TILE_B;
        uint32_t bBase = st + 2 * TILE_B + (wn * 64) * 80 + b_off;
        uint32_t blBase = bBase + TILE_B;

#pragma unroll
        for (int kk = 0; kk < 2; ++kk) {
            uint32_t kof = kk * 32;
            uint32_t af[2][4], alf[2][4];
#pragma unroll
            for (int i = 0; i < 2; ++i) {
                ldmx4(af[i], aBase + i * 1280 + kof);
                if (split) ldmx4(alf[i], alBase + i * 1280 + kof);
            }
#pragma unroll
            for (int jj = 0; jj < 4; ++jj) {
                uint32_t rb[4], rbl[4];
                ldmx4(rb, bBase + jj * 1280 + kof);
                if (split) ldmx4(rbl, blBase + jj * 1280 + kof);
#pragma unroll
                for (int h = 0; h < 2; ++h) {
                    int j = 2 * jj + h;
                    uint32_t bf[2] = {rb[2 * h], rb[2 * h + 1]};
#pragma unroll
                    for (int i = 0; i < 2; ++i) mma16816(acc[i][j], af[i], bf);
                    if (split) {
                        uint32_t blf[2] = {rbl[2 * h], rbl[2 * h + 1]};
#pragma unroll
                        for (int i = 0; i < 2; ++i) {
                            mma16816(acc[i][j], af[i], blf);
                            mma16816(acc[i][j], alf[i], bf);
                        }
                    }
                }
            }
        }
        __syncthreads();
    }

    // epilogue
    int rbase = m0 + wm * 32 + (lane >> 2);
    int cbase = n0 + wn * 64 + (lane & 3) * 2;
#pragma unroll
    for (int i = 0; i < 2; ++i) {
        int r = rbase + i * 16;
#pragma unroll
        for (int j = 0; j < 8; ++j) {
            int cc = cbase + j * 8;
            float2 lo = make_float2(acc[i][j][0], acc[i][j][1]);
            float2 hi = make_float2(acc[i][j][2], acc[i][j][3]);
            if (flags & 4) {
                float2 bv = *(const float2*)(bias + cc);
                lo.x += bv.x; lo.y += bv.y; hi.x += bv.x; hi.y += bv.y;
            }
            if (flags & 8) {
                float2 r0 = *(const float2*)(resid + (long long)r * ldc + cc);
                float2 r1 = *(const float2*)(resid + (long long)(r + 8) * ldc + cc);
                lo.x += r0.x; lo.y += r0.y; hi.x += r1.x; hi.y += r1.y;
            }
            if (flags & 1) {
                lo.x = fmaxf(lo.x, 0.f); lo.y = fmaxf(lo.y, 0.f);
                hi.x = fmaxf(hi.x, 0.f); hi.y = fmaxf(hi.y, 0.f);
            }
            if (flags & 2) {
                if (cc + 0 >= r) lo.x = 0.f;
                if (cc + 1 >= r) lo.y = 0.f;
                if (cc + 0 >= r + 8) hi.x = 0.f;
                if (cc + 1 >= r + 8) hi.y = 0.f;
            }
            if (Ch) {
                __half2 hlo = __floats2half2_rn(lo.x, lo.y);
                __half2 hhi = __floats2half2_rn(hi.x, hi.y);
                *(__half2*)(Ch + (long long)r * ldc + cc) = hlo;
                *(__half2*)(Ch + (long long)(r + 8) * ldc + cc) = hhi;
                if (Chl) {
                    *(__half2*)(Chl + (long long)r * ldc + cc) =
                        __floats2half2_rn(lo.x - __half2float(hlo.x), lo.y - __half2float(hlo.y));
                    *(__half2*)(Chl + (long long)(r + 8) * ldc + cc) =
                        __floats2half2_rn(hi.x - __half2float(hhi.x), hi.y - __half2float(hhi.y));
                }
            } else {
                *(float2*)(C + (long long)r * ldc + cc) = lo;
                *(float2*)(C + (long long)(r + 8) * ldc + cc) = hi;
            }
        }
    }
#undef ISSUE_STAGE
}

// ===================== fused 128-row panel forward substitution =====================
__global__ void chunksolve2_kernel(float* __restrict__ u, const float* __restrict__ KK, int ci) {
    __shared__ float Ks[64][64];
    __shared__ float Ks2[64][64];
    __shared__ float Ksn[64][64];
    int batch = blockIdx.y;
    int d = blockIdx.x * 256 + threadIdx.x;
    const float* KKb = KK + (size_t)batch * TT * TT;
    float* ub = u + (size_t)batch * TT * DD;
    int base = ci * 128;
    for (int i = threadIdx.x; i < 64 * 64; i += 256) {
        int r = i >> 6, c = i & 63;
        Ks[r][c]  = KKb[(size_t)(base + r) * TT + base + c];
        Ks2[r][c] = KKb[(size_t)(base + 64 + r) * TT + base + c];
        Ksn[r][c] = KKb[(size_t)(base + 64 + r) * TT + base + 64 + c];
    }
    __syncthreads();
    float uloc[64];
#pragma unroll
    for (int r = 0; r < 64; ++r) {
        float val = ub[(size_t)(base + r) * DD + d];
#pragma unroll
        for (int s = 0; s < r; ++s) val -= Ks[r][s] * uloc[s];
        uloc[r] = val;
        ub[(size_t)(base + r) * DD + d] = val;
    }
#pragma unroll 4
    for (int r = 0; r < 64; ++r) {
        float val = ub[(size_t)(base + 64 + r) * DD + d];
#pragma unroll
        for (int s = 0; s < 64; ++s) val -= Ks2[r][s] * uloc[s];
        ub[(size_t)(base + 64 + r) * DD + d] = val;
    }
#pragma unroll
    for (int r = 0; r < 64; ++r) {
        float val = ub[(size_t)(base + 64 + r) * DD + d];
#pragma unroll
        for (int s = 0; s < r; ++s) val -= Ksn[r][s] * uloc[s];
        uloc[r] = val;
        ub[(size_t)(base + 64 + r) * DD + d] = val;
    }
}

// ===================== SIMT SGEMM (solve trailing updates): C -= A@B =====================
__global__ void sgemm_upd_kernel(const float* __restrict__ A, const float* __restrict__ B,
                                 float* __restrict__ C, int M, int N, int K,
                                 int lda, int ldb, int ldc,
                                 long long sA, long long sB, long long sC) {
    long long z = blockIdx.z;
    A += z * sA; B += z * sB; C += z * sC;
    int m0 = blockIdx.y * 128, n0 = blockIdx.x * 128;
    __shared__ float As[8][128];
    __shared__ float Bs[8][128];
    int tid = threadIdx.x;
    int tx = tid & 15, ty = tid >> 4;
    int ar = tid >> 1, ac = (tid & 1) * 4;
    int br = tid >> 5, bc = (tid & 31) * 4;
    float acc[8][8];
#pragma unroll
    for (int i = 0; i < 8; ++i)
#pragma unroll
        for (int j = 0; j < 8; ++j) acc[i][j] = 0.0f;
    for (int k0 = 0; k0 < K; k0 += 8) {
        float4 av = make_float4(0.f, 0.f, 0.f, 0.f);
        if (m0 + ar < M) av = *(const float4*)(A + (long long)(m0 + ar) * lda + k0 + ac);
        As[ac + 0][ar] = av.x; As[ac + 1][ar] = av.y;
        As[ac + 2][ar] = av.z; As[ac + 3][ar] = av.w;
        float4 bv = *(const float4*)(B + (long long)(k0 + br) * ldb + n0 + bc);
        *(float4*)&Bs[br][bc] = bv;
        __syncthreads();
#pragma unroll
        for (int k = 0; k < 8; ++k) {
            float ra[8], rb[8];
            *(float4*)&ra[0] = *(float4*)&As[k][ty * 8];
            *(float4*)&ra[4] = *(float4*)&As[k][ty * 8 + 4];
            *(float4*)&rb[0] = *(float4*)&Bs[k][tx * 8];
            *(float4*)&rb[4] = *(float4*)&Bs[k][tx * 8 + 4];
#pragma unroll
            for (int i = 0; i < 8; ++i)
#pragma unroll
                for (int j = 0; j < 8; ++j) acc[i][j] += ra[i] * rb[j];
        }
        __syncthreads();
    }
#pragma unroll
    for (int i = 0; i < 8; ++i) {
        int r = m0 + ty * 8 + i;
        if (r >= M) continue;
#pragma unroll
        for (int j = 0; j < 8; ++j) {
            int c = n0 + tx * 8 + j;
            C[(long long)r * ldc + c] -= acc[i][j];
        }
    }
}

// ===================== host launcher =====================
static void launch_hgemm(int flags, const __half* Ah, const __half* Al,
                         const __half* Bh, const __half* Bl,
                         const float* bias, const float* resid,
                         float* C, __half* Ch, __half* Chl,
                         int M, int N, int K, int lda, int ldb, int ldc,
                         long long sA, long long sB, long long sC, int batch) {
    dim3 grid(M / 128, N / 128, batch);  // x = M tiles (L2 reuse of A)
    hgemm_kernel<<<grid, 256, TG_DYN_SMEM>>>(Ah, Al, Bh, Bl, bias, resid, C, Ch, Chl,
                                             K, lda, ldb, ldc, sA, sB, sC, flags);
}

extern "C" void kernel_launch(void* const* d_in, const int* in_sizes, int n_in,
                              void* d_out, int out_size) {
    const int* ids = (const int*)d_in[0];
    const float* E = (const float*)d_in[1];
    const float* Wg = (const float*)d_in[2];
    const float* bg = (const float*)d_in[3];
    const float* Wlr = (const float*)d_in[4];
    const float* blr = (const float*)d_in[5];
    const float* Wo = (const float*)d_in[6];
    const float* bo = (const float*)d_in[7];
    const float* g_d = (const float*)d_in[8];
    const float* b_d = (const float*)d_in[9];
    const float* W1 = (const float*)d_in[10];
    const float* b1 = (const float*)d_in[11];
    const float* W2 = (const float*)d_in[12];
    const float* b2 = (const float*)d_in[13];
    const float* g_m = (const float*)d_in[14];
    const float* b_m = (const float*)d_in[15];
    const float* g_o = (const float*)d_in[16];
    const float* b_o = (const float*)d_in[17];
    float* out = (float*)d_out;

    cudaFuncSetAttribute(hgemm_kernel, cudaFuncAttributeMaxDynamicSharedMemorySize, TG_DYN_SMEM);

    float *x, *qkv, *lr, *KK, *u;
    cudaGetSymbolAddress((void**)&x, g_x);
    cudaGetSymbolAddress((void**)&qkv, g_qkv);
    cudaGetSymbolAddress((void**)&lr, g_lr);
    cudaGetSymbolAddress((void**)&KK, g_KK);
    cudaGetSymbolAddress((void**)&u, g_u);
    __half *Eh, *WgT, *WgTl, *WoT, *W1T, *W2T;
    __half *hh, *hhl, *qh, *qhl, *kh, *khl, *ut, *utl, *sh, *shl, *yh, *ah;
    cudaGetSymbolAddress((void**)&Eh, g_Eh);
    cudaGetSymbolAddress((void**)&WgT, g_WgT); cudaGetSymbolAddress((void**)&WgTl, g_WgTl);
    cudaGetSymbolAddress((void**)&WoT, g_WoT);
    cudaGetSymbolAddress((void**)&W1T, g_W1T);
    cudaGetSymbolAddress((void**)&W2T, g_W2T);
    cudaGetSymbolAddress((void**)&hh, g_hh);   cudaGetSymbolAddress((void**)&hhl, g_hhl);
    cudaGetSymbolAddress((void**)&qh, g_qh);   cudaGetSymbolAddress((void**)&qhl, g_qhl);
    cudaGetSymbolAddress((void**)&kh, g_kh);   cudaGetSymbolAddress((void**)&khl, g_khl);
    cudaGetSymbolAddress((void**)&ut, g_ut);   cudaGetSymbolAddress((void**)&utl, g_utl);
    cudaGetSymbolAddress((void**)&sh, g_sh);   cudaGetSymbolAddress((void**)&shl, g_shl);
    cudaGetSymbolAddress((void**)&yh, g_yh);
    cudaGetSymbolAddress((void**)&ah, g_ah);

    const long long sTT = (long long)TT * TT;
    const long long sTD = (long long)TT * DD;
    const int SPLIT = 16;

    // ---- prepass: convert E (hi); transpose+split Wg; transpose-convert Wo/W1/W2 (hi only) ----
    {
        long long nE = (long long)VV * DD;
        conv_kernel<<<(int)((nE / 4 + 255) / 256), 256>>>(E, Eh, nE);
        dim3 tb(32, 8);
        tsplit_kernel<<<dim3(3 * DD / 32, DD / 32, LL), tb>>>(Wg, WgT, WgTl, DD, 3 * DD,
                                                              (long long)DD * 3 * DD, (long long)DD * 3 * DD);
        // Wo/W1/W2 single-pass: reuse tsplit (lo written but unused) into their hi + scratch-lo
        __half *WoTl, *W1Tl, *W2Tl;
        cudaGetSymbolAddress((void**)&WoTl, g_WoTl);
        cudaGetSymbolAddress((void**)&W1Tl, g_W1Tl);
        cudaGetSymbolAddress((void**)&W2Tl, g_W2Tl);
        tsplit_kernel<<<dim3(DD / 32, DD / 32, LL), tb>>>(Wo, WoT, WoTl, DD, DD,
                                                          (long long)DD * DD, (long long)DD * DD);
        tsplit_kernel<<<dim3(DD / 32, DD / 32, LL), tb>>>(W1, W1T, W1Tl, DD, DD,
                                                          (long long)DD * DD, (long long)DD * DD);
        tsplit_kernel<<<dim3(DD / 32, DD / 32, LL), tb>>>(W2, W2T, W2Tl, DD, DD,
                                                          (long long)DD * DD, (long long)DD * DD);
    }

    embed_kernel<<<MTOT, 256>>>(x, E, ids);

    for (int l = 0; l < LL; ++l) {
        const __half* WgT_l = WgT + (size_t)l * 3 * DD * DD;
        const __half* WgTl_l = WgTl + (size_t)l * 3 * DD * DD;
        const __half* WoT_l = WoT + (size_t)l * DD * DD;
        const __half* W1T_l = W1T + (size_t)l * DD * DD;
        const __half* W2T_l = W2T + (size_t)l * DD * DD;

        // --- delta block (split precision: feeds the solve) ---
        ln_kernel<<<MTOT, 256>>>(hh, hhl, x, g_d + (size_t)l * DD, b_d + (size_t)l * DD,
                                 Wlr + (size_t)l * DD, blr + l, lr);
        launch_hgemm(SPLIT | 4, hh, hhl, WgT_l, WgTl_l, bg + (size_t)l * 3 * DD, nullptr,
                     qkv, nullptr, nullptr, MTOT, 3 * DD, DD, DD, DD, 3 * DD, 0, 0, 0, 1);
        knorm_kernel<<<MTOT, 256>>>(qkv, qh, qhl, kh, khl, u);
        launch_hgemm(SPLIT | 2, kh, khl, kh, khl, nullptr, nullptr,
                     KK, nullptr, nullptr, TT, TT, DD, DD, DD, TT, sTD, sTD, sTT, NB);
        for (int ci = 0; ci < 8; ++ci) {
            chunksolve2_kernel<<<dim3(DD / 256, NB), 256>>>(u, KK, ci);
            if (ci < 7) {
                int r0 = 128 * (ci + 1);
                int Mu = TT - r0;
                sgemm_upd_kernel<<<dim3(DD / 128, (Mu + 127) / 128, NB), 256>>>(
                    KK + (size_t)r0 * TT + ci * 128, u + (size_t)ci * 128 * DD,
                    u + (size_t)r0 * DD, Mu, DD, 128, TT, DD, DD, sTT, sTD, sTD);
            }
        }
        {
            dim3 tb(32, 8);
            tscale_kernel<<<dim3(DD / 32, TT / 32, NB), tb>>>(u, lr, ut, utl);
        }
        launch_hgemm(SPLIT, qh, qhl, kh, khl, nullptr, nullptr,
                     nullptr, sh, shl, TT, TT, DD, DD, DD, TT, sTD, sTD, sTT, NB);
        // y: split inputs, but only hi output needed (Wo is single-pass)
        launch_hgemm(SPLIT, sh, shl, ut, utl, nullptr, nullptr,
                     nullptr, yh, nullptr, TT, DD, TT, TT, TT, DD, sTT, sTD, sTD, NB);
        // x = x + y @ Wo + bo — SINGLE-PASS (residual-stream increment; no solve amplification)
        launch_hgemm(4 | 8, yh, yh, WoT_l, WoT_l, bo + (size_t)l * DD, x,
                     x, nullptr, nullptr, MTOT, DD, DD, DD, DD, DD, 0, 0, 0, 1);

        // --- MLP block — SINGLE-PASS GEMMs ---
        ln_kernel<<<MTOT, 256>>>(hh, hhl, x, g_m + (size_t)l * DD, b_m + (size_t)l * DD,
                                 nullptr, nullptr, nullptr);
        launch_hgemm(4 | 1, hh, hh, W1T_l, W1T_l, b1 + (size_t)l * DD, nullptr,
                     nullptr, ah, nullptr, MTOT, DD, DD, DD, DD, DD, 0, 0, 0, 1);
        launch_hgemm(4 | 8, ah, ah, W2T_l, W2T_l, b2 + (size_t)l * DD, x,
                     x, nullptr, nullptr, MTOT, DD, DD, DD, DD, DD, 0, 0, 0, 1);
    }

    // final LN + tied decoder: single-pass fp16 logits (error lands once, ~3e-4)
    ln_kernel<<<MTOT, 256>>>(hh, hhl, x, g_o, b_o, nullptr, nullptr, nullptr);
    launch_hgemm(0, hh, hh, Eh, Eh, nullptr, nullptr,
                 out, nullptr, nullptr, MTOT, VV, DD, DD, DD, VV, 0, 0, 0, 1);
}

// round 12
// speedup vs baseline: 2.3961x; 1.1577x over previous
#include <cuda_runtime.h>
#include <cuda_fp16.h>
#include <cstdint>

// Problem constants
#define NB 4          // batch
#define TT 1024       // seq len
#define DD 1024       // dim
#define LL 4          // layers
#define VV 32000      // vocab
#define MTOT (NB*TT)  // 4096 rows

// ===================== PTX helpers (base ISA only) =====================
__device__ __forceinline__ uint32_t smem_to_u32(const void* p) {
    uint32_t a;
    asm("{ .reg .u64 t; cvta.to.shared.u64 t, %1; cvt.u32.u64 %0, t; }" : "=r"(a) : "l"(p));
    return a;
}
#define CP_ASYNC16(dst, src) \
    asm volatile("cp.async.cg.shared.global [%0], [%1], 16;" :: "r"((uint32_t)(dst)), "l"(src))
#define CP_ASYNC_COMMIT() asm volatile("cp.async.commit_group;" ::: "memory")
#define CP_ASYNC_WAIT(n) asm volatile("cp.async.wait_group %0;" :: "n"(n) : "memory")

__device__ __forceinline__ void ldmx4(uint32_t* r, uint32_t addr) {
    asm volatile("ldmatrix.sync.aligned.m8n8.x4.shared.b16 {%0,%1,%2,%3}, [%4];"
                 : "=r"(r[0]), "=r"(r[1]), "=r"(r[2]), "=r"(r[3]) : "r"(addr));
}
__device__ __forceinline__ void mma16816(float* c, const uint32_t* a, const uint32_t* b) {
    asm volatile(
        "mma.sync.aligned.m16n8k16.row.col.f32.f16.f16.f32 "
        "{%0,%1,%2,%3}, {%4,%5,%6,%7}, {%8,%9}, {%0,%1,%2,%3};"
        : "+f"(c[0]), "+f"(c[1]), "+f"(c[2]), "+f"(c[3])
        : "r"(a[0]), "r"(a[1]), "r"(a[2]), "r"(a[3]), "r"(b[0]), "r"(b[1]));
}

// ===================== scratch (device globals) =====================
__device__ float g_x[MTOT * DD];
__device__ float g_qkv[MTOT * 3 * DD];
__device__ float g_lr[MTOT];
__device__ float g_KK[NB * TT * TT];
__device__ float g_u[MTOT * DD];
__device__ __half g_Eh[VV * DD], g_El[VV * DD];  // g_El unused (image parity)
__device__ __half g_WgT[LL * 3 * DD * DD], g_WgTl[LL * 3 * DD * DD];
__device__ __half g_WoT[LL * DD * DD], g_WoTl[LL * DD * DD];
__device__ __half g_W1T[LL * DD * DD], g_W1Tl[LL * DD * DD];
__device__ __half g_W2T[LL * DD * DD], g_W2Tl[LL * DD * DD];
__device__ __half g_hh[MTOT * DD], g_hhl[MTOT * DD];
__device__ __half g_qh[MTOT * DD], g_qhl[MTOT * DD];
__device__ __half g_kh[MTOT * DD], g_khl[MTOT * DD];
__device__ __half g_ut[MTOT * DD], g_utl[MTOT * DD];
__device__ __half g_sh[NB * TT * TT], g_shl[NB * TT * TT];
__device__ __half g_yh[MTOT * DD], g_yhl[MTOT * DD];
__device__ __half g_ah[MTOT * DD], g_ahl[MTOT * DD];

// ===================== small kernels =====================
__device__ __forceinline__ float blockReduceSum(float v, float* sdata) {
    int tid = threadIdx.x;
    sdata[tid] = v;
    __syncthreads();
    for (int s = 128; s > 0; s >>= 1) {
        if (tid < s) sdata[tid] += sdata[tid + s];
        __syncthreads();
    }
    float r = sdata[0];
    __syncthreads();
    return r;
}

__device__ __forceinline__ void store_h4_pair(__half* ph, __half* pl,
                                              float a, float b, float c, float d) {
    union { __half2 h2[2]; uint2 u; } hi, lo;
    hi.h2[0] = __floats2half2_rn(a, b);
    hi.h2[1] = __floats2half2_rn(c, d);
    lo.h2[0] = __floats2half2_rn(a - __half2float(hi.h2[0].x), b - __half2float(hi.h2[0].y));
    lo.h2[1] = __floats2half2_rn(c - __half2float(hi.h2[1].x), d - __half2float(hi.h2[1].y));
    *(uint2*)ph = hi.u;
    *(uint2*)pl = lo.u;
}

__global__ void embed_kernel(float* __restrict__ x, const float* __restrict__ E,
                             const int* __restrict__ ids) {
    int m = blockIdx.x;
    int id = ids[m];
    const float4* src = (const float4*)(E + (size_t)id * DD);
    float4* dst = (float4*)(x + (size_t)m * DD);
    dst[threadIdx.x] = src[threadIdx.x];
}

__global__ void ln_kernel(__half* __restrict__ oh, __half* __restrict__ ol,
                          const float* __restrict__ in,
                          const float* __restrict__ g, const float* __restrict__ b,
                          const float* __restrict__ Wlr, const float* __restrict__ blr,
                          float* __restrict__ lr) {
    __shared__ float sdata[256];
    int m = blockIdx.x, tid = threadIdx.x;
    const float* row = in + (size_t)m * DD;
    float4 v = *(const float4*)(row + tid * 4);
    float s = v.x + v.y + v.z + v.w;
    float mean = blockReduceSum(s, sdata) * (1.0f / DD);
    float dx = v.x - mean, dy = v.y - mean, dz = v.z - mean, dw = v.w - mean;
    float s2 = dx * dx + dy * dy + dz * dz + dw * dw;
    float var = blockReduceSum(s2, sdata) * (1.0f / DD);
    float rstd = 1.0f / sqrtf(var + 1e-5f);
    int c = tid * 4;
    float n0 = dx * rstd * g[c + 0] + b[c + 0];
    float n1 = dy * rstd * g[c + 1] + b[c + 1];
    float n2 = dz * rstd * g[c + 2] + b[c + 2];
    float n3 = dw * rstd * g[c + 3] + b[c + 3];
    store_h4_pair(oh + (size_t)m * DD + c, ol + (size_t)m * DD + c, n0, n1, n2, n3);
    if (Wlr) {
        float4 wv = *(const float4*)(Wlr + c);
        float d = n0 * wv.x + n1 * wv.y + n2 * wv.z + n3 * wv.w;
        float dot = blockReduceSum(d, sdata);
        if (tid == 0) lr[m] = dot + blr[0];
    }
}

__global__ void knorm_kernel(const float* __restrict__ qkv,
                             __half* __restrict__ qh, __half* __restrict__ ql,
                             __half* __restrict__ kh, __half* __restrict__ kl,
                             float* __restrict__ u) {
    __shared__ float sdata[256];
    int m = blockIdx.x, tid = threadIdx.x;
    const float* base = qkv + (size_t)m * (3 * DD);
    int c = tid * 4;
    float4 kv = *(const float4*)(base + DD + c);
    float ss = kv.x * kv.x + kv.y * kv.y + kv.z * kv.z + kv.w * kv.w;
    float ksum = blockReduceSum(ss, sdata);
    float scale = 1.0f / sqrtf(ksum);
    size_t o = (size_t)m * DD + c;
    store_h4_pair(kh + o, kl + o, kv.x * scale, kv.y * scale, kv.z * scale, kv.w * scale);
    float4 qv = *(const float4*)(base + c);
    store_h4_pair(qh + o, ql + o, qv.x, qv.y, qv.z, qv.w);
    *(float4*)(u + o) = *(const float4*)(base + 2 * DD + c);
}

// transpose + lr-scale + fp16 hi/lo: u [T,D] fp32 -> ut [D,T] (batched via z)
__global__ void tscale_kernel(const float* __restrict__ u, const float* __restrict__ lr,
                              __half* __restrict__ ut, __half* __restrict__ utl) {
    __shared__ float tile[32][33];
    long long z = blockIdx.z;
    u += z * (long long)TT * DD;
    ut += z * (long long)TT * DD;
    utl += z * (long long)TT * DD;
    lr += z * TT;
    int r0 = blockIdx.y * 32, c0 = blockIdx.x * 32;
    int tx = threadIdx.x, ty = threadIdx.y;  // 32 x 8
#pragma unroll
    for (int i = 0; i < 32; i += 8)
        tile[ty + i][tx] = u[(size_t)(r0 + ty + i) * DD + c0 + tx] * lr[r0 + ty + i];
    __syncthreads();
#pragma unroll
    for (int i = 0; i < 32; i += 8) {
        int c = c0 + ty + i, r = r0 + tx;
        float v = tile[tx][ty + i];
        __half hv = __float2half_rn(v);
        ut[(size_t)c * TT + r] = hv;
        utl[(size_t)c * TT + r] = __float2half_rn(v - __half2float(hv));
    }
}

// fp32 -> fp16 elementwise (for E hi)
__global__ void conv_kernel(const float* __restrict__ in, __half* __restrict__ out, long long n) {
    long long i = ((long long)blockIdx.x * blockDim.x + threadIdx.x) * 4;
    if (i >= n) return;
    float4 v = *(const float4*)(in + i);
    union { __half2 h2[2]; uint2 u; } pk;
    pk.h2[0] = __floats2half2_rn(v.x, v.y);
    pk.h2[1] = __floats2half2_rn(v.z, v.w);
    *(uint2*)(out + i) = pk.u;
}

// transpose + fp16 hi/lo: in [R,C] fp32 -> out [C,R] (batched via z)
__global__ void tsplit_kernel(const float* __restrict__ in, __half* __restrict__ oh,
                              __half* __restrict__ ol, int R, int C,
                              long long sIn, long long sOut) {
    __shared__ float tile[32][33];
    long long z = blockIdx.z;
    in += z * sIn; oh += z * sOut; ol += z * sOut;
    int r0 = blockIdx.y * 32, c0 = blockIdx.x * 32;
    int tx = threadIdx.x, ty = threadIdx.y;
#pragma unroll
    for (int i = 0; i < 32; i += 8)
        tile[ty + i][tx] = in[(size_t)(r0 + ty + i) * C + c0 + tx];
    __syncthreads();
#pragma unroll
    for (int i = 0; i < 32; i += 8) {
        int c = c0 + ty + i, r = r0 + tx;
        float v = tile[tx][ty + i];
        __half hv = __float2half_rn(v);
        oh[(size_t)c * R + r] = hv;
        ol[(size_t)c * R + r] = __float2half_rn(v - __half2float(hv));
    }
}

// ============ mma.sync fp16(x2-split) NT GEMM, 2-stage, 2 CTAs/SM ============
// C = A@B^T; split: 3 MMAs (Ah*Bh + Ah*Bl + Al*Bh), BK=32; single: 1 MMA on hi, BK=64
// (lo-tile smem slots repurposed as the second K-half; identical accumulation order).
// CTA 128x128, 256 thr = 8 warps (4m x 2n), warp tile 32x64.
// smem/stage: 4 tiles x 128 rows x 80B = 40960B; 2 stages = 81920B (opt-in; 2 CTAs/SM).
// flags: 1=relu 2=strict-lower-mask 4=bias 8=resid 16=split
#define TILE_B 10240
#define STAGE_B 40960
#define TG_DYN_SMEM 81920

__global__ void __launch_bounds__(256, 2)
hgemm_kernel(const __half* __restrict__ Ah, const __half* __restrict__ Al,
             const __half* __restrict__ Bh, const __half* __restrict__ Bl,
             const float* __restrict__ bias, const float* __restrict__ resid,
             float* __restrict__ C, __half* __restrict__ Ch, __half* __restrict__ Chl,
             int K, int lda, int ldb, int ldc,
             long long sA, long long sB, long long sC, int flags) {
    long long z = blockIdx.z;
    Ah += z * sA; Bh += z * sB;
    Al += z * sA; Bl += z * sB;   // always valid (hi aliased when !split)
    if (C) C += z * sC;
    if (Ch) Ch += z * sC;
    if (Chl) Chl += z * sC;
    if (resid) resid += z * sC;
    int m0 = blockIdx.x * 128, n0 = blockIdx.y * 128;
    if ((flags & 2) && n0 >= m0 + 128) return;
    const bool split = (flags & 16) != 0;

    extern __shared__ char dynsmem[];
    uint32_t sb = smem_to_u32(dynsmem);
    int tid = threadIdx.x, lane = tid & 31, wid = tid >> 5;
    int wm = wid >> 1, wn = wid & 1;

    int ldrow = tid & 127, ldpair = tid >> 7;
    const __half* ph = (ldpair ? Bh : Ah) + (size_t)((ldpair ? n0 : m0) + ldrow) * (ldpair ? ldb : lda);
    const __half* pl = (ldpair ? Bl : Al) + (size_t)((ldpair ? n0 : m0) + ldrow) * (ldpair ? ldb : lda);
    uint32_t dsth = sb + ldpair * 2 * TILE_B + ldrow * 80;
    uint32_t dstl = dsth + TILE_B;

    // split: BK=32 per chunk; single: BK=64 per chunk (lo slots = k32..63)
    const int nch = split ? (K >> 5) : (K >> 6);

#define ISSUE_STAGE(cc) do {                                                  \
        uint32_t _so = ((cc) & 1) * STAGE_B;                                  \
        if (split) {                                                          \
            const __half* _q = ph + ((size_t)(cc) << 5);                      \
            CP_ASYNC16(dsth + _so, _q);           CP_ASYNC16(dsth + _so + 16, _q + 8);  \
            CP_ASYNC16(dsth + _so + 32, _q + 16); CP_ASYNC16(dsth + _so + 48, _q + 24); \
            const __half* _ql = pl + ((size_t)(cc) << 5);                     \
            CP_ASYNC16(dstl + _so, _ql);           CP_ASYNC16(dstl + _so + 16, _ql + 8);  \
            CP_ASYNC16(dstl + _so + 32, _ql + 16); CP_ASYNC16(dstl + _so + 48, _ql + 24); \
        } else {                                                              \
            const __half* _q = ph + ((size_t)(cc) << 6);                      \
            CP_ASYNC16(dsth + _so, _q);           CP_ASYNC16(dsth + _so + 16, _q + 8);  \
            CP_ASYNC16(dsth + _so + 32, _q + 16); CP_ASYNC16(dsth + _so + 48, _q + 24); \
            CP_ASYNC16(dstl + _so, _q + 32);      CP_ASYNC16(dstl + _so + 16, _q + 40); \
            CP_ASYNC16(dstl + _so + 32, _q + 48); CP_ASYNC16(dstl + _so + 48, _q + 56); \
        }                                                                     \
        CP_ASYNC_COMMIT();                                                    \
    } while (0)

    ISSUE_STAGE(0);

    float acc[2][8][4];
#pragma unroll
    for (int i = 0; i < 2; ++i)
#pragma unroll
        for (int j = 0; j < 8; ++j)
#pragma unroll
            for (int r = 0; r < 4; ++r) acc[i][j][r] = 0.0f;

    uint32_t a_off = (lane & 15) * 80 + (lane >> 4) * 16;
    uint32_t b_off = ((lane & 7) + ((lane >> 4) & 1) * 8) * 80 + ((lane >> 3) & 1) * 16;

    for (int c = 0; c < nch; ++c) {
        if (c + 1 < nch) {
            ISSUE_STAGE(c + 1);
            CP_ASYNC_WAIT(1);
        } else {
            CP_ASYNC_WAIT(0);
        }
        __syncthreads();

        uint32_t st = sb + (c & 1) * STAGE_B;
        uint32_t aBase = st + (wm * 32) * 80 + a_off;
        uint32_t alBase = aBase + TILE_B;
        uint32_t bBase = st + 2 * TILE_B + (wn * 64) * 80 + b_off;
        uint32_t blBase = bBase + TILE_B;

        if (split) {
#pragma unroll
            for (int kk = 0; kk < 2; ++kk) {
                uint32_t kof = kk * 32;
                uint32_t af[2][4], alf[2][4];
#pragma unroll
                for (int i = 0; i < 2; ++i) {
                    ldmx4(af[i], aBase + i * 1280 + kof);
                    ldmx4(alf[i], alBase + i * 1280 + kof);
                }
#pragma unroll
                for (int jj = 0; jj < 4; ++jj) {
                    uint32_t rb[4], rbl[4];
                    ldmx4(rb, bBase + jj * 1280 + kof);
                    ldmx4(rbl, blBase + jj * 1280 + kof);
#pragma unroll
                    for (int h = 0; h < 2; ++h) {
                        int j = 2 * jj + h;
                        uint32_t bf[2] = {rb[2 * h], rb[2 * h + 1]};
                        uint32_t blf[2] = {rbl[2 * h], rbl[2 * h + 1]};
#pragma unroll
                        for (int i = 0; i < 2; ++i) {
                            mma16816(acc[i][j], af[i], bf);
                            mma16816(acc[i][j], af[i], blf);
                            mma16816(acc[i][j], alf[i], bf);
                        }
                    }
                }
            }
        } else {
            // BK=64: 4 k16 steps; hi tile holds k0..31, lo-slot tile holds k32..63
#pragma unroll
            for (int kk = 0; kk < 4; ++kk) {
                uint32_t ab = (kk < 2 ? aBase : alBase) + (kk & 1) * 32;
                uint32_t bb = (kk < 2 ? bBase : blBase) + (kk & 1) * 32;
                uint32_t af[2][4];
                ldmx4(af[0], ab);
                ldmx4(af[1], ab + 1280);
#pragma unroll
                for (int jj = 0; jj < 4; ++jj) {
                    uint32_t rb[4];
                    ldmx4(rb, bb + jj * 1280);
#pragma unroll
                    for (int h = 0; h < 2; ++h) {
                        int j = 2 * jj + h;
                        uint32_t bf[2] = {rb[2 * h], rb[2 * h + 1]};
#pragma unroll
                        for (int i = 0; i < 2; ++i) mma16816(acc[i][j], af[i], bf);
                    }
                }
            }
        }
        __syncthreads();
    }

    // epilogue
    int rbase = m0 + wm * 32 + (lane >> 2);
    int cbase = n0 + wn * 64 + (lane & 3) * 2;
#pragma unroll
    for (int i = 0; i < 2; ++i) {
        int r = rbase + i * 16;
#pragma unroll
        for (int j = 0; j < 8; ++j) {
            int cc = cbase + j * 8;
            float2 lo = make_float2(acc[i][j][0], acc[i][j][1]);
            float2 hi = make_float2(acc[i][j][2], acc[i][j][3]);
            if (flags & 4) {
                float2 bv = *(const float2*)(bias + cc);
                lo.x += bv.x; lo.y += bv.y; hi.x += bv.x; hi.y += bv.y;
            }
            if (flags & 8) {
                float2 r0 = *(const float2*)(resid + (long long)r * ldc + cc);
                float2 r1 = *(const float2*)(resid + (long long)(r + 8) * ldc + cc);
                lo.x += r0.x; lo.y += r0.y; hi.x += r1.x; hi.y += r1.y;
            }
            if (flags & 1) {
                lo.x = fmaxf(lo.x, 0.f); lo.y = fmaxf(lo.y, 0.f);
                hi.x = fmaxf(hi.x, 0.f); hi.y = fmaxf(hi.y, 0.f);
            }
            if (flags & 2) {
                if (cc + 0 >= r) lo.x = 0.f;
                if (cc + 1 >= r) lo.y = 0.f;
                if (cc + 0 >= r + 8) hi.x = 0.f;
                if (cc + 1 >= r + 8) hi.y = 0.f;
            }
            if (Ch) {
                __half2 hlo = __floats2half2_rn(lo.x, lo.y);
                __half2 hhi = __floats2half2_rn(hi.x, hi.y);
                *(__half2*)(Ch + (long long)r * ldc + cc) = hlo;
                *(__half2*)(Ch + (long long)(r + 8) * ldc + cc) = hhi;
                if (Chl) {
                    *(__half2*)(Chl + (long long)r * ldc + cc) =
                        __floats2half2_rn(lo.x - __half2float(hlo.x), lo.y - __half2float(hlo.y));
                    *(__half2*)(Chl + (long long)(r + 8) * ldc + cc) =
                        __floats2half2_rn(hi.x - __half2float(hhi.x), hi.y - __half2float(hhi.y));
                }
            } else {
                *(float2*)(C + (long long)r * ldc + cc) = lo;
                *(float2*)(C + (long long)(r + 8) * ldc + cc) = hi;
            }
        }
    }
#undef ISSUE_STAGE
}

// ===================== fused 128-row panel forward substitution =====================
__global__ void chunksolve2_kernel(float* __restrict__ u, const float* __restrict__ KK, int ci) {
    __shared__ float Ks[64][64];
    __shared__ float Ks2[64][64];
    __shared__ float Ksn[64][64];
    int batch = blockIdx.y;
    int d = blockIdx.x * 256 + threadIdx.x;
    const float* KKb = KK + (size_t)batch * TT * TT;
    float* ub = u + (size_t)batch * TT * DD;
    int base = ci * 128;
    for (int i = threadIdx.x; i < 64 * 64; i += 256) {
        int r = i >> 6, c = i & 63;
        Ks[r][c]  = KKb[(size_t)(base + r) * TT + base + c];
        Ks2[r][c] = KKb[(size_t)(base + 64 + r) * TT + base + c];
        Ksn[r][c] = KKb[(size_t)(base + 64 + r) * TT + base + 64 + c];
    }
    __syncthreads();
    float uloc[64];
#pragma unroll
    for (int r = 0; r < 64; ++r) {
        float val = ub[(size_t)(base + r) * DD + d];
#pragma unroll
        for (int s = 0; s < r; ++s) val -= Ks[r][s] * uloc[s];
        uloc[r] = val;
        ub[(size_t)(base + r) * DD + d] = val;
    }
#pragma unroll 4
    for (int r = 0; r < 64; ++r) {
        float val = ub[(size_t)(base + 64 + r) * DD + d];
#pragma unroll
        for (int s = 0; s < 64; ++s) val -= Ks2[r][s] * uloc[s];
        ub[(size_t)(base + 64 + r) * DD + d] = val;
    }
#pragma unroll
    for (int r = 0; r < 64; ++r) {
        float val = ub[(size_t)(base + 64 + r) * DD + d];
#pragma unroll
        for (int s = 0; s < r; ++s) val -= Ksn[r][s] * uloc[s];
        uloc[r] = val;
        ub[(size_t)(base + 64 + r) * DD + d] = val;
    }
}

// ===================== SIMT SGEMM (solve trailing updates): C -= A@B =====================
__global__ void sgemm_upd_kernel(const float* __restrict__ A, const float* __restrict__ B,
                                 float* __restrict__ C, int M, int N, int K,
                                 int lda, int ldb, int ldc,
                                 long long sA, long long sB, long long sC) {
    long long z = blockIdx.z;
    A += z * sA; B += z * sB; C += z * sC;
    int m0 = blockIdx.y * 128, n0 = blockIdx.x * 128;
    __shared__ float As[8][128];
    __shared__ float Bs[8][128];
    int tid = threadIdx.x;
    int tx = tid & 15, ty = tid >> 4;
    int ar = tid >> 1, ac = (tid & 1) * 4;
    int br = tid >> 5, bc = (tid & 31) * 4;
    float acc[8][8];
#pragma unroll
    for (int i = 0; i < 8; ++i)
#pragma unroll
        for (int j = 0; j < 8; ++j) acc[i][j] = 0.0f;
    for (int k0 = 0; k0 < K; k0 += 8) {
        float4 av = make_float4(0.f, 0.f, 0.f, 0.f);
        if (m0 + ar < M) av = *(const float4*)(A + (long long)(m0 + ar) * lda + k0 + ac);
        As[ac + 0][ar] = av.x; As[ac + 1][ar] = av.y;
        As[ac + 2][ar] = av.z; As[ac + 3][ar] = av.w;
        float4 bv = *(const float4*)(B + (long long)(k0 + br) * ldb + n0 + bc);
        *(float4*)&Bs[br][bc] = bv;
        __syncthreads();
#pragma unroll
        for (int k = 0; k < 8; ++k) {
            float ra[8], rb[8];
            *(float4*)&ra[0] = *(float4*)&As[k][ty * 8];
            *(float4*)&ra[4] = *(float4*)&As[k][ty * 8 + 4];
            *(float4*)&rb[0] = *(float4*)&Bs[k][tx * 8];
            *(float4*)&rb[4] = *(float4*)&Bs[k][tx * 8 + 4];
#pragma unroll
            for (int i = 0; i < 8; ++i)
#pragma unroll
                for (int j = 0; j < 8; ++j) acc[i][j] += ra[i] * rb[j];
        }
        __syncthreads();
    }
#pragma unroll
    for (int i = 0; i < 8; ++i) {
        int r = m0 + ty * 8 + i;
        if (r >= M) continue;
#pragma unroll
        for (int j = 0; j < 8; ++j) {
            int c = n0 + tx * 8 + j;
            C[(long long)r * ldc + c] -= acc[i][j];
        }
    }
}

// ===================== host launcher =====================
static void launch_hgemm(int flags, const __half* Ah, const __half* Al,
                         const __half* Bh, const __half* Bl,
                         const float* bias, const float* resid,
                         float* C, __half* Ch, __half* Chl,
                         int M, int N, int K, int lda, int ldb, int ldc,
                         long long sA, long long sB, long long sC, int batch) {
    dim3 grid(M / 128, N / 128, batch);  // x = M tiles (L2 reuse of A)
    hgemm_kernel<<<grid, 256, TG_DYN_SMEM>>>(Ah, Al, Bh, Bl, bias, resid, C, Ch, Chl,
                                             K, lda, ldb, ldc, sA, sB, sC, flags);
}

extern "C" void kernel_launch(void* const* d_in, const int* in_sizes, int n_in,
                              void* d_out, int out_size) {
    const int* ids = (const int*)d_in[0];
    const float* E = (const float*)d_in[1];
    const float* Wg = (const float*)d_in[2];
    const float* bg = (const float*)d_in[3];
    const float* Wlr = (const float*)d_in[4];
    const float* blr = (const float*)d_in[5];
    const float* Wo = (const float*)d_in[6];
    const float* bo = (const float*)d_in[7];
    const float* g_d = (const float*)d_in[8];
    const float* b_d = (const float*)d_in[9];
    const float* W1 = (const float*)d_in[10];
    const float* b1 = (const float*)d_in[11];
    const float* W2 = (const float*)d_in[12];
    const float* b2 = (const float*)d_in[13];
    const float* g_m = (const float*)d_in[14];
    const float* b_m = (const float*)d_in[15];
    const float* g_o = (const float*)d_in[16];
    const float* b_o = (const float*)d_in[17];
    float* out = (float*)d_out;

    cudaFuncSetAttribute(hgemm_kernel, cudaFuncAttributeMaxDynamicSharedMemorySize, TG_DYN_SMEM);

    float *x, *qkv, *lr, *KK, *u;
    cudaGetSymbolAddress((void**)&x, g_x);
    cudaGetSymbolAddress((void**)&qkv, g_qkv);
    cudaGetSymbolAddress((void**)&lr, g_lr);
    cudaGetSymbolAddress((void**)&KK, g_KK);
    cudaGetSymbolAddress((void**)&u, g_u);
    __half *Eh, *WgT, *WgTl, *WoT, *W1T, *W2T;
    __half *hh, *hhl, *qh, *qhl, *kh, *khl, *ut, *utl, *sh, *shl, *yh, *ah;
    cudaGetSymbolAddress((void**)&Eh, g_Eh);
    cudaGetSymbolAddress((void**)&WgT, g_WgT); cudaGetSymbolAddress((void**)&WgTl, g_WgTl);
    cudaGetSymbolAddress((void**)&WoT, g_WoT);
    cudaGetSymbolAddress((void**)&W1T, g_W1T);
    cudaGetSymbolAddress((void**)&W2T, g_W2T);
    cudaGetSymbolAddress((void**)&hh, g_hh);   cudaGetSymbolAddress((void**)&hhl, g_hhl);
    cudaGetSymbolAddress((void**)&qh, g_qh);   cudaGetSymbolAddress((void**)&qhl, g_qhl);
    cudaGetSymbolAddress((void**)&kh, g_kh);   cudaGetSymbolAddress((void**)&khl, g_khl);
    cudaGetSymbolAddress((void**)&ut, g_ut);   cudaGetSymbolAddress((void**)&utl, g_utl);
    cudaGetSymbolAddress((void**)&sh, g_sh);   cudaGetSymbolAddress((void**)&shl, g_shl);
    cudaGetSymbolAddress((void**)&yh, g_yh);
    cudaGetSymbolAddress((void**)&ah, g_ah);

    const long long sTT = (long long)TT * TT;
    const long long sTD = (long long)TT * DD;
    const int SPLIT = 16;

    // ---- prepass: convert E (hi); transpose+split Wg; transpose-convert Wo/W1/W2 (hi only) ----
    {
        long long nE = (long long)VV * DD;
        conv_kernel<<<(int)((nE / 4 + 255) / 256), 256>>>(E, Eh, nE);
        dim3 tb(32, 8);
        tsplit_kernel<<<dim3(3 * DD / 32, DD / 32, LL), tb>>>(Wg, WgT, WgTl, DD, 3 * DD,
                                                              (long long)DD * 3 * DD, (long long)DD * 3 * DD);
        __half *WoTl, *W1Tl, *W2Tl;
        cudaGetSymbolAddress((void**)&WoTl, g_WoTl);
        cudaGetSymbolAddress((void**)&W1Tl, g_W1Tl);
        cudaGetSymbolAddress((void**)&W2Tl, g_W2Tl);
        tsplit_kernel<<<dim3(DD / 32, DD / 32, LL), tb>>>(Wo, WoT, WoTl, DD, DD,
                                                          (long long)DD * DD, (long long)DD * DD);
        tsplit_kernel<<<dim3(DD / 32, DD / 32, LL), tb>>>(W1, W1T, W1Tl, DD, DD,
                                                          (long long)DD * DD, (long long)DD * DD);
        tsplit_kernel<<<dim3(DD / 32, DD / 32, LL), tb>>>(W2, W2T, W2Tl, DD, DD,
                                                          (long long)DD * DD, (long long)DD * DD);
    }

    embed_kernel<<<MTOT, 256>>>(x, E, ids);

    for (int l = 0; l < LL; ++l) {
        const __half* WgT_l = WgT + (size_t)l * 3 * DD * DD;
        const __half* WgTl_l = WgTl + (size_t)l * 3 * DD * DD;
        const __half* WoT_l = WoT + (size_t)l * DD * DD;
        const __half* W1T_l = W1T + (size_t)l * DD * DD;
        const __half* W2T_l = W2T + (size_t)l * DD * DD;

        // --- delta block (split precision: feeds the solve) ---
        ln_kernel<<<MTOT, 256>>>(hh, hhl, x, g_d + (size_t)l * DD, b_d + (size_t)l * DD,
                                 Wlr + (size_t)l * DD, blr + l, lr);
        launch_hgemm(SPLIT | 4, hh, hhl, WgT_l, WgTl_l, bg + (size_t)l * 3 * DD, nullptr,
                     qkv, nullptr, nullptr, MTOT, 3 * DD, DD, DD, DD, 3 * DD, 0, 0, 0, 1);
        knorm_kernel<<<MTOT, 256>>>(qkv, qh, qhl, kh, khl, u);
        launch_hgemm(SPLIT | 2, kh, khl, kh, khl, nullptr, nullptr,
                     KK, nullptr, nullptr, TT, TT, DD, DD, DD, TT, sTD, sTD, sTT, NB);
        for (int ci = 0; ci < 8; ++ci) {
            chunksolve2_kernel<<<dim3(DD / 256, NB), 256>>>(u, KK, ci);
            if (ci < 7) {
                int r0 = 128 * (ci + 1);
                int Mu = TT - r0;
                sgemm_upd_kernel<<<dim3(DD / 128, (Mu + 127) / 128, NB), 256>>>(
                    KK + (size_t)r0 * TT + ci * 128, u + (size_t)ci * 128 * DD,
                    u + (size_t)r0 * DD, Mu, DD, 128, TT, DD, DD, sTT, sTD, sTD);
            }
        }
        {
            dim3 tb(32, 8);
            tscale_kernel<<<dim3(DD / 32, TT / 32, NB), tb>>>(u, lr, ut, utl);
        }
        launch_hgemm(SPLIT, qh, qhl, kh, khl, nullptr, nullptr,
                     nullptr, sh, shl, TT, TT, DD, DD, DD, TT, sTD, sTD, sTT, NB);
        // y: split inputs, only hi output needed (Wo is single-pass)
        launch_hgemm(SPLIT, sh, shl, ut, utl, nullptr, nullptr,
                     nullptr, yh, nullptr, TT, DD, TT, TT, TT, DD, sTT, sTD, sTD, NB);
        // x = x + y @ Wo + bo — SINGLE-PASS, BK=64 path
        launch_hgemm(4 | 8, yh, yh, WoT_l, WoT_l, bo + (size_t)l * DD, x,
                     x, nullptr, nullptr, MTOT, DD, DD, DD, DD, DD, 0, 0, 0, 1);

        // --- MLP block — SINGLE-PASS GEMMs, BK=64 path ---
        ln_kernel<<<MTOT, 256>>>(hh, hhl, x, g_m + (size_t)l * DD, b_m + (size_t)l * DD,
                                 nullptr, nullptr, nullptr);
        launch_hgemm(4 | 1, hh, hh, W1T_l, W1T_l, b1 + (size_t)l * DD, nullptr,
                     nullptr, ah, nullptr, MTOT, DD, DD, DD, DD, DD, 0, 0, 0, 1);
        launch_hgemm(4 | 8, ah, ah, W2T_l, W2T_l, b2 + (size_t)l * DD, x,
                     x, nullptr, nullptr, MTOT, DD, DD, DD, DD, DD, 0, 0, 0, 1);
    }

    // final LN + tied decoder: single-pass fp16 logits, BK=64 path
    ln_kernel<<<MTOT, 256>>>(hh, hhl, x, g_o, b_o, nullptr, nullptr, nullptr);
    launch_hgemm(0, hh, hh, Eh, Eh, nullptr, nullptr,
                 out, nullptr, nullptr, MTOT, VV, DD, DD, DD, VV, 0, 0, 0, 1);
}

// round 14
// speedup vs baseline: 2.4013x; 1.0022x over previous
#include <cuda_runtime.h>
#include <cuda_fp16.h>
#include <cstdint>

// Problem constants
#define NB 4          // batch
#define TT 1024       // seq len
#define DD 1024       // dim
#define LL 4          // layers
#define VV 32000      // vocab
#define MTOT (NB*TT)  // 4096 rows

// ===================== PTX helpers (base ISA only) =====================
__device__ __forceinline__ uint32_t smem_to_u32(const void* p) {
    uint32_t a;
    asm("{ .reg .u64 t; cvta.to.shared.u64 t, %1; cvt.u32.u64 %0, t; }" : "=r"(a) : "l"(p));
    return a;
}
#define CP_ASYNC16(dst, src) \
    asm volatile("cp.async.cg.shared.global [%0], [%1], 16;" :: "r"((uint32_t)(dst)), "l"(src))
#define CP_ASYNC_COMMIT() asm volatile("cp.async.commit_group;" ::: "memory")
#define CP_ASYNC_WAIT(n) asm volatile("cp.async.wait_group %0;" :: "n"(n) : "memory")

__device__ __forceinline__ void ldmx4(uint32_t* r, uint32_t addr) {
    asm volatile("ldmatrix.sync.aligned.m8n8.x4.shared.b16 {%0,%1,%2,%3}, [%4];"
                 : "=r"(r[0]), "=r"(r[1]), "=r"(r[2]), "=r"(r[3]) : "r"(addr));
}
__device__ __forceinline__ void mma16816(float* c, const uint32_t* a, const uint32_t* b) {
    asm volatile(
        "mma.sync.aligned.m16n8k16.row.col.f32.f16.f16.f32 "
        "{%0,%1,%2,%3}, {%4,%5,%6,%7}, {%8,%9}, {%0,%1,%2,%3};"
        : "+f"(c[0]), "+f"(c[1]), "+f"(c[2]), "+f"(c[3])
        : "r"(a[0]), "r"(a[1]), "r"(a[2]), "r"(a[3]), "r"(b[0]), "r"(b[1]));
}

// ===================== scratch (device globals) =====================
__device__ float g_x[MTOT * DD];
__device__ float g_qkv[MTOT * 3 * DD];
__device__ float g_lr[MTOT];
__device__ float g_KK[NB * TT * TT];
__device__ float g_u[MTOT * DD];
__device__ __half g_Eh[VV * DD], g_El[VV * DD];  // g_El unused (image parity)
__device__ __half g_WgT[LL * 3 * DD * DD], g_WgTl[LL * 3 * DD * DD];
__device__ __half g_WoT[LL * DD * DD], g_WoTl[LL * DD * DD];
__device__ __half g_W1T[LL * DD * DD], g_W1Tl[LL * DD * DD];
__device__ __half g_W2T[LL * DD * DD], g_W2Tl[LL * DD * DD];
__device__ __half g_hh[MTOT * DD], g_hhl[MTOT * DD];
__device__ __half g_qh[MTOT * DD], g_qhl[MTOT * DD];
__device__ __half g_kh[MTOT * DD], g_khl[MTOT * DD];
__device__ __half g_ut[MTOT * DD], g_utl[MTOT * DD];
__device__ __half g_sh[NB * TT * TT], g_shl[NB * TT * TT];
__device__ __half g_yh[MTOT * DD], g_yhl[MTOT * DD];
__device__ __half g_ah[MTOT * DD], g_ahl[MTOT * DD];

// ===================== small kernels =====================
__device__ __forceinline__ float blockReduceSum(float v, float* sdata) {
    int tid = threadIdx.x;
    sdata[tid] = v;
    __syncthreads();
    for (int s = 128; s > 0; s >>= 1) {
        if (tid < s) sdata[tid] += sdata[tid + s];
        __syncthreads();
    }
    float r = sdata[0];
    __syncthreads();
    return r;
}

__device__ __forceinline__ void store_h4_pair(__half* ph, __half* pl,
                                              float a, float b, float c, float d) {
    union { __half2 h2[2]; uint2 u; } hi, lo;
    hi.h2[0] = __floats2half2_rn(a, b);
    hi.h2[1] = __floats2half2_rn(c, d);
    lo.h2[0] = __floats2half2_rn(a - __half2float(hi.h2[0].x), b - __half2float(hi.h2[0].y));
    lo.h2[1] = __floats2half2_rn(c - __half2float(hi.h2[1].x), d - __half2float(hi.h2[1].y));
    *(uint2*)ph = hi.u;
    *(uint2*)pl = lo.u;
}

__global__ void embed_kernel(float* __restrict__ x, const float* __restrict__ E,
                             const int* __restrict__ ids) {
    int m = blockIdx.x;
    int id = ids[m];
    const float4* src = (const float4*)(E + (size_t)id * DD);
    float4* dst = (float4*)(x + (size_t)m * DD);
    dst[threadIdx.x] = src[threadIdx.x];
}

__global__ void ln_kernel(__half* __restrict__ oh, __half* __restrict__ ol,
                          const float* __restrict__ in,
                          const float* __restrict__ g, const float* __restrict__ b,
                          const float* __restrict__ Wlr, const float* __restrict__ blr,
                          float* __restrict__ lr) {
    __shared__ float sdata[256];
    int m = blockIdx.x, tid = threadIdx.x;
    const float* row = in + (size_t)m * DD;
    float4 v = *(const float4*)(row + tid * 4);
    float s = v.x + v.y + v.z + v.w;
    float mean = blockReduceSum(s, sdata) * (1.0f / DD);
    float dx = v.x - mean, dy = v.y - mean, dz = v.z - mean, dw = v.w - mean;
    float s2 = dx * dx + dy * dy + dz * dz + dw * dw;
    float var = blockReduceSum(s2, sdata) * (1.0f / DD);
    float rstd = 1.0f / sqrtf(var + 1e-5f);
    int c = tid * 4;
    float n0 = dx * rstd * g[c + 0] + b[c + 0];
    float n1 = dy * rstd * g[c + 1] + b[c + 1];
    float n2 = dz * rstd * g[c + 2] + b[c + 2];
    float n3 = dw * rstd * g[c + 3] + b[c + 3];
    store_h4_pair(oh + (size_t)m * DD + c, ol + (size_t)m * DD + c, n0, n1, n2, n3);
    if (Wlr) {
        float4 wv = *(const float4*)(Wlr + c);
        float d = n0 * wv.x + n1 * wv.y + n2 * wv.z + n3 * wv.w;
        float dot = blockReduceSum(d, sdata);
        if (tid == 0) lr[m] = dot + blr[0];
    }
}

__global__ void knorm_kernel(const float* __restrict__ qkv,
                             __half* __restrict__ qh, __half* __restrict__ ql,
                             __half* __restrict__ kh, __half* __restrict__ kl,
                             float* __restrict__ u) {
    __shared__ float sdata[256];
    int m = blockIdx.x, tid = threadIdx.x;
    const float* base = qkv + (size_t)m * (3 * DD);
    int c = tid * 4;
    float4 kv = *(const float4*)(base + DD + c);
    float ss = kv.x * kv.x + kv.y * kv.y + kv.z * kv.z + kv.w * kv.w;
    float ksum = blockReduceSum(ss, sdata);
    float scale = 1.0f / sqrtf(ksum);
    size_t o = (size_t)m * DD + c;
    store_h4_pair(kh + o, kl + o, kv.x * scale, kv.y * scale, kv.z * scale, kv.w * scale);
    float4 qv = *(const float4*)(base + c);
    store_h4_pair(qh + o, ql + o, qv.x, qv.y, qv.z, qv.w);
    *(float4*)(u + o) = *(const float4*)(base + 2 * DD + c);
}

// transpose + lr-scale + fp16 hi/lo: u [T,D] fp32 -> ut [D,T] (batched via z)
__global__ void tscale_kernel(const float* __restrict__ u, const float* __restrict__ lr,
                              __half* __restrict__ ut, __half* __restrict__ utl) {
    __shared__ float tile[32][33];
    long long z = blockIdx.z;
    u += z * (long long)TT * DD;
    ut += z * (long long)TT * DD;
    utl += z * (long long)TT * DD;
    lr += z * TT;
    int r0 = blockIdx.y * 32, c0 = blockIdx.x * 32;
    int tx = threadIdx.x, ty = threadIdx.y;  // 32 x 8
#pragma unroll
    for (int i = 0; i < 32; i += 8)
        tile[ty + i][tx] = u[(size_t)(r0 + ty + i) * DD + c0 + tx] * lr[r0 + ty + i];
    __syncthreads();
#pragma unroll
    for (int i = 0; i < 32; i += 8) {
        int c = c0 + ty + i, r = r0 + tx;
        float v = tile[tx][ty + i];
        __half hv = __float2half_rn(v);
        ut[(size_t)c * TT + r] = hv;
        utl[(size_t)c * TT + r] = __float2half_rn(v - __half2float(hv));
    }
}

// fp32 -> fp16 elementwise (for E hi)
__global__ void conv_kernel(const float* __restrict__ in, __half* __restrict__ out, long long n) {
    long long i = ((long long)blockIdx.x * blockDim.x + threadIdx.x) * 4;
    if (i >= n) return;
    float4 v = *(const float4*)(in + i);
    union { __half2 h2[2]; uint2 u; } pk;
    pk.h2[0] = __floats2half2_rn(v.x, v.y);
    pk.h2[1] = __floats2half2_rn(v.z, v.w);
    *(uint2*)(out + i) = pk.u;
}

// transpose + fp16 hi/lo: in [R,C] fp32 -> out [C,R] (batched via z)
__global__ void tsplit_kernel(const float* __restrict__ in, __half* __restrict__ oh,
                              __half* __restrict__ ol, int R, int C,
                              long long sIn, long long sOut) {
    __shared__ float tile[32][33];
    long long z = blockIdx.z;
    in += z * sIn; oh += z * sOut; ol += z * sOut;
    int r0 = blockIdx.y * 32, c0 = blockIdx.x * 32;
    int tx = threadIdx.x, ty = threadIdx.y;
#pragma unroll
    for (int i = 0; i < 32; i += 8)
        tile[ty + i][tx] = in[(size_t)(r0 + ty + i) * C + c0 + tx];
    __syncthreads();
#pragma unroll
    for (int i = 0; i < 32; i += 8) {
        int c = c0 + ty + i, r = r0 + tx;
        float v = tile[tx][ty + i];
        __half hv = __float2half_rn(v);
        oh[(size_t)c * R + r] = hv;
        ol[(size_t)c * R + r] = __float2half_rn(v - __half2float(hv));
    }
}

// ============ mma.sync fp16(x2-split) NT GEMM, BK=64 both paths ============
// C = A@B^T; split: 3 MMAs/k16 (Ah*Bh + Ah*Bl + Al*Bh); single: 1 MMA/k16 on hi.
// CTA 128x128, 256 thr = 8 warps (4m x 2n), warp tile 32x64. BK=64 per chunk.
// split stage: 8 tiles [AhK0,AlK0,BhK0,BlK0, AhK1,AlK1,BhK1,BlK1] = 81920B; 2 stages = 163840B (1 CTA/SM).
// single stage: 4 tiles [A_K0, A_K1, B_K0, B_K1] = 40960B; 2 stages = 81920B (2 CTAs/SM).
// MMA issue sequence over k16 blocks identical to the BK=32 version => bit-exact results.
// flags: 1=relu 2=strict-lower-mask 4=bias 8=resid 16=split
#define TILE_B 10240
#define SS_SINGLE 40960
#define SS_SPLIT 81920
#define TG_DYN_SINGLE 81920
#define TG_DYN_SPLIT 163840

__global__ void __launch_bounds__(256, 2)
hgemm_kernel(const __half* __restrict__ Ah, const __half* __restrict__ Al,
             const __half* __restrict__ Bh, const __half* __restrict__ Bl,
             const float* __restrict__ bias, const float* __restrict__ resid,
             float* __restrict__ C, __half* __restrict__ Ch, __half* __restrict__ Chl,
             int K, int lda, int ldb, int ldc,
             long long sA, long long sB, long long sC, int flags) {
    long long z = blockIdx.z;
    Ah += z * sA; Bh += z * sB;
    Al += z * sA; Bl += z * sB;   // always valid (hi aliased when !split)
    if (C) C += z * sC;
    if (Ch) Ch += z * sC;
    if (Chl) Chl += z * sC;
    if (resid) resid += z * sC;
    int m0 = blockIdx.x * 128, n0 = blockIdx.y * 128;
    if ((flags & 2) && n0 >= m0 + 128) return;
    const bool split = (flags & 16) != 0;

    extern __shared__ char dynsmem[];
    uint32_t sb = smem_to_u32(dynsmem);
    int tid = threadIdx.x, lane = tid & 31, wid = tid >> 5;
    int wm = wid >> 1, wn = wid & 1;

    int ldrow = tid & 127, ldpair = tid >> 7;
    const __half* ph = (ldpair ? Bh : Ah) + (size_t)((ldpair ? n0 : m0) + ldrow) * (ldpair ? ldb : lda);
    const __half* pl = (ldpair ? Bl : Al) + (size_t)((ldpair ? n0 : m0) + ldrow) * (ldpair ? ldb : lda);
    uint32_t dsth = sb + ldpair * 2 * TILE_B + ldrow * 80;
    uint32_t dstl = dsth + TILE_B;

    const int nch = K >> 6;  // BK = 64 both paths
    const uint32_t SS = split ? SS_SPLIT : SS_SINGLE;

#define ISSUE_STAGE(cc) do {                                                  \
        uint32_t _so = ((cc) & 1) * SS;                                       \
        const __half* _q = ph + ((size_t)(cc) << 6);                          \
        CP_ASYNC16(dsth + _so, _q);           CP_ASYNC16(dsth + _so + 16, _q + 8);  \
        CP_ASYNC16(dsth + _so + 32, _q + 16); CP_ASYNC16(dsth + _so + 48, _q + 24); \
        if (split) {                                                          \
            const __half* _ql = pl + ((size_t)(cc) << 6);                     \
            CP_ASYNC16(dstl + _so, _ql);           CP_ASYNC16(dstl + _so + 16, _ql + 8);  \
            CP_ASYNC16(dstl + _so + 32, _ql + 16); CP_ASYNC16(dstl + _so + 48, _ql + 24); \
            uint32_t _k1 = _so + 4 * TILE_B;                                  \
            CP_ASYNC16(dsth + _k1, _q + 32);      CP_ASYNC16(dsth + _k1 + 16, _q + 40); \
            CP_ASYNC16(dsth + _k1 + 32, _q + 48); CP_ASYNC16(dsth + _k1 + 48, _q + 56); \
            CP_ASYNC16(dstl + _k1, _ql + 32);      CP_ASYNC16(dstl + _k1 + 16, _ql + 40); \
            CP_ASYNC16(dstl + _k1 + 32, _ql + 48); CP_ASYNC16(dstl + _k1 + 48, _ql + 56); \
        } else {                                                              \
            CP_ASYNC16(dstl + _so, _q + 32);      CP_ASYNC16(dstl + _so + 16, _q + 40); \
            CP_ASYNC16(dstl + _so + 32, _q + 48); CP_ASYNC16(dstl + _so + 48, _q + 56); \
        }                                                                     \
        CP_ASYNC_COMMIT();                                                    \
    } while (0)

    ISSUE_STAGE(0);

    float acc[2][8][4];
#pragma unroll
    for (int i = 0; i < 2; ++i)
#pragma unroll
        for (int j = 0; j < 8; ++j)
#pragma unroll
            for (int r = 0; r < 4; ++r) acc[i][j][r] = 0.0f;

    uint32_t a_off = (lane & 15) * 80 + (lane >> 4) * 16;
    uint32_t b_off = ((lane & 7) + ((lane >> 4) & 1) * 8) * 80 + ((lane >> 3) & 1) * 16;

    for (int c = 0; c < nch; ++c) {
        if (c + 1 < nch) {
            ISSUE_STAGE(c + 1);
            CP_ASYNC_WAIT(1);
        } else {
            CP_ASYNC_WAIT(0);
        }
        __syncthreads();

        uint32_t st = sb + (c & 1) * SS;
        uint32_t aBase = st + (wm * 32) * 80 + a_off;
        uint32_t alBase = aBase + TILE_B;
        uint32_t bBase = st + 2 * TILE_B + (wn * 64) * 80 + b_off;
        uint32_t blBase = bBase + TILE_B;

        if (split) {
            // 4 k16 steps: kk 0,1 in K0 tile group (+0), kk 2,3 in K1 group (+4*TILE_B)
#pragma unroll
            for (int kk = 0; kk < 4; ++kk) {
                uint32_t add = (kk >> 1) * (4 * TILE_B);
                uint32_t kof = (kk & 1) * 32;
                uint32_t af[2][4], alf[2][4];
#pragma unroll
                for (int i = 0; i < 2; ++i) {
                    ldmx4(af[i], aBase + add + i * 1280 + kof);
                    ldmx4(alf[i], alBase + add + i * 1280 + kof);
                }
#pragma unroll
                for (int jj = 0; jj < 4; ++jj) {
                    uint32_t rb[4], rbl[4];
                    ldmx4(rb, bBase + add + jj * 1280 + kof);
                    ldmx4(rbl, blBase + add + jj * 1280 + kof);
#pragma unroll
                    for (int h = 0; h < 2; ++h) {
                        int j = 2 * jj + h;
                        uint32_t bf[2] = {rb[2 * h], rb[2 * h + 1]};
                        uint32_t blf[2] = {rbl[2 * h], rbl[2 * h + 1]};
#pragma unroll
                        for (int i = 0; i < 2; ++i) {
                            mma16816(acc[i][j], af[i], bf);
                            mma16816(acc[i][j], af[i], blf);
                            mma16816(acc[i][j], alf[i], bf);
                        }
                    }
                }
            }
        } else {
            // BK=64 single: hi tile holds k0..31, lo-slot tile holds k32..63
#pragma unroll
            for (int kk = 0; kk < 4; ++kk) {
                uint32_t ab = (kk < 2 ? aBase : alBase) + (kk & 1) * 32;
                uint32_t bb = (kk < 2 ? bBase : blBase) + (kk & 1) * 32;
                uint32_t af[2][4];
                ldmx4(af[0], ab);
                ldmx4(af[1], ab + 1280);
#pragma unroll
                for (int jj = 0; jj < 4; ++jj) {
                    uint32_t rb[4];
                    ldmx4(rb, bb + jj * 1280);
#pragma unroll
                    for (int h = 0; h < 2; ++h) {
                        int j = 2 * jj + h;
                        uint32_t bf[2] = {rb[2 * h], rb[2 * h + 1]};
#pragma unroll
                        for (int i = 0; i < 2; ++i) mma16816(acc[i][j], af[i], bf);
                    }
                }
            }
        }
        __syncthreads();
    }

    // epilogue
    int rbase = m0 + wm * 32 + (lane >> 2);
    int cbase = n0 + wn * 64 + (lane & 3) * 2;
#pragma unroll
    for (int i = 0; i < 2; ++i) {
        int r = rbase + i * 16;
#pragma unroll
        for (int j = 0; j < 8; ++j) {
            int cc = cbase + j * 8;
            float2 lo = make_float2(acc[i][j][0], acc[i][j][1]);
            float2 hi = make_float2(acc[i][j][2], acc[i][j][3]);
            if (flags & 4) {
                float2 bv = *(const float2*)(bias + cc);
                lo.x += bv.x; lo.y += bv.y; hi.x += bv.x; hi.y += bv.y;
            }
            if (flags & 8) {
                float2 r0 = *(const float2*)(resid + (long long)r * ldc + cc);
                float2 r1 = *(const float2*)(resid + (long long)(r + 8) * ldc + cc);
                lo.x += r0.x; lo.y += r0.y; hi.x += r1.x; hi.y += r1.y;
            }
            if (flags & 1) {
                lo.x = fmaxf(lo.x, 0.f); lo.y = fmaxf(lo.y, 0.f);
                hi.x = fmaxf(hi.x, 0.f); hi.y = fmaxf(hi.y, 0.f);
            }
            if (flags & 2) {
                if (cc + 0 >= r) lo.x = 0.f;
                if (cc + 1 >= r) lo.y = 0.f;
                if (cc + 0 >= r + 8) hi.x = 0.f;
                if (cc + 1 >= r + 8) hi.y = 0.f;
            }
            if (Ch) {
                __half2 hlo = __floats2half2_rn(lo.x, lo.y);
                __half2 hhi = __floats2half2_rn(hi.x, hi.y);
                *(__half2*)(Ch + (long long)r * ldc + cc) = hlo;
                *(__half2*)(Ch + (long long)(r + 8) * ldc + cc) = hhi;
                if (Chl) {
                    *(__half2*)(Chl + (long long)r * ldc + cc) =
                        __floats2half2_rn(lo.x - __half2float(hlo.x), lo.y - __half2float(hlo.y));
                    *(__half2*)(Chl + (long long)(r + 8) * ldc + cc) =
                        __floats2half2_rn(hi.x - __half2float(hhi.x), hi.y - __half2float(hhi.y));
                }
            } else {
                *(float2*)(C + (long long)r * ldc + cc) = lo;
                *(float2*)(C + (long long)(r + 8) * ldc + cc) = hi;
            }
        }
    }
#undef ISSUE_STAGE
}

// ===================== fused 128-row panel forward substitution =====================
__global__ void chunksolve2_kernel(float* __restrict__ u, const float* __restrict__ KK, int ci) {
    __shared__ float Ks[64][64];
    __shared__ float Ks2[64][64];
    __shared__ float Ksn[64][64];
    int batch = blockIdx.y;
    int d = blockIdx.x * 256 + threadIdx.x;
    const float* KKb = KK + (size_t)batch * TT * TT;
    float* ub = u + (size_t)batch * TT * DD;
    int base = ci * 128;
    for (int i = threadIdx.x; i < 64 * 64; i += 256) {
        int r = i >> 6, c = i & 63;
        Ks[r][c]  = KKb[(size_t)(base + r) * TT + base + c];
        Ks2[r][c] = KKb[(size_t)(base + 64 + r) * TT + base + c];
        Ksn[r][c] = KKb[(size_t)(base + 64 + r) * TT + base + 64 + c];
    }
    __syncthreads();
    float uloc[64];
#pragma unroll
    for (int r = 0; r < 64; ++r) {
        float val = ub[(size_t)(base + r) * DD + d];
#pragma unroll
        for (int s = 0; s < r; ++s) val -= Ks[r][s] * uloc[s];
        uloc[r] = val;
        ub[(size_t)(base + r) * DD + d] = val;
    }
#pragma unroll 4
    for (int r = 0; r < 64; ++r) {
        float val = ub[(size_t)(base + 64 + r) * DD + d];
#pragma unroll
        for (int s = 0; s < 64; ++s) val -= Ks2[r][s] * uloc[s];
        ub[(size_t)(base + 64 + r) * DD + d] = val;
    }
#pragma unroll
    for (int r = 0; r < 64; ++r) {
        float val = ub[(size_t)(base + 64 + r) * DD + d];
#pragma unroll
        for (int s = 0; s < r; ++s) val -= Ksn[r][s] * uloc[s];
        uloc[r] = val;
        ub[(size_t)(base + 64 + r) * DD + d] = val;
    }
}

// ===================== SIMT SGEMM (solve trailing updates): C -= A@B =====================
__global__ void sgemm_upd_kernel(const float* __restrict__ A, const float* __restrict__ B,
                                 float* __restrict__ C, int M, int N, int K,
                                 int lda, int ldb, int ldc,
                                 long long sA, long long sB, long long sC) {
    long long z = blockIdx.z;
    A += z * sA; B += z * sB; C += z * sC;
    int m0 = blockIdx.y * 128, n0 = blockIdx.x * 128;
    __shared__ float As[8][128];
    __shared__ float Bs[8][128];
    int tid = threadIdx.x;
    int tx = tid & 15, ty = tid >> 4;
    int ar = tid >> 1, ac = (tid & 1) * 4;
    int br = tid >> 5, bc = (tid & 31) * 4;
    float acc[8][8];
#pragma unroll
    for (int i = 0; i < 8; ++i)
#pragma unroll
        for (int j = 0; j < 8; ++j) acc[i][j] = 0.0f;
    for (int k0 = 0; k0 < K; k0 += 8) {
        float4 av = make_float4(0.f, 0.f, 0.f, 0.f);
        if (m0 + ar < M) av = *(const float4*)(A + (long long)(m0 + ar) * lda + k0 + ac);
        As[ac + 0][ar] = av.x; As[ac + 1][ar] = av.y;
        As[ac + 2][ar] = av.z; As[ac + 3][ar] = av.w;
        float4 bv = *(const float4*)(B + (long long)(k0 + br) * ldb + n0 + bc);
        *(float4*)&Bs[br][bc] = bv;
        __syncthreads();
#pragma unroll
        for (int k = 0; k < 8; ++k) {
            float ra[8], rb[8];
            *(float4*)&ra[0] = *(float4*)&As[k][ty * 8];
            *(float4*)&ra[4] = *(float4*)&As[k][ty * 8 + 4];
            *(float4*)&rb[0] = *(float4*)&Bs[k][tx * 8];
            *(float4*)&rb[4] = *(float4*)&Bs[k][tx * 8 + 4];
#pragma unroll
            for (int i = 0; i < 8; ++i)
#pragma unroll
                for (int j = 0; j < 8; ++j) acc[i][j] += ra[i] * rb[j];
        }
        __syncthreads();
    }
#pragma unroll
    for (int i = 0; i < 8; ++i) {
        int r = m0 + ty * 8 + i;
        if (r >= M) continue;
#pragma unroll
        for (int j = 0; j < 8; ++j) {
            int c = n0 + tx * 8 + j;
            C[(long long)r * ldc + c] -= acc[i][j];
        }
    }
}

// ===================== host launcher =====================
static void launch_hgemm(int flags, const __half* Ah, const __half* Al,
                         const __half* Bh, const __half* Bl,
                         const float* bias, const float* resid,
                         float* C, __half* Ch, __half* Chl,
                         int M, int N, int K, int lda, int ldb, int ldc,
                         long long sA, long long sB, long long sC, int batch) {
    dim3 grid(M / 128, N / 128, batch);  // x = M tiles (L2 reuse of A)
    int dyn = (flags & 16) ? TG_DYN_SPLIT : TG_DYN_SINGLE;
    hgemm_kernel<<<grid, 256, dyn>>>(Ah, Al, Bh, Bl, bias, resid, C, Ch, Chl,
                                     K, lda, ldb, ldc, sA, sB, sC, flags);
}

extern "C" void kernel_launch(void* const* d_in, const int* in_sizes, int n_in,
                              void* d_out, int out_size) {
    const int* ids = (const int*)d_in[0];
    const float* E = (const float*)d_in[1];
    const float* Wg = (const float*)d_in[2];
    const float* bg = (const float*)d_in[3];
    const float* Wlr = (const float*)d_in[4];
    const float* blr = (const float*)d_in[5];
    const float* Wo = (const float*)d_in[6];
    const float* bo = (const float*)d_in[7];
    const float* g_d = (const float*)d_in[8];
    const float* b_d = (const float*)d_in[9];
    const float* W1 = (const float*)d_in[10];
    const float* b1 = (const float*)d_in[11];
    const float* W2 = (const float*)d_in[12];
    const float* b2 = (const float*)d_in[13];
    const float* g_m = (const float*)d_in[14];
    const float* b_m = (const float*)d_in[15];
    const float* g_o = (const float*)d_in[16];
    const float* b_o = (const float*)d_in[17];
    float* out = (float*)d_out;

    cudaFuncSetAttribute(hgemm_kernel, cudaFuncAttributeMaxDynamicSharedMemorySize, TG_DYN_SPLIT);

    float *x, *qkv, *lr, *KK, *u;
    cudaGetSymbolAddress((void**)&x, g_x);
    cudaGetSymbolAddress((void**)&qkv, g_qkv);
    cudaGetSymbolAddress((void**)&lr, g_lr);
    cudaGetSymbolAddress((void**)&KK, g_KK);
    cudaGetSymbolAddress((void**)&u, g_u);
    __half *Eh, *WgT, *WgTl, *WoT, *W1T, *W2T;
    __half *hh, *hhl, *qh, *qhl, *kh, *khl, *ut, *utl, *sh, *shl, *yh, *ah;
    cudaGetSymbolAddress((void**)&Eh, g_Eh);
    cudaGetSymbolAddress((void**)&WgT, g_WgT); cudaGetSymbolAddress((void**)&WgTl, g_WgTl);
    cudaGetSymbolAddress((void**)&WoT, g_WoT);
    cudaGetSymbolAddress((void**)&W1T, g_W1T);
    cudaGetSymbolAddress((void**)&W2T, g_W2T);
    cudaGetSymbolAddress((void**)&hh, g_hh);   cudaGetSymbolAddress((void**)&hhl, g_hhl);
    cudaGetSymbolAddress((void**)&qh, g_qh);   cudaGetSymbolAddress((void**)&qhl, g_qhl);
    cudaGetSymbolAddress((void**)&kh, g_kh);   cudaGetSymbolAddress((void**)&khl, g_khl);
    cudaGetSymbolAddress((void**)&ut, g_ut);   cudaGetSymbolAddress((void**)&utl, g_utl);
    cudaGetSymbolAddress((void**)&sh, g_sh);   cudaGetSymbolAddress((void**)&shl, g_shl);
    cudaGetSymbolAddress((void**)&yh, g_yh);
    cudaGetSymbolAddress((void**)&ah, g_ah);

    const long long sTT = (long long)TT * TT;
    const long long sTD = (long long)TT * DD;
    const int SPLIT = 16;

    // ---- prepass: convert E (hi); transpose+split Wg; transpose-convert Wo/W1/W2 (hi only) ----
    {
        long long nE = (long long)VV * DD;
        conv_kernel<<<(int)((nE / 4 + 255) / 256), 256>>>(E, Eh, nE);
        dim3 tb(32, 8);
        tsplit_kernel<<<dim3(3 * DD / 32, DD / 32, LL), tb>>>(Wg, WgT, WgTl, DD, 3 * DD,
                                                              (long long)DD * 3 * DD, (long long)DD * 3 * DD);
        __half *WoTl, *W1Tl, *W2Tl;
        cudaGetSymbolAddress((void**)&WoTl, g_WoTl);
        cudaGetSymbolAddress((void**)&W1Tl, g_W1Tl);
        cudaGetSymbolAddress((void**)&W2Tl, g_W2Tl);
        tsplit_kernel<<<dim3(DD / 32, DD / 32, LL), tb>>>(Wo, WoT, WoTl, DD, DD,
                                                          (long long)DD * DD, (long long)DD * DD);
        tsplit_kernel<<<dim3(DD / 32, DD / 32, LL), tb>>>(W1, W1T, W1Tl, DD, DD,
                                                          (long long)DD * DD, (long long)DD * DD);
        tsplit_kernel<<<dim3(DD / 32, DD / 32, LL), tb>>>(W2, W2T, W2Tl, DD, DD,
                                                          (long long)DD * DD, (long long)DD * DD);
    }

    embed_kernel<<<MTOT, 256>>>(x, E, ids);

    for (int l = 0; l < LL; ++l) {
        const __half* WgT_l = WgT + (size_t)l * 3 * DD * DD;
        const __half* WgTl_l = WgTl + (size_t)l * 3 * DD * DD;
        const __half* WoT_l = WoT + (size_t)l * DD * DD;
        const __half* W1T_l = W1T + (size_t)l * DD * DD;
        const __half* W2T_l = W2T + (size_t)l * DD * DD;

        // --- delta block (split precision: feeds the solve) ---
        ln_kernel<<<MTOT, 256>>>(hh, hhl, x, g_d + (size_t)l * DD, b_d + (size_t)l * DD,
                                 Wlr + (size_t)l * DD, blr + l, lr);
        launch_hgemm(SPLIT | 4, hh, hhl, WgT_l, WgTl_l, bg + (size_t)l * 3 * DD, nullptr,
                     qkv, nullptr, nullptr, MTOT, 3 * DD, DD, DD, DD, 3 * DD, 0, 0, 0, 1);
        knorm_kernel<<<MTOT, 256>>>(qkv, qh, qhl, kh, khl, u);
        launch_hgemm(SPLIT | 2, kh, khl, kh, khl, nullptr, nullptr,
                     KK, nullptr, nullptr, TT, TT, DD, DD, DD, TT, sTD, sTD, sTT, NB);
        for (int ci = 0; ci < 8; ++ci) {
            chunksolve2_kernel<<<dim3(DD / 256, NB), 256>>>(u, KK, ci);
            if (ci < 7) {
                int r0 = 128 * (ci + 1);
                int Mu = TT - r0;
                sgemm_upd_kernel<<<dim3(DD / 128, (Mu + 127) / 128, NB), 256>>>(
                    KK + (size_t)r0 * TT + ci * 128, u + (size_t)ci * 128 * DD,
                    u + (size_t)r0 * DD, Mu, DD, 128, TT, DD, DD, sTT, sTD, sTD);
            }
        }
        {
            dim3 tb(32, 8);
            tscale_kernel<<<dim3(DD / 32, TT / 32, NB), tb>>>(u, lr, ut, utl);
        }
        launch_hgemm(SPLIT, qh, qhl, kh, khl, nullptr, nullptr,
                     nullptr, sh, shl, TT, TT, DD, DD, DD, TT, sTD, sTD, sTT, NB);
        // y: split inputs, only hi output needed (Wo is single-pass)
        launch_hgemm(SPLIT, sh, shl, ut, utl, nullptr, nullptr,
                     nullptr, yh, nullptr, TT, DD, TT, TT, TT, DD, sTT, sTD, sTD, NB);
        // x = x + y @ Wo + bo — SINGLE-PASS, BK=64
        launch_hgemm(4 | 8, yh, yh, WoT_l, WoT_l, bo + (size_t)l * DD, x,
                     x, nullptr, nullptr, MTOT, DD, DD, DD, DD, DD, 0, 0, 0, 1);

        // --- MLP block — SINGLE-PASS GEMMs, BK=64 ---
        ln_kernel<<<MTOT, 256>>>(hh, hhl, x, g_m + (size_t)l * DD, b_m + (size_t)l * DD,
                                 nullptr, nullptr, nullptr);
        launch_hgemm(4 | 1, hh, hh, W1T_l, W1T_l, b1 + (size_t)l * DD, nullptr,
                     nullptr, ah, nullptr, MTOT, DD, DD, DD, DD, DD, 0, 0, 0, 1);
        launch_hgemm(4 | 8, ah, ah, W2T_l, W2T_l, b2 + (size_t)l * DD, x,
                     x, nullptr, nullptr, MTOT, DD, DD, DD, DD, DD, 0, 0, 0, 1);
    }

    // final LN + tied decoder: single-pass fp16 logits, BK=64
    ln_kernel<<<MTOT, 256>>>(hh, hhl, x, g_o, b_o, nullptr, nullptr, nullptr);
    launch_hgemm(0, hh, hh, Eh, Eh, nullptr, nullptr,
                 out, nullptr, nullptr, MTOT, VV, DD, DD, DD, VV, 0, 0, 0, 1);
}

// round 16
// speedup vs baseline: 2.4315x; 1.0125x over previous
#include <cuda_runtime.h>
#include <cuda_fp16.h>
#include <cstdint>

// Problem constants
#define NB 4          // batch
#define TT 1024       // seq len
#define DD 1024       // dim
#define LL 4          // layers
#define VV 32000      // vocab
#define MTOT (NB*TT)  // 4096 rows

// ===================== PTX helpers (base ISA only) =====================
__device__ __forceinline__ uint32_t smem_to_u32(const void* p) {
    uint32_t a;
    asm("{ .reg .u64 t; cvta.to.shared.u64 t, %1; cvt.u32.u64 %0, t; }" : "=r"(a) : "l"(p));
    return a;
}
#define CP_ASYNC16(dst, src) \
    asm volatile("cp.async.cg.shared.global [%0], [%1], 16;" :: "r"((uint32_t)(dst)), "l"(src))
#define CP_ASYNC_COMMIT() asm volatile("cp.async.commit_group;" ::: "memory")
#define CP_ASYNC_WAIT(n) asm volatile("cp.async.wait_group %0;" :: "n"(n) : "memory")

__device__ __forceinline__ void ldmx4(uint32_t* r, uint32_t addr) {
    asm volatile("ldmatrix.sync.aligned.m8n8.x4.shared.b16 {%0,%1,%2,%3}, [%4];"
                 : "=r"(r[0]), "=r"(r[1]), "=r"(r[2]), "=r"(r[3]) : "r"(addr));
}
__device__ __forceinline__ void mma16816(float* c, const uint32_t* a, const uint32_t* b) {
    asm volatile(
        "mma.sync.aligned.m16n8k16.row.col.f32.f16.f16.f32 "
        "{%0,%1,%2,%3}, {%4,%5,%6,%7}, {%8,%9}, {%0,%1,%2,%3};"
        : "+f"(c[0]), "+f"(c[1]), "+f"(c[2]), "+f"(c[3])
        : "r"(a[0]), "r"(a[1]), "r"(a[2]), "r"(a[3]), "r"(b[0]), "r"(b[1]));
}

// ===================== scratch (device globals) =====================
__device__ float g_x[MTOT * DD];
__device__ float g_qkv[MTOT * 3 * DD];
__device__ float g_lr[MTOT];
__device__ float g_KK[NB * TT * TT];
__device__ float g_u[MTOT * DD];
__device__ __half g_Eh[VV * DD], g_El[VV * DD];  // g_El unused (image parity)
__device__ __half g_WgT[LL * 3 * DD * DD], g_WgTl[LL * 3 * DD * DD];
__device__ __half g_WoT[LL * DD * DD], g_WoTl[LL * DD * DD];
__device__ __half g_W1T[LL * DD * DD], g_W1Tl[LL * DD * DD];
__device__ __half g_W2T[LL * DD * DD], g_W2Tl[LL * DD * DD];
__device__ __half g_hh[MTOT * DD], g_hhl[MTOT * DD];
__device__ __half g_qh[MTOT * DD], g_qhl[MTOT * DD];
__device__ __half g_kh[MTOT * DD], g_khl[MTOT * DD];
__device__ __half g_ut[MTOT * DD], g_utl[MTOT * DD];
__device__ __half g_sh[NB * TT * TT], g_shl[NB * TT * TT];
__device__ __half g_yh[MTOT * DD], g_yhl[MTOT * DD];
__device__ __half g_ah[MTOT * DD], g_ahl[MTOT * DD];

// ===================== small kernels =====================
__device__ __forceinline__ float blockReduceSum(float v, float* sdata) {
    int tid = threadIdx.x;
    sdata[tid] = v;
    __syncthreads();
    for (int s = 128; s > 0; s >>= 1) {
        if (tid < s) sdata[tid] += sdata[tid + s];
        __syncthreads();
    }
    float r = sdata[0];
    __syncthreads();
    return r;
}

__device__ __forceinline__ void store_h4_pair(__half* ph, __half* pl,
                                              float a, float b, float c, float d) {
    union { __half2 h2[2]; uint2 u; } hi, lo;
    hi.h2[0] = __floats2half2_rn(a, b);
    hi.h2[1] = __floats2half2_rn(c, d);
    lo.h2[0] = __floats2half2_rn(a - __half2float(hi.h2[0].x), b - __half2float(hi.h2[0].y));
    lo.h2[1] = __floats2half2_rn(c - __half2float(hi.h2[1].x), d - __half2float(hi.h2[1].y));
    *(uint2*)ph = hi.u;
    *(uint2*)pl = lo.u;
}

__global__ void embed_kernel(float* __restrict__ x, const float* __restrict__ E,
                             const int* __restrict__ ids) {
    int m = blockIdx.x;
    int id = ids[m];
    const float4* src = (const float4*)(E + (size_t)id * DD);
    float4* dst = (float4*)(x + (size_t)m * DD);
    dst[threadIdx.x] = src[threadIdx.x];
}

__global__ void ln_kernel(__half* __restrict__ oh, __half* __restrict__ ol,
                          const float* __restrict__ in,
                          const float* __restrict__ g, const float* __restrict__ b,
                          const float* __restrict__ Wlr, const float* __restrict__ blr,
                          float* __restrict__ lr) {
    __shared__ float sdata[256];
    int m = blockIdx.x, tid = threadIdx.x;
    const float* row = in + (size_t)m * DD;
    float4 v = *(const float4*)(row + tid * 4);
    float s = v.x + v.y + v.z + v.w;
    float mean = blockReduceSum(s, sdata) * (1.0f / DD);
    float dx = v.x - mean, dy = v.y - mean, dz = v.z - mean, dw = v.w - mean;
    float s2 = dx * dx + dy * dy + dz * dz + dw * dw;
    float var = blockReduceSum(s2, sdata) * (1.0f / DD);
    float rstd = 1.0f / sqrtf(var + 1e-5f);
    int c = tid * 4;
    float n0 = dx * rstd * g[c + 0] + b[c + 0];
    float n1 = dy * rstd * g[c + 1] + b[c + 1];
    float n2 = dz * rstd * g[c + 2] + b[c + 2];
    float n3 = dw * rstd * g[c + 3] + b[c + 3];
    store_h4_pair(oh + (size_t)m * DD + c, ol + (size_t)m * DD + c, n0, n1, n2, n3);
    if (Wlr) {
        float4 wv = *(const float4*)(Wlr + c);
        float d = n0 * wv.x + n1 * wv.y + n2 * wv.z + n3 * wv.w;
        float dot = blockReduceSum(d, sdata);
        if (tid == 0) lr[m] = dot + blr[0];
    }
}

__global__ void knorm_kernel(const float* __restrict__ qkv,
                             __half* __restrict__ qh, __half* __restrict__ ql,
                             __half* __restrict__ kh, __half* __restrict__ kl,
                             float* __restrict__ u) {
    __shared__ float sdata[256];
    int m = blockIdx.x, tid = threadIdx.x;
    const float* base = qkv + (size_t)m * (3 * DD);
    int c = tid * 4;
    float4 kv = *(const float4*)(base + DD + c);
    float ss = kv.x * kv.x + kv.y * kv.y + kv.z * kv.z + kv.w * kv.w;
    float ksum = blockReduceSum(ss, sdata);
    float scale = 1.0f / sqrtf(ksum);
    size_t o = (size_t)m * DD + c;
    store_h4_pair(kh + o, kl + o, kv.x * scale, kv.y * scale, kv.z * scale, kv.w * scale);
    float4 qv = *(const float4*)(base + c);
    store_h4_pair(qh + o, ql + o, qv.x, qv.y, qv.z, qv.w);
    *(float4*)(u + o) = *(const float4*)(base + 2 * DD + c);
}

// transpose + lr-scale + fp16 hi/lo: u [T,D] fp32 -> ut [D,T] (batched via z)
__global__ void tscale_kernel(const float* __restrict__ u, const float* __restrict__ lr,
                              __half* __restrict__ ut, __half* __restrict__ utl) {
    __shared__ float tile[32][33];
    long long z = blockIdx.z;
    u += z * (long long)TT * DD;
    ut += z * (long long)TT * DD;
    utl += z * (long long)TT * DD;
    lr += z * TT;
    int r0 = blockIdx.y * 32, c0 = blockIdx.x * 32;
    int tx = threadIdx.x, ty = threadIdx.y;  // 32 x 8
#pragma unroll
    for (int i = 0; i < 32; i += 8)
        tile[ty + i][tx] = u[(size_t)(r0 + ty + i) * DD + c0 + tx] * lr[r0 + ty + i];
    __syncthreads();
#pragma unroll
    for (int i = 0; i < 32; i += 8) {
        int c = c0 + ty + i, r = r0 + tx;
        float v = tile[tx][ty + i];
        __half hv = __float2half_rn(v);
        ut[(size_t)c * TT + r] = hv;
        utl[(size_t)c * TT + r] = __float2half_rn(v - __half2float(hv));
    }
}

// fp32 -> fp16 elementwise (for E hi)
__global__ void conv_kernel(const float* __restrict__ in, __half* __restrict__ out, long long n) {
    long long i = ((long long)blockIdx.x * blockDim.x + threadIdx.x) * 4;
    if (i >= n) return;
    float4 v = *(const float4*)(in + i);
    union { __half2 h2[2]; uint2 u; } pk;
    pk.h2[0] = __floats2half2_rn(v.x, v.y);
    pk.h2[1] = __floats2half2_rn(v.z, v.w);
    *(uint2*)(out + i) = pk.u;
}

// transpose + fp16 hi/lo: in [R,C] fp32 -> out [C,R] (batched via z)
__global__ void tsplit_kernel(const float* __restrict__ in, __half* __restrict__ oh,
                              __half* __restrict__ ol, int R, int C,
                              long long sIn, long long sOut) {
    __shared__ float tile[32][33];
    long long z = blockIdx.z;
    in += z * sIn; oh += z * sOut; ol += z * sOut;
    int r0 = blockIdx.y * 32, c0 = blockIdx.x * 32;
    int tx = threadIdx.x, ty = threadIdx.y;
#pragma unroll
    for (int i = 0; i < 32; i += 8)
        tile[ty + i][tx] = in[(size_t)(r0 + ty + i) * C + c0 + tx];
    __syncthreads();
#pragma unroll
    for (int i = 0; i < 32; i += 8) {
        int c = c0 + ty + i, r = r0 + tx;
        float v = tile[tx][ty + i];
        __half hv = __float2half_rn(v);
        oh[(size_t)c * R + r] = hv;
        ol[(size_t)c * R + r] = __float2half_rn(v - __half2float(hv));
    }
}

// ============ mma.sync fp16(x2-split) NT GEMM, BK=64 both paths ============
// C = A@B^T; split: 3 MMAs/k16 (Ah*Bh + Ah*Bl + Al*Bh); single: 1 MMA/k16 on hi.
// CTA 128x128, 256 thr = 8 warps (4m x 2n), warp tile 32x64. BK=64 per chunk.
// split stage: 8 tiles = 81920B; 2 stages = 163840B (1 CTA/SM).
// single stage: 4 tiles = 40960B; 2 stages = 81920B (2 CTAs/SM).
// flags: 1=relu 2=strict-lower-mask 4=bias 8=resid 16=split
#define TILE_B 10240
#define SS_SINGLE 40960
#define SS_SPLIT 81920
#define TG_DYN_SINGLE 81920
#define TG_DYN_SPLIT 163840

__global__ void __launch_bounds__(256, 2)
hgemm_kernel(const __half* __restrict__ Ah, const __half* __restrict__ Al,
             const __half* __restrict__ Bh, const __half* __restrict__ Bl,
             const float* __restrict__ bias, const float* __restrict__ resid,
             float* __restrict__ C, __half* __restrict__ Ch, __half* __restrict__ Chl,
             int K, int lda, int ldb, int ldc,
             long long sA, long long sB, long long sC, int flags) {
    long long z = blockIdx.z;
    Ah += z * sA; Bh += z * sB;
    Al += z * sA; Bl += z * sB;   // always valid (hi aliased when !split)
    if (C) C += z * sC;
    if (Ch) Ch += z * sC;
    if (Chl) Chl += z * sC;
    if (resid) resid += z * sC;
    int m0 = blockIdx.x * 128, n0 = blockIdx.y * 128;
    if ((flags & 2) && n0 >= m0 + 128) return;
    const bool split = (flags & 16) != 0;

    extern __shared__ char dynsmem[];
    uint32_t sb = smem_to_u32(dynsmem);
    int tid = threadIdx.x, lane = tid & 31, wid = tid >> 5;
    int wm = wid >> 1, wn = wid & 1;

    int ldrow = tid & 127, ldpair = tid >> 7;
    const __half* ph = (ldpair ? Bh : Ah) + (size_t)((ldpair ? n0 : m0) + ldrow) * (ldpair ? ldb : lda);
    const __half* pl = (ldpair ? Bl : Al) + (size_t)((ldpair ? n0 : m0) + ldrow) * (ldpair ? ldb : lda);
    uint32_t dsth = sb + ldpair * 2 * TILE_B + ldrow * 80;
    uint32_t dstl = dsth + TILE_B;

    const int nch = K >> 6;  // BK = 64 both paths
    const uint32_t SS = split ? SS_SPLIT : SS_SINGLE;

#define ISSUE_STAGE(cc) do {                                                  \
        uint32_t _so = ((cc) & 1) * SS;                                       \
        const __half* _q = ph + ((size_t)(cc) << 6);                          \
        CP_ASYNC16(dsth + _so, _q);           CP_ASYNC16(dsth + _so + 16, _q + 8);  \
        CP_ASYNC16(dsth + _so + 32, _q + 16); CP_ASYNC16(dsth + _so + 48, _q + 24); \
        if (split) {                                                          \
            const __half* _ql = pl + ((size_t)(cc) << 6);                     \
            CP_ASYNC16(dstl + _so, _ql);           CP_ASYNC16(dstl + _so + 16, _ql + 8);  \
            CP_ASYNC16(dstl + _so + 32, _ql + 16); CP_ASYNC16(dstl + _so + 48, _ql + 24); \
            uint32_t _k1 = _so + 4 * TILE_B;                                  \
            CP_ASYNC16(dsth + _k1, _q + 32);      CP_ASYNC16(dsth + _k1 + 16, _q + 40); \
            CP_ASYNC16(dsth + _k1 + 32, _q + 48); CP_ASYNC16(dsth + _k1 + 48, _q + 56); \
            CP_ASYNC16(dstl + _k1, _ql + 32);      CP_ASYNC16(dstl + _k1 + 16, _ql + 40); \
            CP_ASYNC16(dstl + _k1 + 32, _ql + 48); CP_ASYNC16(dstl + _k1 + 48, _ql + 56); \
        } else {                                                              \
            CP_ASYNC16(dstl + _so, _q + 32);      CP_ASYNC16(dstl + _so + 16, _q + 40); \
            CP_ASYNC16(dstl + _so + 32, _q + 48); CP_ASYNC16(dstl + _so + 48, _q + 56); \
        }                                                                     \
        CP_ASYNC_COMMIT();                                                    \
    } while (0)

    ISSUE_STAGE(0);

    float acc[2][8][4];
#pragma unroll
    for (int i = 0; i < 2; ++i)
#pragma unroll
        for (int j = 0; j < 8; ++j)
#pragma unroll
            for (int r = 0; r < 4; ++r) acc[i][j][r] = 0.0f;

    uint32_t a_off = (lane & 15) * 80 + (lane >> 4) * 16;
    uint32_t b_off = ((lane & 7) + ((lane >> 4) & 1) * 8) * 80 + ((lane >> 3) & 1) * 16;

    for (int c = 0; c < nch; ++c) {
        if (c + 1 < nch) {
            ISSUE_STAGE(c + 1);
            CP_ASYNC_WAIT(1);
        } else {
            CP_ASYNC_WAIT(0);
        }
        __syncthreads();

        uint32_t st = sb + (c & 1) * SS;
        uint32_t aBase = st + (wm * 32) * 80 + a_off;
        uint32_t alBase = aBase + TILE_B;
        uint32_t bBase = st + 2 * TILE_B + (wn * 64) * 80 + b_off;
        uint32_t blBase = bBase + TILE_B;

        if (split) {
            // 4 k16 steps: kk 0,1 in K0 tile group (+0), kk 2,3 in K1 group (+4*TILE_B)
#pragma unroll
            for (int kk = 0; kk < 4; ++kk) {
                uint32_t add = (kk >> 1) * (4 * TILE_B);
                uint32_t kof = (kk & 1) * 32;
                uint32_t af[2][4], alf[2][4];
#pragma unroll
                for (int i = 0; i < 2; ++i) {
                    ldmx4(af[i], aBase + add + i * 1280 + kof);
                    ldmx4(alf[i], alBase + add + i * 1280 + kof);
                }
#pragma unroll
                for (int jj = 0; jj < 4; ++jj) {
                    uint32_t rb[4], rbl[4];
                    ldmx4(rb, bBase + add + jj * 1280 + kof);
                    ldmx4(rbl, blBase + add + jj * 1280 + kof);
#pragma unroll
                    for (int h = 0; h < 2; ++h) {
                        int j = 2 * jj + h;
                        uint32_t bf[2] = {rb[2 * h], rb[2 * h + 1]};
                        uint32_t blf[2] = {rbl[2 * h], rbl[2 * h + 1]};
#pragma unroll
                        for (int i = 0; i < 2; ++i) {
                            mma16816(acc[i][j], af[i], bf);
                            mma16816(acc[i][j], af[i], blf);
                            mma16816(acc[i][j], alf[i], bf);
                        }
                    }
                }
            }
        } else {
            // BK=64 single: hi tile holds k0..31, lo-slot tile holds k32..63
#pragma unroll
            for (int kk = 0; kk < 4; ++kk) {
                uint32_t ab = (kk < 2 ? aBase : alBase) + (kk & 1) * 32;
                uint32_t bb = (kk < 2 ? bBase : blBase) + (kk & 1) * 32;
                uint32_t af[2][4];
                ldmx4(af[0], ab);
                ldmx4(af[1], ab + 1280);
#pragma unroll
                for (int jj = 0; jj < 4; ++jj) {
                    uint32_t rb[4];
                    ldmx4(rb, bb + jj * 1280);
#pragma unroll
                    for (int h = 0; h < 2; ++h) {
                        int j = 2 * jj + h;
                        uint32_t bf[2] = {rb[2 * h], rb[2 * h + 1]};
#pragma unroll
                        for (int i = 0; i < 2; ++i) mma16816(acc[i][j], af[i], bf);
                    }
                }
            }
        }
        __syncthreads();
    }

    // epilogue
    int rbase = m0 + wm * 32 + (lane >> 2);
    int cbase = n0 + wn * 64 + (lane & 3) * 2;
#pragma unroll
    for (int i = 0; i < 2; ++i) {
        int r = rbase + i * 16;
#pragma unroll
        for (int j = 0; j < 8; ++j) {
            int cc = cbase + j * 8;
            float2 lo = make_float2(acc[i][j][0], acc[i][j][1]);
            float2 hi = make_float2(acc[i][j][2], acc[i][j][3]);
            if (flags & 4) {
                float2 bv = *(const float2*)(bias + cc);
                lo.x += bv.x; lo.y += bv.y; hi.x += bv.x; hi.y += bv.y;
            }
            if (flags & 8) {
                float2 r0 = *(const float2*)(resid + (long long)r * ldc + cc);
                float2 r1 = *(const float2*)(resid + (long long)(r + 8) * ldc + cc);
                lo.x += r0.x; lo.y += r0.y; hi.x += r1.x; hi.y += r1.y;
            }
            if (flags & 1) {
                lo.x = fmaxf(lo.x, 0.f); lo.y = fmaxf(lo.y, 0.f);
                hi.x = fmaxf(hi.x, 0.f); hi.y = fmaxf(hi.y, 0.f);
            }
            if (flags & 2) {
                if (cc + 0 >= r) lo.x = 0.f;
                if (cc + 1 >= r) lo.y = 0.f;
                if (cc + 0 >= r + 8) hi.x = 0.f;
                if (cc + 1 >= r + 8) hi.y = 0.f;
            }
            if (Ch) {
                __half2 hlo = __floats2half2_rn(lo.x, lo.y);
                __half2 hhi = __floats2half2_rn(hi.x, hi.y);
                *(__half2*)(Ch + (long long)r * ldc + cc) = hlo;
                *(__half2*)(Ch + (long long)(r + 8) * ldc + cc) = hhi;
                if (Chl) {
                    *(__half2*)(Chl + (long long)r * ldc + cc) =
                        __floats2half2_rn(lo.x - __half2float(hlo.x), lo.y - __half2float(hlo.y));
                    *(__half2*)(Chl + (long long)(r + 8) * ldc + cc) =
                        __floats2half2_rn(hi.x - __half2float(hhi.x), hi.y - __half2float(hhi.y));
                }
            } else {
                *(float2*)(C + (long long)r * ldc + cc) = lo;
                *(float2*)(C + (long long)(r + 8) * ldc + cc) = hi;
            }
        }
    }
#undef ISSUE_STAGE
}

// ===================== fused 128-row panel forward substitution (ILP version) =====================
// 4-way partial sums break the serial FMA chain; rows 64..127 stay register-resident
// across phases 2-3 (no gmem round trip). fp32 reassociation drift ~1e-7 relative.
__global__ void __launch_bounds__(256)
chunksolve2_kernel(float* __restrict__ u, const float* __restrict__ KK, int ci) {
    __shared__ float Ks[64][64];
    __shared__ float Ks2[64][64];
    __shared__ float Ksn[64][64];
    int batch = blockIdx.y;
    int d = blockIdx.x * 256 + threadIdx.x;
    const float* KKb = KK + (size_t)batch * TT * TT;
    float* ub = u + (size_t)batch * TT * DD;
    int base = ci * 128;
    for (int i = threadIdx.x; i < 64 * 64; i += 256) {
        int r = i >> 6, c = i & 63;
        Ks[r][c]  = KKb[(size_t)(base + r) * TT + base + c];
        Ks2[r][c] = KKb[(size_t)(base + 64 + r) * TT + base + c];
        Ksn[r][c] = KKb[(size_t)(base + 64 + r) * TT + base + 64 + c];
    }
    __syncthreads();
    float uloc[64];
    // phase 1: solve rows base..base+63
#pragma unroll
    for (int r = 0; r < 64; ++r) {
        float a0 = 0.f, a1 = 0.f, a2 = 0.f, a3 = 0.f;
        int s = 0;
#pragma unroll
        for (; s + 4 <= r; s += 4) {
            a0 += Ks[r][s + 0] * uloc[s + 0];
            a1 += Ks[r][s + 1] * uloc[s + 1];
            a2 += Ks[r][s + 2] * uloc[s + 2];
            a3 += Ks[r][s + 3] * uloc[s + 3];
        }
#pragma unroll
        for (; s < r; ++s) a0 += Ks[r][s] * uloc[s];
        float val = ub[(size_t)(base + r) * DD + d] - ((a0 + a1) + (a2 + a3));
        uloc[r] = val;
        ub[(size_t)(base + r) * DD + d] = val;
    }
    // phase 2: rank-64 off-diag update into registers (u2)
    float u2[64];
#pragma unroll
    for (int r = 0; r < 64; ++r) {
        float a0 = 0.f, a1 = 0.f, a2 = 0.f, a3 = 0.f;
#pragma unroll
        for (int s = 0; s < 64; s += 4) {
            a0 += Ks2[r][s + 0] * uloc[s + 0];
            a1 += Ks2[r][s + 1] * uloc[s + 1];
            a2 += Ks2[r][s + 2] * uloc[s + 2];
            a3 += Ks2[r][s + 3] * uloc[s + 3];
        }
        u2[r] = ub[(size_t)(base + 64 + r) * DD + d] - ((a0 + a1) + (a2 + a3));
    }
    // phase 3: solve rows base+64..base+127 in registers, store once
#pragma unroll
    for (int r = 0; r < 64; ++r) {
        float a0 = 0.f, a1 = 0.f, a2 = 0.f, a3 = 0.f;
        int s = 0;
#pragma unroll
        for (; s + 4 <= r; s += 4) {
            a0 += Ksn[r][s + 0] * u2[s + 0];
            a1 += Ksn[r][s + 1] * u2[s + 1];
            a2 += Ksn[r][s + 2] * u2[s + 2];
            a3 += Ksn[r][s + 3] * u2[s + 3];
        }
#pragma unroll
        for (; s < r; ++s) a0 += Ksn[r][s] * u2[s];
        float val = u2[r] - ((a0 + a1) + (a2 + a3));
        u2[r] = val;
        ub[(size_t)(base + 64 + r) * DD + d] = val;
    }
}

// ===================== SIMT SGEMM (solve trailing updates): C -= A@B =====================
__global__ void sgemm_upd_kernel(const float* __restrict__ A, const float* __restrict__ B,
                                 float* __restrict__ C, int M, int N, int K,
                                 int lda, int ldb, int ldc,
                                 long long sA, long long sB, long long sC) {
    long long z = blockIdx.z;
    A += z * sA; B += z * sB; C += z * sC;
    int m0 = blockIdx.y * 128, n0 = blockIdx.x * 128;
    __shared__ float As[8][128];
    __shared__ float Bs[8][128];
    int tid = threadIdx.x;
    int tx = tid & 15, ty = tid >> 4;
    int ar = tid >> 1, ac = (tid & 1) * 4;
    int br = tid >> 5, bc = (tid & 31) * 4;
    float acc[8][8];
#pragma unroll
    for (int i = 0; i < 8; ++i)
#pragma unroll
        for (int j = 0; j < 8; ++j) acc[i][j] = 0.0f;
    for (int k0 = 0; k0 < K; k0 += 8) {
        float4 av = make_float4(0.f, 0.f, 0.f, 0.f);
        if (m0 + ar < M) av = *(const float4*)(A + (long long)(m0 + ar) * lda + k0 + ac);
        As[ac + 0][ar] = av.x; As[ac + 1][ar] = av.y;
        As[ac + 2][ar] = av.z; As[ac + 3][ar] = av.w;
        float4 bv = *(const float4*)(B + (long long)(k0 + br) * ldb + n0 + bc);
        *(float4*)&Bs[br][bc] = bv;
        __syncthreads();
#pragma unroll
        for (int k = 0; k < 8; ++k) {
            float ra[8], rb[8];
            *(float4*)&ra[0] = *(float4*)&As[k][ty * 8];
            *(float4*)&ra[4] = *(float4*)&As[k][ty * 8 + 4];
            *(float4*)&rb[0] = *(float4*)&Bs[k][tx * 8];
            *(float4*)&rb[4] = *(float4*)&Bs[k][tx * 8 + 4];
#pragma unroll
            for (int i = 0; i < 8; ++i)
#pragma unroll
                for (int j = 0; j < 8; ++j) acc[i][j] += ra[i] * rb[j];
        }
        __syncthreads();
    }
#pragma unroll
    for (int i = 0; i < 8; ++i) {
        int r = m0 + ty * 8 + i;
        if (r >= M) continue;
#pragma unroll
        for (int j = 0; j < 8; ++j) {
            int c = n0 + tx * 8 + j;
            C[(long long)r * ldc + c] -= acc[i][j];
        }
    }
}

// ===================== host launcher =====================
static void launch_hgemm(int flags, const __half* Ah, const __half* Al,
                         const __half* Bh, const __half* Bl,
                         const float* bias, const float* resid,
                         float* C, __half* Ch, __half* Chl,
                         int M, int N, int K, int lda, int ldb, int ldc,
                         long long sA, long long sB, long long sC, int batch) {
    dim3 grid(M / 128, N / 128, batch);  // x = M tiles (L2 reuse of A)
    int dyn = (flags & 16) ? TG_DYN_SPLIT : TG_DYN_SINGLE;
    hgemm_kernel<<<grid, 256, dyn>>>(Ah, Al, Bh, Bl, bias, resid, C, Ch, Chl,
                                     K, lda, ldb, ldc, sA, sB, sC, flags);
}

extern "C" void kernel_launch(void* const* d_in, const int* in_sizes, int n_in,
                              void* d_out, int out_size) {
    const int* ids = (const int*)d_in[0];
    const float* E = (const float*)d_in[1];
    const float* Wg = (const float*)d_in[2];
    const float* bg = (const float*)d_in[3];
    const float* Wlr = (const float*)d_in[4];
    const float* blr = (const float*)d_in[5];
    const float* Wo = (const float*)d_in[6];
    const float* bo = (const float*)d_in[7];
    const float* g_d = (const float*)d_in[8];
    const float* b_d = (const float*)d_in[9];
    const float* W1 = (const float*)d_in[10];
    const float* b1 = (const float*)d_in[11];
    const float* W2 = (const float*)d_in[12];
    const float* b2 = (const float*)d_in[13];
    const float* g_m = (const float*)d_in[14];
    const float* b_m = (const float*)d_in[15];
    const float* g_o = (const float*)d_in[16];
    const float* b_o = (const float*)d_in[17];
    float* out = (float*)d_out;

    cudaFuncSetAttribute(hgemm_kernel, cudaFuncAttributeMaxDynamicSharedMemorySize, TG_DYN_SPLIT);

    float *x, *qkv, *lr, *KK, *u;
    cudaGetSymbolAddress((void**)&x, g_x);
    cudaGetSymbolAddress((void**)&qkv, g_qkv);
    cudaGetSymbolAddress((void**)&lr, g_lr);
    cudaGetSymbolAddress((void**)&KK, g_KK);
    cudaGetSymbolAddress((void**)&u, g_u);
    __half *Eh, *WgT, *WgTl, *WoT, *W1T, *W2T;
    __half *hh, *hhl, *qh, *qhl, *kh, *khl, *ut, *utl, *sh, *shl, *yh, *ah;
    cudaGetSymbolAddress((void**)&Eh, g_Eh);
    cudaGetSymbolAddress((void**)&WgT, g_WgT); cudaGetSymbolAddress((void**)&WgTl, g_WgTl);
    cudaGetSymbolAddress((void**)&WoT, g_WoT);
    cudaGetSymbolAddress((void**)&W1T, g_W1T);
    cudaGetSymbolAddress((void**)&W2T, g_W2T);
    cudaGetSymbolAddress((void**)&hh, g_hh);   cudaGetSymbolAddress((void**)&hhl, g_hhl);
    cudaGetSymbolAddress((void**)&qh, g_qh);   cudaGetSymbolAddress((void**)&qhl, g_qhl);
    cudaGetSymbolAddress((void**)&kh, g_kh);   cudaGetSymbolAddress((void**)&khl, g_khl);
    cudaGetSymbolAddress((void**)&ut, g_ut);   cudaGetSymbolAddress((void**)&utl, g_utl);
    cudaGetSymbolAddress((void**)&sh, g_sh);   cudaGetSymbolAddress((void**)&shl, g_shl);
    cudaGetSymbolAddress((void**)&yh, g_yh);
    cudaGetSymbolAddress((void**)&ah, g_ah);

    const long long sTT = (long long)TT * TT;
    const long long sTD = (long long)TT * DD;
    const int SPLIT = 16;

    // ---- prepass: convert E (hi); transpose+split Wg; transpose-convert Wo/W1/W2 (hi only) ----
    {
        long long nE = (long long)VV * DD;
        conv_kernel<<<(int)((nE / 4 + 255) / 256), 256>>>(E, Eh, nE);
        dim3 tb(32, 8);
        tsplit_kernel<<<dim3(3 * DD / 32, DD / 32, LL), tb>>>(Wg, WgT, WgTl, DD, 3 * DD,
                                                              (long long)DD * 3 * DD, (long long)DD * 3 * DD);
        __half *WoTl, *W1Tl, *W2Tl;
        cudaGetSymbolAddress((void**)&WoTl, g_WoTl);
        cudaGetSymbolAddress((void**)&W1Tl, g_W1Tl);
        cudaGetSymbolAddress((void**)&W2Tl, g_W2Tl);
        tsplit_kernel<<<dim3(DD / 32, DD / 32, LL), tb>>>(Wo, WoT, WoTl, DD, DD,
                                                          (long long)DD * DD, (long long)DD * DD);
        tsplit_kernel<<<dim3(DD / 32, DD / 32, LL), tb>>>(W1, W1T, W1Tl, DD, DD,
                                                          (long long)DD * DD, (long long)DD * DD);
        tsplit_kernel<<<dim3(DD / 32, DD / 32, LL), tb>>>(W2, W2T, W2Tl, DD, DD,
                                                          (long long)DD * DD, (long long)DD * DD);
    }

    embed_kernel<<<MTOT, 256>>>(x, E, ids);

    for (int l = 0; l < LL; ++l) {
        const __half* WgT_l = WgT + (size_t)l * 3 * DD * DD;
        const __half* WgTl_l = WgTl + (size_t)l * 3 * DD * DD;
        const __half* WoT_l = WoT + (size_t)l * DD * DD;
        const __half* W1T_l = W1T + (size_t)l * DD * DD;
        const __half* W2T_l = W2T + (size_t)l * DD * DD;

        // --- delta block (split precision: feeds the solve) ---
        ln_kernel<<<MTOT, 256>>>(hh, hhl, x, g_d + (size_t)l * DD, b_d + (size_t)l * DD,
                                 Wlr + (size_t)l * DD, blr + l, lr);
        launch_hgemm(SPLIT | 4, hh, hhl, WgT_l, WgTl_l, bg + (size_t)l * 3 * DD, nullptr,
                     qkv, nullptr, nullptr, MTOT, 3 * DD, DD, DD, DD, 3 * DD, 0, 0, 0, 1);
        knorm_kernel<<<MTOT, 256>>>(qkv, qh, qhl, kh, khl, u);
        launch_hgemm(SPLIT | 2, kh, khl, kh, khl, nullptr, nullptr,
                     KK, nullptr, nullptr, TT, TT, DD, DD, DD, TT, sTD, sTD, sTT, NB);
        for (int ci = 0; ci < 8; ++ci) {
            chunksolve2_kernel<<<dim3(DD / 256, NB), 256>>>(u, KK, ci);
            if (ci < 7) {
                int r0 = 128 * (ci + 1);
                int Mu = TT - r0;
                sgemm_upd_kernel<<<dim3(DD / 128, (Mu + 127) / 128, NB), 256>>>(
                    KK + (size_t)r0 * TT + ci * 128, u + (size_t)ci * 128 * DD,
                    u + (size_t)r0 * DD, Mu, DD, 128, TT, DD, DD, sTT, sTD, sTD);
            }
        }
        {
            dim3 tb(32, 8);
            tscale_kernel<<<dim3(DD / 32, TT / 32, NB), tb>>>(u, lr, ut, utl);
        }
        launch_hgemm(SPLIT, qh, qhl, kh, khl, nullptr, nullptr,
                     nullptr, sh, shl, TT, TT, DD, DD, DD, TT, sTD, sTD, sTT, NB);
        // y: split inputs, only hi output needed (Wo is single-pass)
        launch_hgemm(SPLIT, sh, shl, ut, utl, nullptr, nullptr,
                     nullptr, yh, nullptr, TT, DD, TT, TT, TT, DD, sTT, sTD, sTD, NB);
        // x = x + y @ Wo + bo — SINGLE-PASS, BK=64
        launch_hgemm(4 | 8, yh, yh, WoT_l, WoT_l, bo + (size_t)l * DD, x,
                     x, nullptr, nullptr, MTOT, DD, DD, DD, DD, DD, 0, 0, 0, 1);

        // --- MLP block — SINGLE-PASS GEMMs, BK=64 ---
        ln_kernel<<<MTOT, 256>>>(hh, hhl, x, g_m + (size_t)l * DD, b_m + (size_t)l * DD,
                                 nullptr, nullptr, nullptr);
        launch_hgemm(4 | 1, hh, hh, W1T_l, W1T_l, b1 + (size_t)l * DD, nullptr,
                     nullptr, ah, nullptr, MTOT, DD, DD, DD, DD, DD, 0, 0, 0, 1);
        launch_hgemm(4 | 8, ah, ah, W2T_l, W2T_l, b2 + (size_t)l * DD, x,
                     x, nullptr, nullptr, MTOT, DD, DD, DD, DD, DD, 0, 0, 0, 1);
    }

    // final LN + tied decoder: single-pass fp16 logits, BK=64
    ln_kernel<<<MTOT, 256>>>(hh, hhl, x, g_o, b_o, nullptr, nullptr, nullptr);
    launch_hgemm(0, hh, hh, Eh, Eh, nullptr, nullptr,
                 out, nullptr, nullptr, MTOT, VV, DD, DD, DD, VV, 0, 0, 0, 1);
}